// round 3
// baseline (speedup 1.0000x reference)
#include <cuda_runtime.h>

#define NN   100000
#define NE   1600000
#define DIN  128
#define DH   256
#define NCLS 32

typedef unsigned long long ull;

// ---------------- scratch (device globals: no allocation allowed) ----------
__device__ int   g_deg[NN];
__device__ int   g_rowptr[NN + 1];
__device__ int   g_cursor[NN];
__device__ int   g_csr[NE];
__device__ int   g_bsum[128];
__device__ float g_agg[(size_t)NN * DH];
__device__ float g_h1 [(size_t)NN * DH];
__device__ float g_h2 [(size_t)NN * DH];
__device__ float g_stats[1024]; // [0:256) sum1 [256:512) sq1 [512:768) sum2 [768:1024) sq2
__device__ float g_bn[1024];    // layer1: scale[0:256) shift[256:512); layer2: +512

// ---------------- small helpers -------------------------------------------
__device__ __forceinline__ ull dupf(float a) {
    ull r;
    asm("mov.b64 %0, {%1, %1};" : "=l"(r) : "f"(a));
    return r;
}
#define FMA2(accv, av, bv) \
    asm("fma.rn.f32x2 %0, %1, %2, %0;" : "+l"(accv) : "l"(av), "l"(bv))

__device__ __forceinline__ int block_scan_incl(int v) {
    __shared__ int ws[32];
    int lane = threadIdx.x & 31, wid = threadIdx.x >> 5;
#pragma unroll
    for (int o = 1; o < 32; o <<= 1) {
        int n = __shfl_up_sync(0xffffffffu, v, o);
        if (lane >= o) v += n;
    }
    if (lane == 31) ws[wid] = v;
    __syncthreads();
    int nw = blockDim.x >> 5;
    if (wid == 0) {
        int s = (lane < nw) ? ws[lane] : 0;
#pragma unroll
        for (int o = 1; o < 32; o <<= 1) {
            int n = __shfl_up_sync(0xffffffffu, s, o);
            if (lane >= o) s += n;
        }
        ws[lane] = s;
    }
    __syncthreads();
    if (wid > 0) v += ws[wid - 1];
    return v;
}

// ---------------- graph prep ----------------------------------------------
__global__ void k_init() {
    int i = blockIdx.x * blockDim.x + threadIdx.x;
    if (i < NN) { g_deg[i] = 0; g_cursor[i] = 0; }
    if (i < 1024) g_stats[i] = 0.f;
}

__global__ void k_hist(const int* __restrict__ dst) {
    int e = blockIdx.x * blockDim.x + threadIdx.x;
    if (e < NE) atomicAdd(&g_deg[dst[e]], 1);
}

__global__ void k_scan1() {
    int i = blockIdx.x * 1024 + threadIdx.x;
    int v = (i < NN) ? g_deg[i] : 0;
    int incl = block_scan_incl(v);
    if (i < NN) g_rowptr[i + 1] = incl;
    if (threadIdx.x == 1023) g_bsum[blockIdx.x] = incl;
}

__global__ void k_scan2(int nb) {
    int t = threadIdx.x;
    int v = (t < nb) ? g_bsum[t] : 0;
    int incl = block_scan_incl(v);
    if (t < nb) g_bsum[t] = incl;
}

__global__ void k_scan3() {
    int i = blockIdx.x * 1024 + threadIdx.x;
    if (i < NN && blockIdx.x > 0) g_rowptr[i + 1] += g_bsum[blockIdx.x - 1];
    if (i == 0) g_rowptr[0] = 0;
}

__global__ void k_fill(const int* __restrict__ src, const int* __restrict__ dst) {
    int e = blockIdx.x * blockDim.x + threadIdx.x;
    if (e < NE) {
        int d = dst[e];
        int p = atomicAdd(&g_cursor[d], 1);
        g_csr[g_rowptr[d] + p] = src[e];
    }
}

// ---------------- SpMM (mean aggregation): 1 warp per node ----------------
template <int D>
__global__ void __launch_bounds__(256) k_spmm(const float* __restrict__ X,
                                              float* __restrict__ OUT) {
    int warp = threadIdx.x >> 5, lane = threadIdx.x & 31;
    int node = blockIdx.x * 8 + warp;
    if (node >= NN) return;
    int beg = g_rowptr[node], end = g_rowptr[node + 1];
    float4 a0 = make_float4(0.f, 0.f, 0.f, 0.f);
    float4 a1 = make_float4(0.f, 0.f, 0.f, 0.f);
    for (int j = beg; j < end; j++) {
        int s = __ldg(&g_csr[j]);
        const float4* row = (const float4*)(X + (size_t)s * D);
        float4 v = __ldg(&row[lane]);
        a0.x += v.x; a0.y += v.y; a0.z += v.z; a0.w += v.w;
        if (D == 256) {
            float4 w = __ldg(&row[lane + 32]);
            a1.x += w.x; a1.y += w.y; a1.z += w.z; a1.w += w.w;
        }
    }
    float inv = 1.f / fmaxf((float)(end - beg), 1.f);
    float4* o = (float4*)(OUT + (size_t)node * D);
    a0.x *= inv; a0.y *= inv; a0.z *= inv; a0.w *= inv;
    o[lane] = a0;
    if (D == 256) {
        a1.x *= inv; a1.y *= inv; a1.z *= inv; a1.w *= inv;
        o[lane + 32] = a1;
    }
}

// ---------------- fused dual-GEMM + bias + BN-stats ------------------------
// Out[i,:] = Aagg[i,:]@Wl + Aself[i,:]@Wr + bias ; also accumulates per-column
// sum / sumsq into stats (for batch norm). Tile 128x128, BK=16, f32x2 FFMA.
template <int K>
__global__ void __launch_bounds__(256) k_gemm(const float* __restrict__ Aagg,
                                              const float* __restrict__ Aself,
                                              const float* __restrict__ Wl,
                                              const float* __restrict__ Wr,
                                              const float* __restrict__ bias,
                                              float* __restrict__ Out,
                                              float* __restrict__ stats) {
    constexpr int BM = 128, BN = 128, BK = 16;
    __shared__ __align__(16) float As[BK][BM + 4];
    __shared__ __align__(16) float Bs[BK][BN];
    __shared__ float s_sum[BN], s_sq[BN];

    const int t = threadIdx.x;
    const int tx = t & 15, ty = t >> 4;
    const int m0 = blockIdx.x * BM;
    const int n0 = blockIdx.y * BN;

    ull acc[8][4];
#pragma unroll
    for (int i = 0; i < 8; i++)
#pragma unroll
        for (int j = 0; j < 4; j++) acc[i][j] = 0ull;

    const int la_r = t >> 2;        // 0..63
    const int la_k = (t & 3) * 4;   // 0,4,8,12

    for (int k0 = 0; k0 < 2 * K; k0 += BK) {
        const float* Ap; const float* Bp; int kk0;
        if (k0 < K) { Ap = Aagg;  Bp = Wl; kk0 = k0; }
        else        { Ap = Aself; Bp = Wr; kk0 = k0 - K; }
        // A tile: rows m0+la_r(+64), k = kk0+la_k..+3, stored transposed
#pragma unroll
        for (int h = 0; h < 2; h++) {
            int r = la_r + 64 * h;
            int gr = m0 + r;
            float4 v = make_float4(0.f, 0.f, 0.f, 0.f);
            if (gr < NN) v = *(const float4*)(Ap + (size_t)gr * K + kk0 + la_k);
            As[la_k + 0][r] = v.x; As[la_k + 1][r] = v.y;
            As[la_k + 2][r] = v.z; As[la_k + 3][r] = v.w;
        }
        // B tile: 16 rows x 128 cols
#pragma unroll
        for (int h = 0; h < 2; h++) {
            int idx = t + 256 * h;      // 0..511
            int kr = idx >> 5;          // 0..15
            int c4 = idx & 31;          // 0..31
            float4 v = *(const float4*)(Bp + (size_t)(kk0 + kr) * DH + n0 + c4 * 4);
            *(float4*)&Bs[kr][c4 * 4] = v;
        }
        __syncthreads();
#pragma unroll
        for (int kk = 0; kk < BK; kk++) {
            float4 a0 = *(const float4*)&As[kk][ty * 4];
            float4 a1 = *(const float4*)&As[kk][ty * 4 + 64];
            float4 b0 = *(const float4*)&Bs[kk][tx * 4];
            float4 b1 = *(const float4*)&Bs[kk][tx * 4 + 64];
            ulonglong2 bl = *(ulonglong2*)&b0;   // (c0,c1),(c2,c3)
            ulonglong2 bh = *(ulonglong2*)&b1;   // (c64,c65),(c66,c67)
            float ar[8] = {a0.x, a0.y, a0.z, a0.w, a1.x, a1.y, a1.z, a1.w};
#pragma unroll
            for (int i = 0; i < 8; i++) {
                ull ad = dupf(ar[i]);
                FMA2(acc[i][0], ad, bl.x);
                FMA2(acc[i][1], ad, bl.y);
                FMA2(acc[i][2], ad, bh.x);
                FMA2(acc[i][3], ad, bh.y);
            }
        }
        __syncthreads();
    }

    // epilogue: bias, store, BN partial stats
    float4 bb0 = *(const float4*)(bias + n0 + tx * 4);
    float4 bb1 = *(const float4*)(bias + n0 + tx * 4 + 64);
    if (t < BN) { s_sum[t] = 0.f; s_sq[t] = 0.f; }
    __syncthreads();

#pragma unroll
    for (int i = 0; i < 8; i++) {
        int r = ty * 4 + (i & 3) + ((i >= 4) ? 64 : 0);
        int gr = m0 + r;
        if (gr < NN) {
            float v[8];
            ((float2*)v)[0] = *(float2*)&acc[i][0];
            ((float2*)v)[1] = *(float2*)&acc[i][1];
            ((float2*)v)[2] = *(float2*)&acc[i][2];
            ((float2*)v)[3] = *(float2*)&acc[i][3];
            v[0] += bb0.x; v[1] += bb0.y; v[2] += bb0.z; v[3] += bb0.w;
            v[4] += bb1.x; v[5] += bb1.y; v[6] += bb1.z; v[7] += bb1.w;
            *(float4*)(Out + (size_t)gr * DH + n0 + tx * 4)      = *(float4*)&v[0];
            *(float4*)(Out + (size_t)gr * DH + n0 + tx * 4 + 64) = *(float4*)&v[4];
#pragma unroll
            for (int c = 0; c < 8; c++) {
                int lc = tx * 4 + (c & 3) + ((c >= 4) ? 64 : 0);
                atomicAdd(&s_sum[lc], v[c]);
                atomicAdd(&s_sq[lc], v[c] * v[c]);
            }
        }
    }
    __syncthreads();
    if (t < BN) {
        atomicAdd(&stats[n0 + t], s_sum[t]);
        atomicAdd(&stats[256 + n0 + t], s_sq[t]);
    }
}

// ---------------- BN finalize + apply --------------------------------------
__global__ void k_bnfinal(const float* __restrict__ stats,
                          const float* __restrict__ gam,
                          const float* __restrict__ bet,
                          float* __restrict__ bn) {
    int c = threadIdx.x;
    float mu  = stats[c] * (1.f / NN);
    float var = stats[256 + c] * (1.f / NN) - mu * mu;
    float rstd = rsqrtf(var + 1e-5f);
    float sc = rstd * gam[c];
    bn[c] = sc;
    bn[256 + c] = bet[c] - mu * sc;
}

__global__ void k_bnrelu(float* __restrict__ H, const float* __restrict__ bn) {
    const int total = NN * DH / 4;
    for (int i = blockIdx.x * blockDim.x + threadIdx.x; i < total;
         i += gridDim.x * blockDim.x) {
        float4 v = ((float4*)H)[i];
        int c = (i & 63) * 4;
        v.x = fmaxf(0.f, v.x * bn[c + 0] + bn[256 + c + 0]);
        v.y = fmaxf(0.f, v.y * bn[c + 1] + bn[256 + c + 1]);
        v.z = fmaxf(0.f, v.z * bn[c + 2] + bn[256 + c + 2]);
        v.w = fmaxf(0.f, v.w * bn[c + 3] + bn[256 + c + 3]);
        ((float4*)H)[i] = v;
    }
}

// ---------------- final FC: [NN,256]@[256,32] ------------------------------
__global__ void __launch_bounds__(256) k_fc(const float* __restrict__ H,
                                            const float* __restrict__ W,
                                            const float* __restrict__ b,
                                            float* __restrict__ out) {
    __shared__ __align__(16) float Ws[DH * NCLS];
    for (int i = threadIdx.x; i < DH * NCLS / 4; i += 256)
        ((float4*)Ws)[i] = ((const float4*)W)[i];
    __syncthreads();
    int row = blockIdx.x * 32 + (threadIdx.x >> 3);
    int c = (threadIdx.x & 7) * 4;
    if (row >= NN) return;
    const float4* hr = (const float4*)(H + (size_t)row * DH);
    float4 acc = *(const float4*)(b + c);
#pragma unroll 8
    for (int k4 = 0; k4 < DH / 4; k4++) {
        float4 h = hr[k4];
        float4 w0 = *(float4*)&Ws[(k4 * 4 + 0) * NCLS + c];
        float4 w1 = *(float4*)&Ws[(k4 * 4 + 1) * NCLS + c];
        float4 w2 = *(float4*)&Ws[(k4 * 4 + 2) * NCLS + c];
        float4 w3 = *(float4*)&Ws[(k4 * 4 + 3) * NCLS + c];
        acc.x += h.x * w0.x + h.y * w1.x + h.z * w2.x + h.w * w3.x;
        acc.y += h.x * w0.y + h.y * w1.y + h.z * w2.y + h.w * w3.y;
        acc.z += h.x * w0.z + h.y * w1.z + h.z * w2.z + h.w * w3.z;
        acc.w += h.x * w0.w + h.y * w1.w + h.z * w2.w + h.w * w3.w;
    }
    *(float4*)(out + (size_t)row * NCLS + c) = acc;
}

// ---------------- launch ----------------------------------------------------
extern "C" void kernel_launch(void* const* d_in, const int* in_sizes, int n_in,
                              void* d_out, int out_size) {
    const float* x    = (const float*)d_in[0];
    const int*   esrc = (const int*)d_in[1];
    const int*   edst = (const int*)d_in[2];
    const float* W1l  = (const float*)d_in[3];
    const float* b1   = (const float*)d_in[4];
    const float* W1r  = (const float*)d_in[5];
    const float* g1   = (const float*)d_in[6];
    const float* be1  = (const float*)d_in[7];
    const float* W2l  = (const float*)d_in[8];
    const float* b2   = (const float*)d_in[9];
    const float* W2r  = (const float*)d_in[10];
    const float* g2   = (const float*)d_in[11];
    const float* be2  = (const float*)d_in[12];
    const float* Wfc  = (const float*)d_in[13];
    const float* bfc  = (const float*)d_in[14];
    float* out = (float*)d_out;

    float *p_agg, *p_h1, *p_h2, *p_stats, *p_bn;
    cudaGetSymbolAddress((void**)&p_agg,   g_agg);
    cudaGetSymbolAddress((void**)&p_h1,    g_h1);
    cudaGetSymbolAddress((void**)&p_h2,    g_h2);
    cudaGetSymbolAddress((void**)&p_stats, g_stats);
    cudaGetSymbolAddress((void**)&p_bn,    g_bn);

    const int nb1 = (NN + 1023) / 1024;           // 98
    const int egrid = (NE + 255) / 256;           // 6250

    k_init<<<(NN + 255) / 256, 256>>>();
    k_hist<<<egrid, 256>>>(edst);
    k_scan1<<<nb1, 1024>>>();
    k_scan2<<<1, 128>>>(nb1);
    k_scan3<<<nb1, 1024>>>();
    k_fill<<<egrid, 256>>>(esrc, edst);

    dim3 gg((NN + 127) / 128, 2);

    // layer 1
    k_spmm<DIN><<<(NN + 7) / 8, 256>>>(x, p_agg);
    k_gemm<DIN><<<gg, 256>>>(p_agg, x, W1l, W1r, b1, p_h1, p_stats);
    k_bnfinal<<<1, 256>>>(p_stats, g1, be1, p_bn);
    k_bnrelu<<<4096, 256>>>(p_h1, p_bn);

    // layer 2
    k_spmm<DH><<<(NN + 7) / 8, 256>>>(p_h1, p_agg);
    k_gemm<DH><<<gg, 256>>>(p_agg, p_h1, W2l, W2r, b2, p_h2, p_stats + 512);
    k_bnfinal<<<1, 256>>>(p_stats + 512, g2, be2, p_bn + 512);
    k_bnrelu<<<4096, 256>>>(p_h2, p_bn + 512);

    // classifier
    k_fc<<<(NN + 31) / 32, 256>>>(p_h2, Wfc, bfc, out);
}

// round 4
// speedup vs baseline: 1.0009x; 1.0009x over previous
#include <cuda_runtime.h>

#define NN   100000
#define NE   1600000
#define DIN  128
#define DH   256
#define NCLS 32

typedef unsigned long long ull;

// ---------------- scratch (device globals: no allocation allowed) ----------
__device__ int   g_deg[NN];
__device__ int   g_rowptr[NN + 1];
__device__ int   g_cursor[NN];
__device__ int   g_csr[NE];
__device__ int   g_bsum[128];
__device__ float g_agg[(size_t)NN * DH];
__device__ float g_h1 [(size_t)NN * DH];
__device__ float g_h2 [(size_t)NN * DH];
__device__ float g_stats[1024]; // [0:256) sum1 [256:512) sq1 [512:768) sum2 [768:1024) sq2
__device__ float g_bn[1024];    // layer1: scale[0:256) shift[256:512); layer2: +512

// ---------------- small helpers -------------------------------------------
__device__ __forceinline__ ull dupf(float a) {
    ull r;
    asm("mov.b64 %0, {%1, %1};" : "=l"(r) : "f"(a));
    return r;
}
#define FMA2(accv, av, bv) \
    asm("fma.rn.f32x2 %0, %1, %2, %0;" : "+l"(accv) : "l"(av), "l"(bv))

__device__ __forceinline__ int block_scan_incl(int v) {
    __shared__ int ws[32];
    int lane = threadIdx.x & 31, wid = threadIdx.x >> 5;
#pragma unroll
    for (int o = 1; o < 32; o <<= 1) {
        int n = __shfl_up_sync(0xffffffffu, v, o);
        if (lane >= o) v += n;
    }
    if (lane == 31) ws[wid] = v;
    __syncthreads();
    int nw = blockDim.x >> 5;
    if (wid == 0) {
        int s = (lane < nw) ? ws[lane] : 0;
#pragma unroll
        for (int o = 1; o < 32; o <<= 1) {
            int n = __shfl_up_sync(0xffffffffu, s, o);
            if (lane >= o) s += n;
        }
        ws[lane] = s;
    }
    __syncthreads();
    if (wid > 0) v += ws[wid - 1];
    return v;
}

// ---------------- graph prep ----------------------------------------------
__global__ void k_init() {
    int i = blockIdx.x * blockDim.x + threadIdx.x;
    if (i < NN) { g_deg[i] = 0; g_cursor[i] = 0; }
    if (i < 1024) g_stats[i] = 0.f;
}

__global__ void k_hist(const int* __restrict__ dst) {
    int e = blockIdx.x * blockDim.x + threadIdx.x;
    if (e < NE) atomicAdd(&g_deg[dst[e]], 1);
}

__global__ void k_scan1() {
    int i = blockIdx.x * 1024 + threadIdx.x;
    int v = (i < NN) ? g_deg[i] : 0;
    int incl = block_scan_incl(v);
    if (i < NN) g_rowptr[i + 1] = incl;
    if (threadIdx.x == 1023) g_bsum[blockIdx.x] = incl;
}

__global__ void k_scan2(int nb) {
    int t = threadIdx.x;
    int v = (t < nb) ? g_bsum[t] : 0;
    int incl = block_scan_incl(v);
    if (t < nb) g_bsum[t] = incl;
}

__global__ void k_scan3() {
    int i = blockIdx.x * 1024 + threadIdx.x;
    if (i < NN && blockIdx.x > 0) g_rowptr[i + 1] += g_bsum[blockIdx.x - 1];
    if (i == 0) g_rowptr[0] = 0;
}

__global__ void k_fill(const int* __restrict__ src, const int* __restrict__ dst) {
    int e = blockIdx.x * blockDim.x + threadIdx.x;
    if (e < NE) {
        int d = dst[e];
        int p = atomicAdd(&g_cursor[d], 1);
        g_csr[g_rowptr[d] + p] = src[e];
    }
}

// ---------------- SpMM (mean aggregation): 1 warp per node ----------------
template <int D>
__global__ void __launch_bounds__(256) k_spmm(const float* __restrict__ X,
                                              float* __restrict__ OUT) {
    int warp = threadIdx.x >> 5, lane = threadIdx.x & 31;
    int node = blockIdx.x * 8 + warp;
    if (node >= NN) return;
    int beg = g_rowptr[node], end = g_rowptr[node + 1];
    float4 a0 = make_float4(0.f, 0.f, 0.f, 0.f);
    float4 a1 = make_float4(0.f, 0.f, 0.f, 0.f);
    for (int j = beg; j < end; j++) {
        int s = __ldg(&g_csr[j]);
        const float4* row = (const float4*)(X + (size_t)s * D);
        float4 v = __ldg(&row[lane]);
        a0.x += v.x; a0.y += v.y; a0.z += v.z; a0.w += v.w;
        if (D == 256) {
            float4 w = __ldg(&row[lane + 32]);
            a1.x += w.x; a1.y += w.y; a1.z += w.z; a1.w += w.w;
        }
    }
    float inv = 1.f / fmaxf((float)(end - beg), 1.f);
    float4* o = (float4*)(OUT + (size_t)node * D);
    a0.x *= inv; a0.y *= inv; a0.z *= inv; a0.w *= inv;
    o[lane] = a0;
    if (D == 256) {
        a1.x *= inv; a1.y *= inv; a1.z *= inv; a1.w *= inv;
        o[lane + 32] = a1;
    }
}

// ---------------- fused dual-GEMM + bias + BN-stats ------------------------
// Out[i,:] = Aagg[i,:]@Wl + Aself[i,:]@Wr + bias ; also accumulates per-column
// sum / sumsq into stats (for batch norm). Tile 128x128, BK=16, f32x2 FFMA.
template <int K>
__global__ void __launch_bounds__(256) k_gemm(const float* __restrict__ Aagg,
                                              const float* __restrict__ Aself,
                                              const float* __restrict__ Wl,
                                              const float* __restrict__ Wr,
                                              const float* __restrict__ bias,
                                              float* __restrict__ Out,
                                              float* __restrict__ stats) {
    constexpr int BM = 128, BN = 128, BK = 16;
    __shared__ __align__(16) float As[BK][BM + 4];
    __shared__ __align__(16) float Bs[BK][BN];
    __shared__ float s_sum[BN], s_sq[BN];

    const int t = threadIdx.x;
    const int tx = t & 15, ty = t >> 4;
    const int m0 = blockIdx.x * BM;
    const int n0 = blockIdx.y * BN;

    ull acc[8][4];
#pragma unroll
    for (int i = 0; i < 8; i++)
#pragma unroll
        for (int j = 0; j < 4; j++) acc[i][j] = 0ull;

    const int la_r = t >> 2;        // 0..63
    const int la_k = (t & 3) * 4;   // 0,4,8,12

    for (int k0 = 0; k0 < 2 * K; k0 += BK) {
        const float* Ap; const float* Bp; int kk0;
        if (k0 < K) { Ap = Aagg;  Bp = Wl; kk0 = k0; }
        else        { Ap = Aself; Bp = Wr; kk0 = k0 - K; }
        // A tile: rows m0+la_r(+64), k = kk0+la_k..+3, stored transposed
#pragma unroll
        for (int h = 0; h < 2; h++) {
            int r = la_r + 64 * h;
            int gr = m0 + r;
            float4 v = make_float4(0.f, 0.f, 0.f, 0.f);
            if (gr < NN) v = *(const float4*)(Ap + (size_t)gr * K + kk0 + la_k);
            As[la_k + 0][r] = v.x; As[la_k + 1][r] = v.y;
            As[la_k + 2][r] = v.z; As[la_k + 3][r] = v.w;
        }
        // B tile: 16 rows x 128 cols
#pragma unroll
        for (int h = 0; h < 2; h++) {
            int idx = t + 256 * h;      // 0..511
            int kr = idx >> 5;          // 0..15
            int c4 = idx & 31;          // 0..31
            float4 v = *(const float4*)(Bp + (size_t)(kk0 + kr) * DH + n0 + c4 * 4);
            *(float4*)&Bs[kr][c4 * 4] = v;
        }
        __syncthreads();
#pragma unroll
        for (int kk = 0; kk < BK; kk++) {
            float4 a0 = *(const float4*)&As[kk][ty * 4];
            float4 a1 = *(const float4*)&As[kk][ty * 4 + 64];
            float4 b0 = *(const float4*)&Bs[kk][tx * 4];
            float4 b1 = *(const float4*)&Bs[kk][tx * 4 + 64];
            ulonglong2 bl = *(ulonglong2*)&b0;   // (c0,c1),(c2,c3)
            ulonglong2 bh = *(ulonglong2*)&b1;   // (c64,c65),(c66,c67)
            float ar[8] = {a0.x, a0.y, a0.z, a0.w, a1.x, a1.y, a1.z, a1.w};
#pragma unroll
            for (int i = 0; i < 8; i++) {
                ull ad = dupf(ar[i]);
                FMA2(acc[i][0], ad, bl.x);
                FMA2(acc[i][1], ad, bl.y);
                FMA2(acc[i][2], ad, bh.x);
                FMA2(acc[i][3], ad, bh.y);
            }
        }
        __syncthreads();
    }

    // epilogue: bias, store, BN partial stats
    float4 bb0 = *(const float4*)(bias + n0 + tx * 4);
    float4 bb1 = *(const float4*)(bias + n0 + tx * 4 + 64);
    if (t < BN) { s_sum[t] = 0.f; s_sq[t] = 0.f; }
    __syncthreads();

#pragma unroll
    for (int i = 0; i < 8; i++) {
        int r = ty * 4 + (i & 3) + ((i >= 4) ? 64 : 0);
        int gr = m0 + r;
        if (gr < NN) {
            float v[8];
            ((float2*)v)[0] = *(float2*)&acc[i][0];
            ((float2*)v)[1] = *(float2*)&acc[i][1];
            ((float2*)v)[2] = *(float2*)&acc[i][2];
            ((float2*)v)[3] = *(float2*)&acc[i][3];
            v[0] += bb0.x; v[1] += bb0.y; v[2] += bb0.z; v[3] += bb0.w;
            v[4] += bb1.x; v[5] += bb1.y; v[6] += bb1.z; v[7] += bb1.w;
            *(float4*)(Out + (size_t)gr * DH + n0 + tx * 4)      = *(float4*)&v[0];
            *(float4*)(Out + (size_t)gr * DH + n0 + tx * 4 + 64) = *(float4*)&v[4];
#pragma unroll
            for (int c = 0; c < 8; c++) {
                int lc = tx * 4 + (c & 3) + ((c >= 4) ? 64 : 0);
                atomicAdd(&s_sum[lc], v[c]);
                atomicAdd(&s_sq[lc], v[c] * v[c]);
            }
        }
    }
    __syncthreads();
    if (t < BN) {
        atomicAdd(&stats[n0 + t], s_sum[t]);
        atomicAdd(&stats[256 + n0 + t], s_sq[t]);
    }
}

// ---------------- BN finalize + apply --------------------------------------
__global__ void k_bnfinal(const float* __restrict__ stats,
                          const float* __restrict__ gam,
                          const float* __restrict__ bet,
                          float* __restrict__ bn) {
    int c = threadIdx.x;
    float mu  = stats[c] * (1.f / NN);
    float var = stats[256 + c] * (1.f / NN) - mu * mu;
    float rstd = rsqrtf(var + 1e-5f);
    float sc = rstd * gam[c];
    bn[c] = sc;
    bn[256 + c] = bet[c] - mu * sc;
}

__global__ void k_bnrelu(float* __restrict__ H, const float* __restrict__ bn) {
    const int total = NN * DH / 4;
    for (int i = blockIdx.x * blockDim.x + threadIdx.x; i < total;
         i += gridDim.x * blockDim.x) {
        float4 v = ((float4*)H)[i];
        int c = (i & 63) * 4;
        v.x = fmaxf(0.f, v.x * bn[c + 0] + bn[256 + c + 0]);
        v.y = fmaxf(0.f, v.y * bn[c + 1] + bn[256 + c + 1]);
        v.z = fmaxf(0.f, v.z * bn[c + 2] + bn[256 + c + 2]);
        v.w = fmaxf(0.f, v.w * bn[c + 3] + bn[256 + c + 3]);
        ((float4*)H)[i] = v;
    }
}

// ---------------- final FC: [NN,256]@[256,32] ------------------------------
__global__ void __launch_bounds__(256) k_fc(const float* __restrict__ H,
                                            const float* __restrict__ W,
                                            const float* __restrict__ b,
                                            float* __restrict__ out) {
    __shared__ __align__(16) float Ws[DH * NCLS];
    for (int i = threadIdx.x; i < DH * NCLS / 4; i += 256)
        ((float4*)Ws)[i] = ((const float4*)W)[i];
    __syncthreads();
    int row = blockIdx.x * 32 + (threadIdx.x >> 3);
    int c = (threadIdx.x & 7) * 4;
    if (row >= NN) return;
    const float4* hr = (const float4*)(H + (size_t)row * DH);
    float4 acc = *(const float4*)(b + c);
#pragma unroll 8
    for (int k4 = 0; k4 < DH / 4; k4++) {
        float4 h = hr[k4];
        float4 w0 = *(float4*)&Ws[(k4 * 4 + 0) * NCLS + c];
        float4 w1 = *(float4*)&Ws[(k4 * 4 + 1) * NCLS + c];
        float4 w2 = *(float4*)&Ws[(k4 * 4 + 2) * NCLS + c];
        float4 w3 = *(float4*)&Ws[(k4 * 4 + 3) * NCLS + c];
        acc.x += h.x * w0.x + h.y * w1.x + h.z * w2.x + h.w * w3.x;
        acc.y += h.x * w0.y + h.y * w1.y + h.z * w2.y + h.w * w3.y;
        acc.z += h.x * w0.z + h.y * w1.z + h.z * w2.z + h.w * w3.z;
        acc.w += h.x * w0.w + h.y * w1.w + h.z * w2.w + h.w * w3.w;
    }
    *(float4*)(out + (size_t)row * NCLS + c) = acc;
}

// ---------------- launch ----------------------------------------------------
extern "C" void kernel_launch(void* const* d_in, const int* in_sizes, int n_in,
                              void* d_out, int out_size) {
    const float* x    = (const float*)d_in[0];
    const int*   esrc = (const int*)d_in[1];
    const int*   edst = (const int*)d_in[2];
    const float* W1l  = (const float*)d_in[3];
    const float* b1   = (const float*)d_in[4];
    const float* W1r  = (const float*)d_in[5];
    const float* g1   = (const float*)d_in[6];
    const float* be1  = (const float*)d_in[7];
    const float* W2l  = (const float*)d_in[8];
    const float* b2   = (const float*)d_in[9];
    const float* W2r  = (const float*)d_in[10];
    const float* g2   = (const float*)d_in[11];
    const float* be2  = (const float*)d_in[12];
    const float* Wfc  = (const float*)d_in[13];
    const float* bfc  = (const float*)d_in[14];
    float* out = (float*)d_out;

    float *p_agg, *p_h1, *p_h2, *p_stats, *p_bn;
    cudaGetSymbolAddress((void**)&p_agg,   g_agg);
    cudaGetSymbolAddress((void**)&p_h1,    g_h1);
    cudaGetSymbolAddress((void**)&p_h2,    g_h2);
    cudaGetSymbolAddress((void**)&p_stats, g_stats);
    cudaGetSymbolAddress((void**)&p_bn,    g_bn);

    const int nb1 = (NN + 1023) / 1024;           // 98
    const int egrid = (NE + 255) / 256;           // 6250

    k_init<<<(NN + 255) / 256, 256>>>();
    k_hist<<<egrid, 256>>>(edst);
    k_scan1<<<nb1, 1024>>>();
    k_scan2<<<1, 128>>>(nb1);
    k_scan3<<<nb1, 1024>>>();
    k_fill<<<egrid, 256>>>(esrc, edst);

    dim3 gg((NN + 127) / 128, 2);

    // layer 1
    k_spmm<DIN><<<(NN + 7) / 8, 256>>>(x, p_agg);
    k_gemm<DIN><<<gg, 256>>>(p_agg, x, W1l, W1r, b1, p_h1, p_stats);
    k_bnfinal<<<1, 256>>>(p_stats, g1, be1, p_bn);
    k_bnrelu<<<4096, 256>>>(p_h1, p_bn);

    // layer 2
    k_spmm<DH><<<(NN + 7) / 8, 256>>>(p_h1, p_agg);
    k_gemm<DH><<<gg, 256>>>(p_agg, p_h1, W2l, W2r, b2, p_h2, p_stats + 512);
    k_bnfinal<<<1, 256>>>(p_stats + 512, g2, be2, p_bn + 512);
    k_bnrelu<<<4096, 256>>>(p_h2, p_bn + 512);

    // classifier
    k_fc<<<(NN + 31) / 32, 256>>>(p_h2, Wfc, bfc, out);
}

// round 6
// speedup vs baseline: 1.1959x; 1.1948x over previous
#include <cuda_runtime.h>
#include <cuda_bf16.h>
#include <cstdint>

#define NN   100000
#define NE   1600000
#define DIN  128
#define DH   256
#define NCLS 32

typedef unsigned long long ull;
typedef __nv_bfloat16 bf16;

// ---------------- scratch (device globals) ---------------------------------
__device__ int   g_deg[NN];
__device__ int   g_rowptr[NN + 1];
__device__ int   g_cursor[NN];
__device__ int   g_csr[NE];
__device__ int   g_bsum[128];
__device__ __align__(128) bf16  g_Ahi[(size_t)NN * DH];
__device__ __align__(128) bf16  g_Alo[(size_t)NN * DH];
__device__ __align__(128) bf16  g_Shi[(size_t)NN * DH];
__device__ __align__(128) bf16  g_Slo[(size_t)NN * DH];
__device__ __align__(128) bf16  g_Bpack[DH * 6 * DH];   // up to 256 x 1536
__device__ __align__(128) float g_h1[(size_t)NN * DH];
__device__ __align__(128) float g_h2[(size_t)NN * DH];
__device__ float g_stats[1024];
__device__ float g_bn[1024];

// ---------------- helpers ---------------------------------------------------
__device__ __forceinline__ uint32_t smem_u32(const void* p) {
    uint32_t a;
    asm("{ .reg .u64 t; cvta.to.shared.u64 t, %1; cvt.u32.u64 %0, t; }"
        : "=r"(a) : "l"(p));
    return a;
}
__device__ __forceinline__ void cpasync16(uint32_t dst, const void* src) {
    asm volatile("cp.async.cg.shared.global [%0], [%1], 16;"
                 :: "r"(dst), "l"(src));
}
#define CP_COMMIT() asm volatile("cp.async.commit_group;" ::: "memory")

__device__ __forceinline__ void ldsm_x4(uint32_t* r, uint32_t addr) {
    asm volatile("ldmatrix.sync.aligned.m8n8.x4.shared.b16 {%0,%1,%2,%3}, [%4];"
                 : "=r"(r[0]), "=r"(r[1]), "=r"(r[2]), "=r"(r[3]) : "r"(addr));
}
__device__ __forceinline__ void ldsm_x2(uint32_t* r, uint32_t addr) {
    asm volatile("ldmatrix.sync.aligned.m8n8.x2.shared.b16 {%0,%1}, [%2];"
                 : "=r"(r[0]), "=r"(r[1]) : "r"(addr));
}
__device__ __forceinline__ void mma16816(float* c, const uint32_t* a,
                                         const uint32_t* b) {
    asm volatile(
        "mma.sync.aligned.m16n8k16.row.col.f32.bf16.bf16.f32 "
        "{%0,%1,%2,%3}, {%4,%5,%6,%7}, {%8,%9}, {%0,%1,%2,%3};"
        : "+f"(c[0]), "+f"(c[1]), "+f"(c[2]), "+f"(c[3])
        : "r"(a[0]), "r"(a[1]), "r"(a[2]), "r"(a[3]), "r"(b[0]), "r"(b[1]));
}

__device__ __forceinline__ uint32_t pk(float a, float b) {
    __nv_bfloat162 t = __floats2bfloat162_rn(a, b);
    return *(uint32_t*)&t;
}

// ---------------- scan helper ----------------------------------------------
__device__ __forceinline__ int block_scan_incl(int v) {
    __shared__ int ws[32];
    int lane = threadIdx.x & 31, wid = threadIdx.x >> 5;
#pragma unroll
    for (int o = 1; o < 32; o <<= 1) {
        int n = __shfl_up_sync(0xffffffffu, v, o);
        if (lane >= o) v += n;
    }
    if (lane == 31) ws[wid] = v;
    __syncthreads();
    int nw = blockDim.x >> 5;
    if (wid == 0) {
        int s = (lane < nw) ? ws[lane] : 0;
#pragma unroll
        for (int o = 1; o < 32; o <<= 1) {
            int n = __shfl_up_sync(0xffffffffu, s, o);
            if (lane >= o) s += n;
        }
        ws[lane] = s;
    }
    __syncthreads();
    if (wid > 0) v += ws[wid - 1];
    return v;
}

// ---------------- graph prep ----------------------------------------------
__global__ void k_init() {
    int i = blockIdx.x * blockDim.x + threadIdx.x;
    if (i < NN) { g_deg[i] = 0; g_cursor[i] = 0; }
    if (i < 1024) g_stats[i] = 0.f;
}
__global__ void k_hist(const int* __restrict__ dst) {
    int e = blockIdx.x * blockDim.x + threadIdx.x;
    if (e < NE) atomicAdd(&g_deg[dst[e]], 1);
}
__global__ void k_scan1() {
    int i = blockIdx.x * 1024 + threadIdx.x;
    int v = (i < NN) ? g_deg[i] : 0;
    int incl = block_scan_incl(v);
    if (i < NN) g_rowptr[i + 1] = incl;
    if (threadIdx.x == 1023) g_bsum[blockIdx.x] = incl;
}
__global__ void k_scan2(int nb) {
    int t = threadIdx.x;
    int v = (t < nb) ? g_bsum[t] : 0;
    int incl = block_scan_incl(v);
    if (t < nb) g_bsum[t] = incl;
}
__global__ void k_scan3() {
    int i = blockIdx.x * 1024 + threadIdx.x;
    if (i < NN && blockIdx.x > 0) g_rowptr[i + 1] += g_bsum[blockIdx.x - 1];
    if (i == 0) g_rowptr[0] = 0;
}
__global__ void k_fill(const int* __restrict__ src, const int* __restrict__ dst) {
    int e = blockIdx.x * blockDim.x + threadIdx.x;
    if (e < NE) {
        int d = dst[e];
        int p = atomicAdd(&g_cursor[d], 1);
        g_csr[g_rowptr[d] + p] = src[e];
    }
}

// ---------------- SpMM: 1 warp per node, writes bf16 hi/lo -----------------
template <int D>
__global__ void __launch_bounds__(256) k_spmm(const float* __restrict__ X,
                                              bf16* __restrict__ Ahi,
                                              bf16* __restrict__ Alo) {
    int warp = threadIdx.x >> 5, lane = threadIdx.x & 31;
    int node = blockIdx.x * 8 + warp;
    if (node >= NN) return;
    int beg = g_rowptr[node], end = g_rowptr[node + 1];
    float4 a0 = make_float4(0.f, 0.f, 0.f, 0.f);
    float4 a1 = make_float4(0.f, 0.f, 0.f, 0.f);
    for (int j = beg; j < end; j++) {
        int s = __ldg(&g_csr[j]);
        const float4* row = (const float4*)(X + (size_t)s * D);
        float4 v = __ldg(&row[lane]);
        a0.x += v.x; a0.y += v.y; a0.z += v.z; a0.w += v.w;
        if (D == 256) {
            float4 w = __ldg(&row[lane + 32]);
            a1.x += w.x; a1.y += w.y; a1.z += w.z; a1.w += w.w;
        }
    }
    float inv = 1.f / fmaxf((float)(end - beg), 1.f);
    a0.x *= inv; a0.y *= inv; a0.z *= inv; a0.w *= inv;
    a1.x *= inv; a1.y *= inv; a1.z *= inv; a1.w *= inv;

    auto wr = [&](float4 v, int colbase) {
        bf16 hx = __float2bfloat16(v.x), hy = __float2bfloat16(v.y);
        bf16 hz = __float2bfloat16(v.z), hw = __float2bfloat16(v.w);
        float lx = v.x - __bfloat162float(hx), ly = v.y - __bfloat162float(hy);
        float lz = v.z - __bfloat162float(hz), lw = v.w - __bfloat162float(hw);
        uint2 h = make_uint2(pk(__bfloat162float(hx), __bfloat162float(hy)),
                             pk(__bfloat162float(hz), __bfloat162float(hw)));
        uint2 l = make_uint2(pk(lx, ly), pk(lz, lw));
        *(uint2*)(Ahi + (size_t)node * D + colbase) = h;
        *(uint2*)(Alo + (size_t)node * D + colbase) = l;
    };
    wr(a0, lane * 4);
    if (D == 256) wr(a1, 128 + lane * 4);
}

// ---------------- x -> hi/lo split -----------------------------------------
__global__ void k_split(const float* __restrict__ X, bf16* __restrict__ Hi,
                        bf16* __restrict__ Lo, int total4) {
    for (int i = blockIdx.x * blockDim.x + threadIdx.x; i < total4;
         i += gridDim.x * blockDim.x) {
        float4 v = ((const float4*)X)[i];
        bf16 hx = __float2bfloat16(v.x), hy = __float2bfloat16(v.y);
        bf16 hz = __float2bfloat16(v.z), hw = __float2bfloat16(v.w);
        uint2 h = make_uint2(pk(__bfloat162float(hx), __bfloat162float(hy)),
                             pk(__bfloat162float(hz), __bfloat162float(hw)));
        uint2 l = make_uint2(pk(v.x - __bfloat162float(hx), v.y - __bfloat162float(hy)),
                             pk(v.z - __bfloat162float(hz), v.w - __bfloat162float(hw)));
        *(uint2*)((char*)Hi + (size_t)i * 8) = h;
        *(uint2*)((char*)Lo + (size_t)i * 8) = l;
    }
}

// ---------------- weight prep: Bpack[n][6K] bf16 K-major --------------------
// B segments: [Wl_hi, Wl_lo, Wl_hi, Wr_hi, Wr_lo, Wr_hi]
// paired with A segs:[Ahi ,  Ahi ,  Alo ,  Shi ,  Shi ,  Slo ]
template <int K>
__global__ void k_prepB(const float* __restrict__ Wl, const float* __restrict__ Wr,
                        bf16* __restrict__ B) {
    int idx = blockIdx.x * 256 + threadIdx.x;
    if (idx >= K * 256) return;
    int k = idx >> 8, n = idx & 255;
    const int LDB = 6 * K;
    float a = Wl[idx];
    bf16 ha = __float2bfloat16(a);
    bf16 la = __float2bfloat16(a - __bfloat162float(ha));
    B[(size_t)n * LDB + 0 * K + k] = ha;
    B[(size_t)n * LDB + 1 * K + k] = la;
    B[(size_t)n * LDB + 2 * K + k] = ha;
    float b = Wr[idx];
    bf16 hb = __float2bfloat16(b);
    bf16 lb = __float2bfloat16(b - __bfloat162float(hb));
    B[(size_t)n * LDB + 3 * K + k] = hb;
    B[(size_t)n * LDB + 4 * K + k] = lb;
    B[(size_t)n * LDB + 5 * K + k] = hb;
}

// ---------------- mma.sync GEMM: CTA 128x128, BK=32, K' = 6K ----------------
// 8 warps (2 m x 4 n), warp tile 64x32, m16n8k16 bf16 mma, 3-stage cp.async.
template <int K>
__global__ void __launch_bounds__(256)
k_mmagemm(const bf16* __restrict__ Ahi, const bf16* __restrict__ Alo,
          const bf16* __restrict__ Shi, const bf16* __restrict__ Slo,
          const bf16* __restrict__ Bp,  const float* __restrict__ bias,
          float* __restrict__ Out) {
    constexpr int NKC = K / 32;         // chunks per segment
    constexpr int CH  = 6 * NKC;        // total 32-wide K' chunks
    constexpr int LDB = 6 * K;
    constexpr int STAGE = 16384;        // A 8KB + B 8KB

    extern __shared__ __align__(128) char dsm[];
    float* sbias = (float*)dsm;                 // 512B
    uint32_t stage0 = smem_u32(dsm) + 1024;

    const int t = threadIdx.x;
    const int wid = t >> 5, lane = t & 31;
    const int wm = wid >> 2, wn = wid & 3;       // warp 2x4
    const int m0 = blockIdx.x * 128;
    const int n0 = blockIdx.y * 128;

    if (t < 128) sbias[t] = bias[n0 + t];

    float acc[4][4][4];
#pragma unroll
    for (int i = 0; i < 4; i++)
#pragma unroll
        for (int j = 0; j < 4; j++)
#pragma unroll
            for (int q = 0; q < 4; q++) acc[i][j][q] = 0.f;

    // per-thread load coords (2 A tiles + 2 B tiles per chunk)
    auto load_chunk = [&](int c, int s) {
        uint32_t sb = stage0 + s * STAGE;
        int seg = c / NKC, kc = c % NKC;
        const bf16* Ap = (seg < 2) ? Ahi : (seg == 2) ? Alo
                        : (seg < 5) ? Shi : Slo;
        int k0 = kc * 32;
#pragma unroll
        for (int it = 0; it < 2; it++) {
            int i = t + 256 * it;                // 0..511
            int row = i >> 2, ch = i & 3;        // 128 rows x 4 16B chunks
            int gr = m0 + row; if (gr > NN - 1) gr = NN - 1;
            uint32_t dst = sb + row * 64 + ((ch ^ (row & 3)) << 4);
            cpasync16(dst, Ap + (size_t)gr * K + k0 + ch * 8);
        }
        uint32_t bb = sb + 8192;
#pragma unroll
        for (int it = 0; it < 2; it++) {
            int i = t + 256 * it;
            int n = i >> 2, ch = i & 3;
            uint32_t dst = bb + n * 64 + ((ch ^ (n & 3)) << 4);
            cpasync16(dst, Bp + (size_t)(n0 + n) * LDB + c * 32 + ch * 8);
        }
        CP_COMMIT();
    };

    load_chunk(0, 0);
    load_chunk(1, 1);
    load_chunk(2, 2);

#pragma unroll 1
    for (int c = 0; c < CH; c++) {
        int s = c % 3;
        int rem = CH - 1 - c;
        if (rem >= 2)      asm volatile("cp.async.wait_group 2;" ::: "memory");
        else if (rem == 1) asm volatile("cp.async.wait_group 1;" ::: "memory");
        else               asm volatile("cp.async.wait_group 0;" ::: "memory");
        __syncthreads();

        uint32_t As = stage0 + s * STAGE;
        uint32_t Bs = As + 8192;
#pragma unroll
        for (int ks = 0; ks < 2; ks++) {
            uint32_t a[4][4], b[4][2];
#pragma unroll
            for (int mt = 0; mt < 4; mt++) {
                int r = wm * 64 + mt * 16 + (lane & 15);
                int kc = ks * 2 + (lane >> 4);
                ldsm_x4(a[mt], As + r * 64 + ((kc ^ (r & 3)) << 4));
            }
#pragma unroll
            for (int nt = 0; nt < 4; nt++) {
                int l15 = lane & 15;
                int n = wn * 32 + nt * 8 + (l15 & 7);
                int kc = ks * 2 + (l15 >> 3);
                ldsm_x2(b[nt], Bs + n * 64 + ((kc ^ (n & 3)) << 4));
            }
#pragma unroll
            for (int mt = 0; mt < 4; mt++)
#pragma unroll
                for (int nt = 0; nt < 4; nt++)
                    mma16816(acc[mt][nt], a[mt], b[nt]);
        }
        __syncthreads();
        if (c + 3 < CH) load_chunk(c + 3, s);
    }

    // epilogue: bias + store
#pragma unroll
    for (int mt = 0; mt < 4; mt++) {
        int r0 = m0 + wm * 64 + mt * 16 + (lane >> 2);
#pragma unroll
        for (int nt = 0; nt < 4; nt++) {
            int lc = wn * 32 + nt * 8 + (lane & 3) * 2;
            float bx = sbias[lc], by = sbias[lc + 1];
            if (r0 < NN) {
                float2 v = make_float2(acc[mt][nt][0] + bx, acc[mt][nt][1] + by);
                *(float2*)(Out + (size_t)r0 * DH + n0 + lc) = v;
            }
            if (r0 + 8 < NN) {
                float2 v = make_float2(acc[mt][nt][2] + bx, acc[mt][nt][3] + by);
                *(float2*)(Out + (size_t)(r0 + 8) * DH + n0 + lc) = v;
            }
        }
    }
}

// ---------------- BN column stats ------------------------------------------
__global__ void __launch_bounds__(256) k_stats(const float* __restrict__ H,
                                               float* __restrict__ stats) {
    int t = threadIdx.x;
    int col4 = t & 63;
    int rl = t >> 6;
    float s0 = 0, s1 = 0, s2 = 0, s3 = 0, q0 = 0, q1 = 0, q2 = 0, q3 = 0;
    for (int r = blockIdx.x * 4 + rl; r < NN; r += gridDim.x * 4) {
        float4 v = *(const float4*)(H + (size_t)r * DH + col4 * 4);
        s0 += v.x; q0 += v.x * v.x;
        s1 += v.y; q1 += v.y * v.y;
        s2 += v.z; q2 += v.z * v.z;
        s3 += v.w; q3 += v.w * v.w;
    }
    atomicAdd(&stats[col4 * 4 + 0], s0);
    atomicAdd(&stats[col4 * 4 + 1], s1);
    atomicAdd(&stats[col4 * 4 + 2], s2);
    atomicAdd(&stats[col4 * 4 + 3], s3);
    atomicAdd(&stats[256 + col4 * 4 + 0], q0);
    atomicAdd(&stats[256 + col4 * 4 + 1], q1);
    atomicAdd(&stats[256 + col4 * 4 + 2], q2);
    atomicAdd(&stats[256 + col4 * 4 + 3], q3);
}

__global__ void k_bnfinal(const float* __restrict__ stats,
                          const float* __restrict__ gam,
                          const float* __restrict__ bet,
                          float* __restrict__ bn) {
    int c = threadIdx.x;
    float mu  = stats[c] * (1.f / NN);
    float var = stats[256 + c] * (1.f / NN) - mu * mu;
    float rstd = rsqrtf(var + 1e-5f);
    float sc = rstd * gam[c];
    bn[c] = sc;
    bn[256 + c] = bet[c] - mu * sc;
}

// BN + ReLU (in place); optionally also writes hi/lo bf16 copy (next GEMM)
template <bool SPL>
__global__ void k_bnrelu(float* __restrict__ H, const float* __restrict__ bn,
                         bf16* __restrict__ Hi, bf16* __restrict__ Lo) {
    const int total = NN * DH / 4;
    for (int i = blockIdx.x * blockDim.x + threadIdx.x; i < total;
         i += gridDim.x * blockDim.x) {
        float4 v = ((float4*)H)[i];
        int c = (i & 63) * 4;
        v.x = fmaxf(0.f, v.x * bn[c + 0] + bn[256 + c + 0]);
        v.y = fmaxf(0.f, v.y * bn[c + 1] + bn[256 + c + 1]);
        v.z = fmaxf(0.f, v.z * bn[c + 2] + bn[256 + c + 2]);
        v.w = fmaxf(0.f, v.w * bn[c + 3] + bn[256 + c + 3]);
        ((float4*)H)[i] = v;
        if (SPL) {
            bf16 hx = __float2bfloat16(v.x), hy = __float2bfloat16(v.y);
            bf16 hz = __float2bfloat16(v.z), hw = __float2bfloat16(v.w);
            uint2 h = make_uint2(pk(__bfloat162float(hx), __bfloat162float(hy)),
                                 pk(__bfloat162float(hz), __bfloat162float(hw)));
            uint2 l = make_uint2(
                pk(v.x - __bfloat162float(hx), v.y - __bfloat162float(hy)),
                pk(v.z - __bfloat162float(hz), v.w - __bfloat162float(hw)));
            *(uint2*)((char*)Hi + (size_t)i * 8) = h;
            *(uint2*)((char*)Lo + (size_t)i * 8) = l;
        }
    }
}

// ---------------- final FC: [NN,256]@[256,32] ------------------------------
__global__ void __launch_bounds__(256) k_fc(const float* __restrict__ H,
                                            const float* __restrict__ W,
                                            const float* __restrict__ b,
                                            float* __restrict__ out) {
    __shared__ __align__(16) float Ws[DH * NCLS];
    for (int i = threadIdx.x; i < DH * NCLS / 4; i += 256)
        ((float4*)Ws)[i] = ((const float4*)W)[i];
    __syncthreads();
    int row = blockIdx.x * 32 + (threadIdx.x >> 3);
    int c = (threadIdx.x & 7) * 4;
    if (row >= NN) return;
    const float4* hr = (const float4*)(H + (size_t)row * DH);
    float4 acc = *(const float4*)(b + c);
#pragma unroll 8
    for (int k4 = 0; k4 < DH / 4; k4++) {
        float4 h = hr[k4];
        float4 w0 = *(float4*)&Ws[(k4 * 4 + 0) * NCLS + c];
        float4 w1 = *(float4*)&Ws[(k4 * 4 + 1) * NCLS + c];
        float4 w2 = *(float4*)&Ws[(k4 * 4 + 2) * NCLS + c];
        float4 w3 = *(float4*)&Ws[(k4 * 4 + 3) * NCLS + c];
        acc.x += h.x * w0.x + h.y * w1.x + h.z * w2.x + h.w * w3.x;
        acc.y += h.x * w0.y + h.y * w1.y + h.z * w2.y + h.w * w3.y;
        acc.z += h.x * w0.z + h.y * w1.z + h.z * w2.z + h.w * w3.z;
        acc.w += h.x * w0.w + h.y * w1.w + h.z * w2.w + h.w * w3.w;
    }
    *(float4*)(out + (size_t)row * NCLS + c) = acc;
}

// ---------------- launch ----------------------------------------------------
extern "C" void kernel_launch(void* const* d_in, const int* in_sizes, int n_in,
                              void* d_out, int out_size) {
    const float* x    = (const float*)d_in[0];
    const int*   esrc = (const int*)d_in[1];
    const int*   edst = (const int*)d_in[2];
    const float* W1l  = (const float*)d_in[3];
    const float* b1   = (const float*)d_in[4];
    const float* W1r  = (const float*)d_in[5];
    const float* g1   = (const float*)d_in[6];
    const float* be1  = (const float*)d_in[7];
    const float* W2l  = (const float*)d_in[8];
    const float* b2   = (const float*)d_in[9];
    const float* W2r  = (const float*)d_in[10];
    const float* g2   = (const float*)d_in[11];
    const float* be2  = (const float*)d_in[12];
    const float* Wfc  = (const float*)d_in[13];
    const float* bfc  = (const float*)d_in[14];
    float* out = (float*)d_out;

    bf16 *p_Ahi, *p_Alo, *p_Shi, *p_Slo, *p_B;
    float *p_h1, *p_h2, *p_stats, *p_bn;
    cudaGetSymbolAddress((void**)&p_Ahi,   g_Ahi);
    cudaGetSymbolAddress((void**)&p_Alo,   g_Alo);
    cudaGetSymbolAddress((void**)&p_Shi,   g_Shi);
    cudaGetSymbolAddress((void**)&p_Slo,   g_Slo);
    cudaGetSymbolAddress((void**)&p_B,     g_Bpack);
    cudaGetSymbolAddress((void**)&p_h1,    g_h1);
    cudaGetSymbolAddress((void**)&p_h2,    g_h2);
    cudaGetSymbolAddress((void**)&p_stats, g_stats);
    cudaGetSymbolAddress((void**)&p_bn,    g_bn);

    const int SMEM = 1024 + 3 * 16384;   // bias + 3 stages = 50176
    cudaFuncSetAttribute(k_mmagemm<DIN>,
                         cudaFuncAttributeMaxDynamicSharedMemorySize, SMEM);
    cudaFuncSetAttribute(k_mmagemm<DH>,
                         cudaFuncAttributeMaxDynamicSharedMemorySize, SMEM);

    const int nb1 = (NN + 1023) / 1024;
    const int egrid = (NE + 255) / 256;
    dim3 gg((NN + 127) / 128, 2);        // 782 x 2 CTAs

    k_init<<<(NN + 255) / 256, 256>>>();
    k_hist<<<egrid, 256>>>(edst);
    k_scan1<<<nb1, 1024>>>();
    k_scan2<<<1, 128>>>(nb1);
    k_scan3<<<nb1, 1024>>>();
    k_fill<<<egrid, 256>>>(esrc, edst);

    // layer 1
    k_split<<<2048, 256>>>(x, p_Shi, p_Slo, NN * DIN / 4);
    k_prepB<DIN><<<DIN, 256>>>(W1l, W1r, p_B);
    k_spmm<DIN><<<(NN + 7) / 8, 256>>>(x, p_Ahi, p_Alo);
    k_mmagemm<DIN><<<gg, 256, SMEM>>>(p_Ahi, p_Alo, p_Shi, p_Slo, p_B, b1, p_h1);
    k_stats<<<296, 256>>>(p_h1, p_stats);
    k_bnfinal<<<1, 256>>>(p_stats, g1, be1, p_bn);
    k_bnrelu<true><<<2048, 256>>>(p_h1, p_bn, p_Shi, p_Slo);

    // layer 2
    k_prepB<DH><<<DH, 256>>>(W2l, W2r, p_B);
    k_spmm<DH><<<(NN + 7) / 8, 256>>>(p_h1, p_Ahi, p_Alo);
    k_mmagemm<DH><<<gg, 256, SMEM>>>(p_Ahi, p_Alo, p_Shi, p_Slo, p_B, b2, p_h2);
    k_stats<<<296, 256>>>(p_h2, p_stats + 512);
    k_bnfinal<<<1, 256>>>(p_stats + 512, g2, be2, p_bn + 512);
    k_bnrelu<false><<<2048, 256>>>(p_h2, p_bn + 512, nullptr, nullptr);

    // classifier
    k_fc<<<(NN + 31) / 32, 256>>>(p_h2, Wfc, bfc, out);
}

// round 7
// speedup vs baseline: 1.3232x; 1.1065x over previous
#include <cuda_runtime.h>
#include <cuda_bf16.h>
#include <cstdint>

#define NN   100000
#define NE   1600000
#define DIN  128
#define DH   256
#define NCLS 32

typedef unsigned long long ull;
typedef __nv_bfloat16 bf16;

// ---------------- scratch (device globals) ---------------------------------
__device__ int   g_deg[NN];
__device__ int   g_rowptr[NN + 1];
__device__ int   g_cursor[NN];
__device__ int   g_csr[NE];
__device__ int   g_bsum[128];
__device__ __align__(128) bf16  g_Ahi[(size_t)NN * DH];
__device__ __align__(128) bf16  g_Alo[(size_t)NN * DH];
__device__ __align__(128) bf16  g_Shi[(size_t)NN * DH];
__device__ __align__(128) bf16  g_Slo[(size_t)NN * DH];
__device__ __align__(128) bf16  g_Bhi[DH * 2 * DH];     // 256 x 512 max
__device__ __align__(128) bf16  g_Blo[DH * 2 * DH];
__device__ __align__(128) float g_h1[(size_t)NN * DH];
__device__ __align__(128) float g_h2[(size_t)NN * DH];
__device__ float g_stats[1024];
__device__ float g_bn[1024];

// ---------------- helpers ---------------------------------------------------
__device__ __forceinline__ uint32_t smem_u32(const void* p) {
    uint32_t a;
    asm("{ .reg .u64 t; cvta.to.shared.u64 t, %1; cvt.u32.u64 %0, t; }"
        : "=r"(a) : "l"(p));
    return a;
}
__device__ __forceinline__ void cpasync16(uint32_t dst, const void* src) {
    asm volatile("cp.async.cg.shared.global [%0], [%1], 16;"
                 :: "r"(dst), "l"(src));
}
#define CP_COMMIT() asm volatile("cp.async.commit_group;" ::: "memory")

__device__ __forceinline__ void ldsm_x4(uint32_t* r, uint32_t addr) {
    asm volatile("ldmatrix.sync.aligned.m8n8.x4.shared.b16 {%0,%1,%2,%3}, [%4];"
                 : "=r"(r[0]), "=r"(r[1]), "=r"(r[2]), "=r"(r[3]) : "r"(addr));
}
__device__ __forceinline__ void ldsm_x2(uint32_t* r, uint32_t addr) {
    asm volatile("ldmatrix.sync.aligned.m8n8.x2.shared.b16 {%0,%1}, [%2];"
                 : "=r"(r[0]), "=r"(r[1]) : "r"(addr));
}
__device__ __forceinline__ void mma16816(float* c, const uint32_t* a,
                                         const uint32_t* b) {
    asm volatile(
        "mma.sync.aligned.m16n8k16.row.col.f32.bf16.bf16.f32 "
        "{%0,%1,%2,%3}, {%4,%5,%6,%7}, {%8,%9}, {%0,%1,%2,%3};"
        : "+f"(c[0]), "+f"(c[1]), "+f"(c[2]), "+f"(c[3])
        : "r"(a[0]), "r"(a[1]), "r"(a[2]), "r"(a[3]), "r"(b[0]), "r"(b[1]));
}

__device__ __forceinline__ uint32_t pk(float a, float b) {
    __nv_bfloat162 t = __floats2bfloat162_rn(a, b);
    return *(uint32_t*)&t;
}

// ---------------- scan helper ----------------------------------------------
__device__ __forceinline__ int block_scan_incl(int v) {
    __shared__ int ws[32];
    int lane = threadIdx.x & 31, wid = threadIdx.x >> 5;
#pragma unroll
    for (int o = 1; o < 32; o <<= 1) {
        int n = __shfl_up_sync(0xffffffffu, v, o);
        if (lane >= o) v += n;
    }
    if (lane == 31) ws[wid] = v;
    __syncthreads();
    int nw = blockDim.x >> 5;
    if (wid == 0) {
        int s = (lane < nw) ? ws[lane] : 0;
#pragma unroll
        for (int o = 1; o < 32; o <<= 1) {
            int n = __shfl_up_sync(0xffffffffu, s, o);
            if (lane >= o) s += n;
        }
        ws[lane] = s;
    }
    __syncthreads();
    if (wid > 0) v += ws[wid - 1];
    return v;
}

// ---------------- graph prep ----------------------------------------------
__global__ void k_init() {
    int i = blockIdx.x * blockDim.x + threadIdx.x;
    if (i < NN) { g_deg[i] = 0; g_cursor[i] = 0; }
    if (i < 1024) g_stats[i] = 0.f;
}
__global__ void k_hist(const int* __restrict__ dst) {
    int e = blockIdx.x * blockDim.x + threadIdx.x;
    if (e < NE) atomicAdd(&g_deg[dst[e]], 1);
}
__global__ void k_scan1() {
    int i = blockIdx.x * 1024 + threadIdx.x;
    int v = (i < NN) ? g_deg[i] : 0;
    int incl = block_scan_incl(v);
    if (i < NN) g_rowptr[i + 1] = incl;
    if (threadIdx.x == 1023) g_bsum[blockIdx.x] = incl;
}
__global__ void k_scan2(int nb) {
    int t = threadIdx.x;
    int v = (t < nb) ? g_bsum[t] : 0;
    int incl = block_scan_incl(v);
    if (t < nb) g_bsum[t] = incl;
}
__global__ void k_scan3() {
    int i = blockIdx.x * 1024 + threadIdx.x;
    if (i < NN && blockIdx.x > 0) g_rowptr[i + 1] += g_bsum[blockIdx.x - 1];
    if (i == 0) g_rowptr[0] = 0;
}
__global__ void k_fill(const int* __restrict__ src, const int* __restrict__ dst) {
    int e = blockIdx.x * blockDim.x + threadIdx.x;
    if (e < NE) {
        int d = dst[e];
        int p = atomicAdd(&g_cursor[d], 1);
        g_csr[g_rowptr[d] + p] = src[e];
    }
}

// ---------------- SpMM: 1 warp/node, index-preload + edge unroll ------------
template <int D>
__global__ void __launch_bounds__(256) k_spmm(const float* __restrict__ X,
                                              bf16* __restrict__ Ahi,
                                              bf16* __restrict__ Alo) {
    int warp = threadIdx.x >> 5, lane = threadIdx.x & 31;
    int node = blockIdx.x * 8 + warp;
    if (node >= NN) return;
    int beg = g_rowptr[node], end = g_rowptr[node + 1];
    int deg = end - beg;
    int myidx = (beg + lane < end) ? __ldg(&g_csr[beg + lane]) : 0;
    int dmax = deg < 32 ? deg : 32;

    float4 p0 = make_float4(0.f, 0.f, 0.f, 0.f);
    float4 p1 = make_float4(0.f, 0.f, 0.f, 0.f);
    float4 q0 = make_float4(0.f, 0.f, 0.f, 0.f);
    float4 q1 = make_float4(0.f, 0.f, 0.f, 0.f);

    int j = 0;
    if (D == 128) {
        for (; j + 4 <= dmax; j += 4) {
            int s0 = __shfl_sync(0xffffffffu, myidx, j + 0);
            int s1 = __shfl_sync(0xffffffffu, myidx, j + 1);
            int s2 = __shfl_sync(0xffffffffu, myidx, j + 2);
            int s3 = __shfl_sync(0xffffffffu, myidx, j + 3);
            float4 v0 = __ldg((const float4*)(X + (size_t)s0 * D) + lane);
            float4 v1 = __ldg((const float4*)(X + (size_t)s1 * D) + lane);
            float4 v2 = __ldg((const float4*)(X + (size_t)s2 * D) + lane);
            float4 v3 = __ldg((const float4*)(X + (size_t)s3 * D) + lane);
            p0.x += v0.x; p0.y += v0.y; p0.z += v0.z; p0.w += v0.w;
            q0.x += v1.x; q0.y += v1.y; q0.z += v1.z; q0.w += v1.w;
            p0.x += v2.x; p0.y += v2.y; p0.z += v2.z; p0.w += v2.w;
            q0.x += v3.x; q0.y += v3.y; q0.z += v3.z; q0.w += v3.w;
        }
    } else {
        for (; j + 2 <= dmax; j += 2) {
            int s0 = __shfl_sync(0xffffffffu, myidx, j + 0);
            int s1 = __shfl_sync(0xffffffffu, myidx, j + 1);
            const float4* r0 = (const float4*)(X + (size_t)s0 * D);
            const float4* r1 = (const float4*)(X + (size_t)s1 * D);
            float4 v0 = __ldg(r0 + lane);
            float4 v1 = __ldg(r0 + lane + 32);
            float4 w0 = __ldg(r1 + lane);
            float4 w1 = __ldg(r1 + lane + 32);
            p0.x += v0.x; p0.y += v0.y; p0.z += v0.z; p0.w += v0.w;
            p1.x += v1.x; p1.y += v1.y; p1.z += v1.z; p1.w += v1.w;
            q0.x += w0.x; q0.y += w0.y; q0.z += w0.z; q0.w += w0.w;
            q1.x += w1.x; q1.y += w1.y; q1.z += w1.z; q1.w += w1.w;
        }
    }
    for (; j < dmax; j++) {
        int s0 = __shfl_sync(0xffffffffu, myidx, j);
        const float4* r0 = (const float4*)(X + (size_t)s0 * D);
        float4 v0 = __ldg(r0 + lane);
        p0.x += v0.x; p0.y += v0.y; p0.z += v0.z; p0.w += v0.w;
        if (D == 256) {
            float4 v1 = __ldg(r0 + lane + 32);
            p1.x += v1.x; p1.y += v1.y; p1.z += v1.z; p1.w += v1.w;
        }
    }
    // rare long-tail (deg > 32)
    for (int jj = beg + 32; jj < end; jj++) {
        int s0 = __ldg(&g_csr[jj]);
        const float4* r0 = (const float4*)(X + (size_t)s0 * D);
        float4 v0 = __ldg(r0 + lane);
        p0.x += v0.x; p0.y += v0.y; p0.z += v0.z; p0.w += v0.w;
        if (D == 256) {
            float4 v1 = __ldg(r0 + lane + 32);
            p1.x += v1.x; p1.y += v1.y; p1.z += v1.z; p1.w += v1.w;
        }
    }

    float inv = 1.f / fmaxf((float)deg, 1.f);
    float4 a0 = make_float4((p0.x + q0.x) * inv, (p0.y + q0.y) * inv,
                            (p0.z + q0.z) * inv, (p0.w + q0.w) * inv);
    float4 a1 = make_float4((p1.x + q1.x) * inv, (p1.y + q1.y) * inv,
                            (p1.z + q1.z) * inv, (p1.w + q1.w) * inv);

    auto wr = [&](float4 v, int colbase) {
        bf16 hx = __float2bfloat16(v.x), hy = __float2bfloat16(v.y);
        bf16 hz = __float2bfloat16(v.z), hw = __float2bfloat16(v.w);
        uint2 h = make_uint2(pk(__bfloat162float(hx), __bfloat162float(hy)),
                             pk(__bfloat162float(hz), __bfloat162float(hw)));
        uint2 l = make_uint2(
            pk(v.x - __bfloat162float(hx), v.y - __bfloat162float(hy)),
            pk(v.z - __bfloat162float(hz), v.w - __bfloat162float(hw)));
        *(uint2*)(Ahi + (size_t)node * D + colbase) = h;
        *(uint2*)(Alo + (size_t)node * D + colbase) = l;
    };
    wr(a0, lane * 4);
    if (D == 256) wr(a1, 128 + lane * 4);
}

// ---------------- x -> hi/lo split -----------------------------------------
__global__ void k_split(const float* __restrict__ X, bf16* __restrict__ Hi,
                        bf16* __restrict__ Lo, int total4) {
    for (int i = blockIdx.x * blockDim.x + threadIdx.x; i < total4;
         i += gridDim.x * blockDim.x) {
        float4 v = ((const float4*)X)[i];
        bf16 hx = __float2bfloat16(v.x), hy = __float2bfloat16(v.y);
        bf16 hz = __float2bfloat16(v.z), hw = __float2bfloat16(v.w);
        uint2 h = make_uint2(pk(__bfloat162float(hx), __bfloat162float(hy)),
                             pk(__bfloat162float(hz), __bfloat162float(hw)));
        uint2 l = make_uint2(pk(v.x - __bfloat162float(hx), v.y - __bfloat162float(hy)),
                             pk(v.z - __bfloat162float(hz), v.w - __bfloat162float(hw)));
        *(uint2*)((char*)Hi + (size_t)i * 8) = h;
        *(uint2*)((char*)Lo + (size_t)i * 8) = l;
    }
}

// ---------------- weight prep: Bhi/Blo [n][2K] bf16 K-major ----------------
// k-order along 2K: [Wl (K) | Wr (K)] matching A'' = [Aagg | Aself]
template <int K>
__global__ void k_prepB(const float* __restrict__ Wl, const float* __restrict__ Wr,
                        bf16* __restrict__ Bh, bf16* __restrict__ Bl) {
    int idx = blockIdx.x * 256 + threadIdx.x;
    if (idx >= K * 256) return;
    int k = idx >> 8, n = idx & 255;
    const int LDB = 2 * K;
    float a = Wl[idx];
    bf16 ha = __float2bfloat16(a);
    Bh[(size_t)n * LDB + k] = ha;
    Bl[(size_t)n * LDB + k] = __float2bfloat16(a - __bfloat162float(ha));
    float b = Wr[idx];
    bf16 hb = __float2bfloat16(b);
    Bh[(size_t)n * LDB + K + k] = hb;
    Bl[(size_t)n * LDB + K + k] = __float2bfloat16(b - __bfloat162float(hb));
}

// ---------------- mma.sync GEMM, pair-in-smem compensated -------------------
// CTA 128x128, chunk = 32-wide slice of K''=2K. Stage holds Ahi/Alo/Bhi/Blo.
// Products per chunk: aH*bH + aH*bL + aL*bH (all into same acc).
template <int K>
__global__ void __launch_bounds__(256)
k_mmagemm(const bf16* __restrict__ Ahi, const bf16* __restrict__ Alo,
          const bf16* __restrict__ Shi, const bf16* __restrict__ Slo,
          const bf16* __restrict__ Bh,  const bf16* __restrict__ Bl,
          const float* __restrict__ bias, float* __restrict__ Out) {
    constexpr int CH  = 2 * K / 32;
    constexpr int LDB = 2 * K;
    constexpr int T_AH = 0, T_AL = 8192, T_BH = 16384, T_BL = 24576;
    constexpr int STAGE = 32768;

    extern __shared__ __align__(128) char dsm[];
    float* sbias = (float*)dsm;                 // 512B
    uint32_t stage0 = smem_u32(dsm) + 1024;

    const int t = threadIdx.x;
    const int wid = t >> 5, lane = t & 31;
    const int wm = wid >> 2, wn = wid & 3;       // warps 2 x 4
    const int m0 = blockIdx.x * 128;
    const int n0 = blockIdx.y * 128;

    if (t < 128) sbias[t] = bias[n0 + t];

    float acc[4][4][4];
#pragma unroll
    for (int i = 0; i < 4; i++)
#pragma unroll
        for (int j = 0; j < 4; j++)
#pragma unroll
            for (int q = 0; q < 4; q++) acc[i][j][q] = 0.f;

    auto load_chunk = [&](int c, int s) {
        uint32_t sb = stage0 + s * STAGE;
        const bf16* Ah; const bf16* Al; int k0;
        if (c < K / 32) { Ah = Ahi; Al = Alo; k0 = c * 32; }
        else            { Ah = Shi; Al = Slo; k0 = (c - K / 32) * 32; }
#pragma unroll
        for (int it = 0; it < 2; it++) {
            int i = t + 256 * it;                 // 0..511
            int row = i >> 2, ch = i & 3;
            uint32_t sw = row * 64 + ((ch ^ (row & 3)) << 4);
            int gr = m0 + row; if (gr > NN - 1) gr = NN - 1;
            cpasync16(sb + T_AH + sw, Ah + (size_t)gr * K + k0 + ch * 8);
            cpasync16(sb + T_AL + sw, Al + (size_t)gr * K + k0 + ch * 8);
            size_t boff = (size_t)(n0 + row) * LDB + c * 32 + ch * 8;
            cpasync16(sb + T_BH + sw, Bh + boff);
            cpasync16(sb + T_BL + sw, Bl + boff);
        }
        CP_COMMIT();
    };

    load_chunk(0, 0);
    load_chunk(1, 1);
    load_chunk(2, 2);

#pragma unroll 1
    for (int c = 0; c < CH; c++) {
        int s = c % 3;
        int rem = CH - 1 - c;
        if (rem >= 2)      asm volatile("cp.async.wait_group 2;" ::: "memory");
        else if (rem == 1) asm volatile("cp.async.wait_group 1;" ::: "memory");
        else               asm volatile("cp.async.wait_group 0;" ::: "memory");
        __syncthreads();

        uint32_t sb = stage0 + s * STAGE;
#pragma unroll
        for (int ks = 0; ks < 2; ks++) {
            uint32_t aH[4][4], aL[4][4], bH[4][2], bL[4][2];
#pragma unroll
            for (int mt = 0; mt < 4; mt++) {
                int r = wm * 64 + mt * 16 + (lane & 15);
                int kc = ks * 2 + (lane >> 4);
                uint32_t sw = r * 64 + ((kc ^ (r & 3)) << 4);
                ldsm_x4(aH[mt], sb + T_AH + sw);
                ldsm_x4(aL[mt], sb + T_AL + sw);
            }
#pragma unroll
            for (int nt = 0; nt < 4; nt++) {
                int l15 = lane & 15;
                int n = wn * 32 + nt * 8 + (l15 & 7);
                int kc = ks * 2 + (l15 >> 3);
                uint32_t sw = n * 64 + ((kc ^ (n & 3)) << 4);
                ldsm_x2(bH[nt], sb + T_BH + sw);
                ldsm_x2(bL[nt], sb + T_BL + sw);
            }
#pragma unroll
            for (int mt = 0; mt < 4; mt++)
#pragma unroll
                for (int nt = 0; nt < 4; nt++) {
                    mma16816(acc[mt][nt], aH[mt], bH[nt]);
                    mma16816(acc[mt][nt], aH[mt], bL[nt]);
                    mma16816(acc[mt][nt], aL[mt], bH[nt]);
                }
        }
        __syncthreads();
        if (c + 3 < CH) load_chunk(c + 3, s);
    }

    // epilogue: bias + store
#pragma unroll
    for (int mt = 0; mt < 4; mt++) {
        int r0 = m0 + wm * 64 + mt * 16 + (lane >> 2);
#pragma unroll
        for (int nt = 0; nt < 4; nt++) {
            int lc = wn * 32 + nt * 8 + (lane & 3) * 2;
            float bx = sbias[lc], by = sbias[lc + 1];
            if (r0 < NN) {
                float2 v = make_float2(acc[mt][nt][0] + bx, acc[mt][nt][1] + by);
                *(float2*)(Out + (size_t)r0 * DH + n0 + lc) = v;
            }
            if (r0 + 8 < NN) {
                float2 v = make_float2(acc[mt][nt][2] + bx, acc[mt][nt][3] + by);
                *(float2*)(Out + (size_t)(r0 + 8) * DH + n0 + lc) = v;
            }
        }
    }
}

// ---------------- BN column stats ------------------------------------------
__global__ void __launch_bounds__(256) k_stats(const float* __restrict__ H,
                                               float* __restrict__ stats) {
    int t = threadIdx.x;
    int col4 = t & 63;
    int rl = t >> 6;
    float s0 = 0, s1 = 0, s2 = 0, s3 = 0, q0 = 0, q1 = 0, q2 = 0, q3 = 0;
    for (int r = blockIdx.x * 4 + rl; r < NN; r += gridDim.x * 4) {
        float4 v = *(const float4*)(H + (size_t)r * DH + col4 * 4);
        s0 += v.x; q0 += v.x * v.x;
        s1 += v.y; q1 += v.y * v.y;
        s2 += v.z; q2 += v.z * v.z;
        s3 += v.w; q3 += v.w * v.w;
    }
    atomicAdd(&stats[col4 * 4 + 0], s0);
    atomicAdd(&stats[col4 * 4 + 1], s1);
    atomicAdd(&stats[col4 * 4 + 2], s2);
    atomicAdd(&stats[col4 * 4 + 3], s3);
    atomicAdd(&stats[256 + col4 * 4 + 0], q0);
    atomicAdd(&stats[256 + col4 * 4 + 1], q1);
    atomicAdd(&stats[256 + col4 * 4 + 2], q2);
    atomicAdd(&stats[256 + col4 * 4 + 3], q3);
}

__global__ void k_bnfinal(const float* __restrict__ stats,
                          const float* __restrict__ gam,
                          const float* __restrict__ bet,
                          float* __restrict__ bn) {
    int c = threadIdx.x;
    float mu  = stats[c] * (1.f / NN);
    float var = stats[256 + c] * (1.f / NN) - mu * mu;
    float rstd = rsqrtf(var + 1e-5f);
    float sc = rstd * gam[c];
    bn[c] = sc;
    bn[256 + c] = bet[c] - mu * sc;
}

// BN + ReLU in place + hi/lo bf16 split-out (layer 1 only)
__global__ void k_bnrelu(float* __restrict__ H, const float* __restrict__ bn,
                         bf16* __restrict__ Hi, bf16* __restrict__ Lo) {
    const int total = NN * DH / 4;
    for (int i = blockIdx.x * blockDim.x + threadIdx.x; i < total;
         i += gridDim.x * blockDim.x) {
        float4 v = ((float4*)H)[i];
        int c = (i & 63) * 4;
        v.x = fmaxf(0.f, v.x * bn[c + 0] + bn[256 + c + 0]);
        v.y = fmaxf(0.f, v.y * bn[c + 1] + bn[256 + c + 1]);
        v.z = fmaxf(0.f, v.z * bn[c + 2] + bn[256 + c + 2]);
        v.w = fmaxf(0.f, v.w * bn[c + 3] + bn[256 + c + 3]);
        ((float4*)H)[i] = v;
        bf16 hx = __float2bfloat16(v.x), hy = __float2bfloat16(v.y);
        bf16 hz = __float2bfloat16(v.z), hw = __float2bfloat16(v.w);
        uint2 h = make_uint2(pk(__bfloat162float(hx), __bfloat162float(hy)),
                             pk(__bfloat162float(hz), __bfloat162float(hw)));
        uint2 l = make_uint2(
            pk(v.x - __bfloat162float(hx), v.y - __bfloat162float(hy)),
            pk(v.z - __bfloat162float(hz), v.w - __bfloat162float(hw)));
        *(uint2*)((char*)Hi + (size_t)i * 8) = h;
        *(uint2*)((char*)Lo + (size_t)i * 8) = l;
    }
}

// ---------------- final FC with fused BN+ReLU ------------------------------
__global__ void __launch_bounds__(256) k_fc(const float* __restrict__ H,
                                            const float* __restrict__ bn,
                                            const float* __restrict__ W,
                                            const float* __restrict__ b,
                                            float* __restrict__ out) {
    __shared__ __align__(16) float Ws[DH * NCLS];
    __shared__ float sbn[512];
    for (int i = threadIdx.x; i < DH * NCLS / 4; i += 256)
        ((float4*)Ws)[i] = ((const float4*)W)[i];
    if (threadIdx.x < 256) {
        sbn[threadIdx.x] = bn[threadIdx.x];
        sbn[256 + threadIdx.x] = bn[256 + threadIdx.x];
    }
    __syncthreads();
    int row = blockIdx.x * 32 + (threadIdx.x >> 3);
    int c = (threadIdx.x & 7) * 4;
    if (row >= NN) return;
    const float4* hr = (const float4*)(H + (size_t)row * DH);
    float4 acc = *(const float4*)(b + c);
#pragma unroll 8
    for (int k4 = 0; k4 < DH / 4; k4++) {
        float4 h = hr[k4];
        int kb = k4 * 4;
        h.x = fmaxf(0.f, h.x * sbn[kb + 0] + sbn[256 + kb + 0]);
        h.y = fmaxf(0.f, h.y * sbn[kb + 1] + sbn[256 + kb + 1]);
        h.z = fmaxf(0.f, h.z * sbn[kb + 2] + sbn[256 + kb + 2]);
        h.w = fmaxf(0.f, h.w * sbn[kb + 3] + sbn[256 + kb + 3]);
        float4 w0 = *(float4*)&Ws[(kb + 0) * NCLS + c];
        float4 w1 = *(float4*)&Ws[(kb + 1) * NCLS + c];
        float4 w2 = *(float4*)&Ws[(kb + 2) * NCLS + c];
        float4 w3 = *(float4*)&Ws[(kb + 3) * NCLS + c];
        acc.x += h.x * w0.x + h.y * w1.x + h.z * w2.x + h.w * w3.x;
        acc.y += h.x * w0.y + h.y * w1.y + h.z * w2.y + h.w * w3.y;
        acc.z += h.x * w0.z + h.y * w1.z + h.z * w2.z + h.w * w3.z;
        acc.w += h.x * w0.w + h.y * w1.w + h.z * w2.w + h.w * w3.w;
    }
    *(float4*)(out + (size_t)row * NCLS + c) = acc;
}

// ---------------- launch ----------------------------------------------------
extern "C" void kernel_launch(void* const* d_in, const int* in_sizes, int n_in,
                              void* d_out, int out_size) {
    const float* x    = (const float*)d_in[0];
    const int*   esrc = (const int*)d_in[1];
    const int*   edst = (const int*)d_in[2];
    const float* W1l  = (const float*)d_in[3];
    const float* b1   = (const float*)d_in[4];
    const float* W1r  = (const float*)d_in[5];
    const float* g1   = (const float*)d_in[6];
    const float* be1  = (const float*)d_in[7];
    const float* W2l  = (const float*)d_in[8];
    const float* b2   = (const float*)d_in[9];
    const float* W2r  = (const float*)d_in[10];
    const float* g2   = (const float*)d_in[11];
    const float* be2  = (const float*)d_in[12];
    const float* Wfc  = (const float*)d_in[13];
    const float* bfc  = (const float*)d_in[14];
    float* out = (float*)d_out;

    bf16 *p_Ahi, *p_Alo, *p_Shi, *p_Slo, *p_Bh, *p_Bl;
    float *p_h1, *p_h2, *p_stats, *p_bn;
    cudaGetSymbolAddress((void**)&p_Ahi,   g_Ahi);
    cudaGetSymbolAddress((void**)&p_Alo,   g_Alo);
    cudaGetSymbolAddress((void**)&p_Shi,   g_Shi);
    cudaGetSymbolAddress((void**)&p_Slo,   g_Slo);
    cudaGetSymbolAddress((void**)&p_Bh,    g_Bhi);
    cudaGetSymbolAddress((void**)&p_Bl,    g_Blo);
    cudaGetSymbolAddress((void**)&p_h1,    g_h1);
    cudaGetSymbolAddress((void**)&p_h2,    g_h2);
    cudaGetSymbolAddress((void**)&p_stats, g_stats);
    cudaGetSymbolAddress((void**)&p_bn,    g_bn);

    const int SMEM = 1024 + 3 * 32768;   // bias + 3 stages = 99328
    cudaFuncSetAttribute(k_mmagemm<DIN>,
                         cudaFuncAttributeMaxDynamicSharedMemorySize, SMEM);
    cudaFuncSetAttribute(k_mmagemm<DH>,
                         cudaFuncAttributeMaxDynamicSharedMemorySize, SMEM);

    const int nb1 = (NN + 1023) / 1024;
    const int egrid = (NE + 255) / 256;
    dim3 gg((NN + 127) / 128, 2);        // 782 x 2 CTAs

    k_init<<<(NN + 255) / 256, 256>>>();
    k_hist<<<egrid, 256>>>(edst);
    k_scan1<<<nb1, 1024>>>();
    k_scan2<<<1, 128>>>(nb1);
    k_scan3<<<nb1, 1024>>>();
    k_fill<<<egrid, 256>>>(esrc, edst);

    // layer 1
    k_split<<<2048, 256>>>(x, p_Shi, p_Slo, NN * DIN / 4);
    k_prepB<DIN><<<DIN, 256>>>(W1l, W1r, p_Bh, p_Bl);
    k_spmm<DIN><<<(NN + 7) / 8, 256>>>(x, p_Ahi, p_Alo);
    k_mmagemm<DIN><<<gg, 256, SMEM>>>(p_Ahi, p_Alo, p_Shi, p_Slo, p_Bh, p_Bl,
                                      b1, p_h1);
    k_stats<<<296, 256>>>(p_h1, p_stats);
    k_bnfinal<<<1, 256>>>(p_stats, g1, be1, p_bn);
    k_bnrelu<<<2048, 256>>>(p_h1, p_bn, p_Shi, p_Slo);

    // layer 2
    k_prepB<DH><<<DH, 256>>>(W2l, W2r, p_Bh, p_Bl);
    k_spmm<DH><<<(NN + 7) / 8, 256>>>(p_h1, p_Ahi, p_Alo);
    k_mmagemm<DH><<<gg, 256, SMEM>>>(p_Ahi, p_Alo, p_Shi, p_Slo, p_Bh, p_Bl,
                                     b2, p_h2);
    k_stats<<<296, 256>>>(p_h2, p_stats + 512);
    k_bnfinal<<<1, 256>>>(p_stats + 512, g2, be2, p_bn + 512);

    // classifier (BN+ReLU fused)
    k_fc<<<(NN + 31) / 32, 256>>>(p_h2, p_bn + 512, Wfc, bfc, out);
}

// round 8
// speedup vs baseline: 1.7681x; 1.3362x over previous
#include <cuda_runtime.h>
#include <cuda_fp16.h>
#include <cstdint>

#define NN   100000
#define NE   1600000
#define DIN  128
#define DH   256
#define NCLS 32

typedef unsigned long long ull;

// ---------------- scratch (device globals) ---------------------------------
__device__ int   g_deg[NN];
__device__ int   g_rowptr[NN + 1];
__device__ int   g_cursor[NN];
__device__ int   g_csr[NE];
__device__ int   g_bsum[128];
__device__ __align__(128) __half g_Ahi[(size_t)NN * DH];
__device__ __align__(128) __half g_Alo[(size_t)NN * DH];
__device__ __align__(128) __half g_Shi[(size_t)NN * DH];
__device__ __align__(128) __half g_Slo[(size_t)NN * DH];
__device__ __align__(128) __half g_Bhi[DH * 2 * DH];     // 256 x 512 max
__device__ __align__(128) float  g_h1[(size_t)NN * DH];
__device__ __align__(128) float  g_h2[(size_t)NN * DH];
__device__ float g_stats[1024];
__device__ float g_bn[1024];

// ---------------- helpers ---------------------------------------------------
__device__ __forceinline__ uint32_t smem_u32(const void* p) {
    uint32_t a;
    asm("{ .reg .u64 t; cvta.to.shared.u64 t, %1; cvt.u32.u64 %0, t; }"
        : "=r"(a) : "l"(p));
    return a;
}
__device__ __forceinline__ void cpasync16(uint32_t dst, const void* src) {
    asm volatile("cp.async.cg.shared.global [%0], [%1], 16;"
                 :: "r"(dst), "l"(src));
}
#define CP_COMMIT() asm volatile("cp.async.commit_group;" ::: "memory")

__device__ __forceinline__ void ldsm_x4(uint32_t* r, uint32_t addr) {
    asm volatile("ldmatrix.sync.aligned.m8n8.x4.shared.b16 {%0,%1,%2,%3}, [%4];"
                 : "=r"(r[0]), "=r"(r[1]), "=r"(r[2]), "=r"(r[3]) : "r"(addr));
}
__device__ __forceinline__ void ldsm_x2(uint32_t* r, uint32_t addr) {
    asm volatile("ldmatrix.sync.aligned.m8n8.x2.shared.b16 {%0,%1}, [%2];"
                 : "=r"(r[0]), "=r"(r[1]) : "r"(addr));
}
__device__ __forceinline__ void mma16816(float* c, const uint32_t* a,
                                         const uint32_t* b) {
    asm volatile(
        "mma.sync.aligned.m16n8k16.row.col.f32.f16.f16.f32 "
        "{%0,%1,%2,%3}, {%4,%5,%6,%7}, {%8,%9}, {%0,%1,%2,%3};"
        : "+f"(c[0]), "+f"(c[1]), "+f"(c[2]), "+f"(c[3])
        : "r"(a[0]), "r"(a[1]), "r"(a[2]), "r"(a[3]), "r"(b[0]), "r"(b[1]));
}

__device__ __forceinline__ uint32_t pkh(float a, float b) {
    __half2 t = __floats2half2_rn(a, b);
    return *(uint32_t*)&t;
}

// ---------------- scan helper ----------------------------------------------
__device__ __forceinline__ int block_scan_incl(int v) {
    __shared__ int ws[32];
    int lane = threadIdx.x & 31, wid = threadIdx.x >> 5;
#pragma unroll
    for (int o = 1; o < 32; o <<= 1) {
        int n = __shfl_up_sync(0xffffffffu, v, o);
        if (lane >= o) v += n;
    }
    if (lane == 31) ws[wid] = v;
    __syncthreads();
    int nw = blockDim.x >> 5;
    if (wid == 0) {
        int s = (lane < nw) ? ws[lane] : 0;
#pragma unroll
        for (int o = 1; o < 32; o <<= 1) {
            int n = __shfl_up_sync(0xffffffffu, s, o);
            if (lane >= o) s += n;
        }
        ws[lane] = s;
    }
    __syncthreads();
    if (wid > 0) v += ws[wid - 1];
    return v;
}

// ---------------- graph prep ----------------------------------------------
__global__ void k_init() {
    int i = blockIdx.x * blockDim.x + threadIdx.x;
    if (i < NN) { g_deg[i] = 0; g_cursor[i] = 0; }
    if (i < 1024) g_stats[i] = 0.f;
}
__global__ void k_hist(const int* __restrict__ dst) {
    int e = blockIdx.x * blockDim.x + threadIdx.x;
    if (e < NE) atomicAdd(&g_deg[dst[e]], 1);
}
__global__ void k_scan1() {
    int i = blockIdx.x * 1024 + threadIdx.x;
    int v = (i < NN) ? g_deg[i] : 0;
    int incl = block_scan_incl(v);
    if (i < NN) g_rowptr[i + 1] = incl;
    if (threadIdx.x == 1023) g_bsum[blockIdx.x] = incl;
}
__global__ void k_scan2(int nb) {
    int t = threadIdx.x;
    int v = (t < nb) ? g_bsum[t] : 0;
    int incl = block_scan_incl(v);
    if (t < nb) g_bsum[t] = incl;
}
__global__ void k_scan3() {
    int i = blockIdx.x * 1024 + threadIdx.x;
    if (i < NN && blockIdx.x > 0) g_rowptr[i + 1] += g_bsum[blockIdx.x - 1];
    if (i == 0) g_rowptr[0] = 0;
}
__global__ void k_fill(const int* __restrict__ src, const int* __restrict__ dst) {
    int e = blockIdx.x * blockDim.x + threadIdx.x;
    if (e < NE) {
        int d = dst[e];
        int p = atomicAdd(&g_cursor[d], 1);
        g_csr[g_rowptr[d] + p] = src[e];
    }
}

// ---------------- x -> hi/lo fp16 split ------------------------------------
__global__ void k_split(const float* __restrict__ X, __half* __restrict__ Hi,
                        __half* __restrict__ Lo, int total4) {
    for (int i = blockIdx.x * blockDim.x + threadIdx.x; i < total4;
         i += gridDim.x * blockDim.x) {
        float4 v = ((const float4*)X)[i];
        __half hx = __float2half_rn(v.x), hy = __float2half_rn(v.y);
        __half hz = __float2half_rn(v.z), hw = __float2half_rn(v.w);
        uint2 h = make_uint2(pkh(__half2float(hx), __half2float(hy)),
                             pkh(__half2float(hz), __half2float(hw)));
        uint2 l = make_uint2(pkh(v.x - __half2float(hx), v.y - __half2float(hy)),
                             pkh(v.z - __half2float(hz), v.w - __half2float(hw)));
        *(uint2*)((char*)Hi + (size_t)i * 8) = h;
        *(uint2*)((char*)Lo + (size_t)i * 8) = l;
    }
}

// ---------------- SpMM layer1: gather fp16 hi table (D=128) ----------------
__global__ void __launch_bounds__(256) k_spmm1(const __half* __restrict__ Xh,
                                               __half* __restrict__ Ahi,
                                               __half* __restrict__ Alo) {
    int warp = threadIdx.x >> 5, lane = threadIdx.x & 31;
    int node = blockIdx.x * 8 + warp;
    if (node >= NN) return;
    int beg = g_rowptr[node], end = g_rowptr[node + 1];
    int deg = end - beg;
    int myidx = (beg + lane < end) ? __ldg(&g_csr[beg + lane]) : 0;
    int dmax = deg < 32 ? deg : 32;

    float4 p = make_float4(0.f, 0.f, 0.f, 0.f);
    float4 q = make_float4(0.f, 0.f, 0.f, 0.f);

    auto addu2 = [&](float4& a, uint2 u) {
        __half2* ph = (__half2*)&u;
        float2 f0 = __half22float2(ph[0]);
        float2 f1 = __half22float2(ph[1]);
        a.x += f0.x; a.y += f0.y; a.z += f1.x; a.w += f1.y;
    };

    int j = 0;
    for (; j + 4 <= dmax; j += 4) {
        int s0 = __shfl_sync(0xffffffffu, myidx, j + 0);
        int s1 = __shfl_sync(0xffffffffu, myidx, j + 1);
        int s2 = __shfl_sync(0xffffffffu, myidx, j + 2);
        int s3 = __shfl_sync(0xffffffffu, myidx, j + 3);
        uint2 u0 = __ldg((const uint2*)(Xh + (size_t)s0 * DIN) + lane);
        uint2 u1 = __ldg((const uint2*)(Xh + (size_t)s1 * DIN) + lane);
        uint2 u2 = __ldg((const uint2*)(Xh + (size_t)s2 * DIN) + lane);
        uint2 u3 = __ldg((const uint2*)(Xh + (size_t)s3 * DIN) + lane);
        addu2(p, u0); addu2(q, u1); addu2(p, u2); addu2(q, u3);
    }
    for (; j < dmax; j++) {
        int s0 = __shfl_sync(0xffffffffu, myidx, j);
        addu2(p, __ldg((const uint2*)(Xh + (size_t)s0 * DIN) + lane));
    }
    for (int jj = beg + 32; jj < end; jj++) {
        int s0 = __ldg(&g_csr[jj]);
        addu2(p, __ldg((const uint2*)(Xh + (size_t)s0 * DIN) + lane));
    }

    float inv = 1.f / fmaxf((float)deg, 1.f);
    float4 a = make_float4((p.x + q.x) * inv, (p.y + q.y) * inv,
                           (p.z + q.z) * inv, (p.w + q.w) * inv);
    __half hx = __float2half_rn(a.x), hy = __float2half_rn(a.y);
    __half hz = __float2half_rn(a.z), hw = __float2half_rn(a.w);
    uint2 h = make_uint2(pkh(__half2float(hx), __half2float(hy)),
                         pkh(__half2float(hz), __half2float(hw)));
    uint2 l = make_uint2(pkh(a.x - __half2float(hx), a.y - __half2float(hy)),
                         pkh(a.z - __half2float(hz), a.w - __half2float(hw)));
    *(uint2*)(Ahi + (size_t)node * DIN + lane * 4) = h;
    *(uint2*)(Alo + (size_t)node * DIN + lane * 4) = l;
}

// ---------------- SpMM layer2: gather fp16 hi table (D=256) ----------------
__global__ void __launch_bounds__(256) k_spmm2(const __half* __restrict__ Xh,
                                               __half* __restrict__ Ahi,
                                               __half* __restrict__ Alo) {
    int warp = threadIdx.x >> 5, lane = threadIdx.x & 31;
    int node = blockIdx.x * 8 + warp;
    if (node >= NN) return;
    int beg = g_rowptr[node], end = g_rowptr[node + 1];
    int deg = end - beg;
    int myidx = (beg + lane < end) ? __ldg(&g_csr[beg + lane]) : 0;
    int dmax = deg < 32 ? deg : 32;

    float p[8] = {0, 0, 0, 0, 0, 0, 0, 0};
    float q[8] = {0, 0, 0, 0, 0, 0, 0, 0};

    auto addu4 = [&](float* a, uint4 u) {
        __half2* ph = (__half2*)&u;
#pragma unroll
        for (int z = 0; z < 4; z++) {
            float2 f = __half22float2(ph[z]);
            a[z * 2] += f.x; a[z * 2 + 1] += f.y;
        }
    };

    int j = 0;
    for (; j + 2 <= dmax; j += 2) {
        int s0 = __shfl_sync(0xffffffffu, myidx, j + 0);
        int s1 = __shfl_sync(0xffffffffu, myidx, j + 1);
        uint4 u0 = __ldg((const uint4*)(Xh + (size_t)s0 * DH) + lane);
        uint4 u1 = __ldg((const uint4*)(Xh + (size_t)s1 * DH) + lane);
        addu4(p, u0); addu4(q, u1);
    }
    for (; j < dmax; j++) {
        int s0 = __shfl_sync(0xffffffffu, myidx, j);
        addu4(p, __ldg((const uint4*)(Xh + (size_t)s0 * DH) + lane));
    }
    for (int jj = beg + 32; jj < end; jj++) {
        int s0 = __ldg(&g_csr[jj]);
        addu4(p, __ldg((const uint4*)(Xh + (size_t)s0 * DH) + lane));
    }

    float inv = 1.f / fmaxf((float)deg, 1.f);
    uint4 h, l;
    uint32_t* hp = (uint32_t*)&h;
    uint32_t* lp = (uint32_t*)&l;
#pragma unroll
    for (int z = 0; z < 4; z++) {
        float v0 = (p[z * 2] + q[z * 2]) * inv;
        float v1 = (p[z * 2 + 1] + q[z * 2 + 1]) * inv;
        __half h0 = __float2half_rn(v0), h1 = __float2half_rn(v1);
        hp[z] = pkh(__half2float(h0), __half2float(h1));
        lp[z] = pkh(v0 - __half2float(h0), v1 - __half2float(h1));
    }
    *(uint4*)(Ahi + (size_t)node * DH + lane * 8) = h;
    *(uint4*)(Alo + (size_t)node * DH + lane * 8) = l;
}

// ---------------- weight prep: Bh [n][2K] fp16 K-major ----------------------
template <int K>
__global__ void k_prepB(const float* __restrict__ Wl, const float* __restrict__ Wr,
                        __half* __restrict__ Bh) {
    int idx = blockIdx.x * 256 + threadIdx.x;
    if (idx >= K * 256) return;
    int k = idx >> 8, n = idx & 255;
    const int LDB = 2 * K;
    Bh[(size_t)n * LDB + k]     = __float2half_rn(Wl[idx]);
    Bh[(size_t)n * LDB + K + k] = __float2half_rn(Wr[idx]);
}

// ---------------- mma.sync GEMM fp16 2-product + fused BN stats -------------
// CTA 128x128. Stage: Ahi 8KB + Alo 8KB + Bh 8KB. acc += aH*bH + aL*bH.
template <int K>
__global__ void __launch_bounds__(256)
k_mmagemm(const __half* __restrict__ Ahi, const __half* __restrict__ Alo,
          const __half* __restrict__ Shi, const __half* __restrict__ Slo,
          const __half* __restrict__ Bh,  const float* __restrict__ bias,
          float* __restrict__ Out, float* __restrict__ stats) {
    constexpr int CH  = 2 * K / 32;
    constexpr int LDB = 2 * K;
    constexpr int T_AH = 0, T_AL = 8192, T_BH = 16384;
    constexpr int STAGE = 24576;

    extern __shared__ __align__(128) char dsm[];
    float* sbias = (float*)dsm;                 // 512B
    float* s_red = (float*)(dsm + 512);         // 1KB: sum[128], sq[128]
    uint32_t stage0 = smem_u32(dsm) + 2048;

    const int t = threadIdx.x;
    const int wid = t >> 5, lane = t & 31;
    const int wm = wid >> 2, wn = wid & 3;       // warps 2 x 4
    const int m0 = blockIdx.x * 128;
    const int n0 = blockIdx.y * 128;

    if (t < 128) { sbias[t] = bias[n0 + t]; s_red[t] = 0.f; s_red[128 + t] = 0.f; }

    float acc[4][4][4];
#pragma unroll
    for (int i = 0; i < 4; i++)
#pragma unroll
        for (int j = 0; j < 4; j++)
#pragma unroll
            for (int q = 0; q < 4; q++) acc[i][j][q] = 0.f;

    auto load_chunk = [&](int c, int s) {
        uint32_t sb = stage0 + s * STAGE;
        const __half* Ah; const __half* Al; int k0;
        if (c < K / 32) { Ah = Ahi; Al = Alo; k0 = c * 32; }
        else            { Ah = Shi; Al = Slo; k0 = (c - K / 32) * 32; }
#pragma unroll
        for (int it = 0; it < 2; it++) {
            int i = t + 256 * it;                 // 0..511
            int row = i >> 2, ch = i & 3;
            uint32_t sw = row * 64 + ((ch ^ (row & 3)) << 4);
            int gr = m0 + row; if (gr > NN - 1) gr = NN - 1;
            cpasync16(sb + T_AH + sw, Ah + (size_t)gr * K + k0 + ch * 8);
            cpasync16(sb + T_AL + sw, Al + (size_t)gr * K + k0 + ch * 8);
            cpasync16(sb + T_BH + sw, Bh + (size_t)(n0 + row) * LDB + c * 32 + ch * 8);
        }
        CP_COMMIT();
    };

    load_chunk(0, 0);
    load_chunk(1, 1);
    load_chunk(2, 2);
    load_chunk(3, 3);

#pragma unroll 1
    for (int c = 0; c < CH; c++) {
        int s = c & 3;
        int rem = CH - 1 - c;
        if (rem >= 3)      asm volatile("cp.async.wait_group 3;" ::: "memory");
        else if (rem == 2) asm volatile("cp.async.wait_group 2;" ::: "memory");
        else if (rem == 1) asm volatile("cp.async.wait_group 1;" ::: "memory");
        else               asm volatile("cp.async.wait_group 0;" ::: "memory");
        __syncthreads();

        uint32_t sb = stage0 + s * STAGE;
#pragma unroll
        for (int ks = 0; ks < 2; ks++) {
            uint32_t aH[4][4], aL[4][4], bH[4][2];
#pragma unroll
            for (int mt = 0; mt < 4; mt++) {
                int r = wm * 64 + mt * 16 + (lane & 15);
                int kc = ks * 2 + (lane >> 4);
                uint32_t sw = r * 64 + ((kc ^ (r & 3)) << 4);
                ldsm_x4(aH[mt], sb + T_AH + sw);
                ldsm_x4(aL[mt], sb + T_AL + sw);
            }
#pragma unroll
            for (int nt = 0; nt < 4; nt++) {
                int l15 = lane & 15;
                int n = wn * 32 + nt * 8 + (l15 & 7);
                int kc = ks * 2 + (l15 >> 3);
                ldsm_x2(bH[nt], sb + T_BH + n * 64 + ((kc ^ (n & 3)) << 4));
            }
#pragma unroll
            for (int mt = 0; mt < 4; mt++)
#pragma unroll
                for (int nt = 0; nt < 4; nt++) {
                    mma16816(acc[mt][nt], aH[mt], bH[nt]);
                    mma16816(acc[mt][nt], aL[mt], bH[nt]);
                }
        }
        __syncthreads();
        if (c + 4 < CH) load_chunk(c + 4, s);
    }

    // epilogue: bias + store + per-column BN partial stats
    float csum[4][2], csq[4][2];
#pragma unroll
    for (int nt = 0; nt < 4; nt++) {
        csum[nt][0] = 0.f; csum[nt][1] = 0.f;
        csq[nt][0] = 0.f;  csq[nt][1] = 0.f;
    }
#pragma unroll
    for (int mt = 0; mt < 4; mt++) {
        int r0 = m0 + wm * 64 + mt * 16 + (lane >> 2);
        bool v0ok = r0 < NN, v1ok = (r0 + 8) < NN;
#pragma unroll
        for (int nt = 0; nt < 4; nt++) {
            int lc = wn * 32 + nt * 8 + (lane & 3) * 2;
            float bx = sbias[lc], by = sbias[lc + 1];
            if (v0ok) {
                float vx = acc[mt][nt][0] + bx, vy = acc[mt][nt][1] + by;
                *(float2*)(Out + (size_t)r0 * DH + n0 + lc) = make_float2(vx, vy);
                csum[nt][0] += vx; csq[nt][0] += vx * vx;
                csum[nt][1] += vy; csq[nt][1] += vy * vy;
            }
            if (v1ok) {
                float vx = acc[mt][nt][2] + bx, vy = acc[mt][nt][3] + by;
                *(float2*)(Out + (size_t)(r0 + 8) * DH + n0 + lc) = make_float2(vx, vy);
                csum[nt][0] += vx; csq[nt][0] += vx * vx;
                csum[nt][1] += vy; csq[nt][1] += vy * vy;
            }
        }
    }
    __syncthreads();   // s_red zeroed earlier; mainloop done
#pragma unroll
    for (int nt = 0; nt < 4; nt++) {
        int lc = wn * 32 + nt * 8 + (lane & 3) * 2;
        atomicAdd(&s_red[lc], csum[nt][0]);
        atomicAdd(&s_red[lc + 1], csum[nt][1]);
        atomicAdd(&s_red[128 + lc], csq[nt][0]);
        atomicAdd(&s_red[128 + lc + 1], csq[nt][1]);
    }
    __syncthreads();
    if (t < 128) {
        atomicAdd(&stats[n0 + t], s_red[t]);
        atomicAdd(&stats[256 + n0 + t], s_red[128 + t]);
    }
}

// ---------------- BN finalize ----------------------------------------------
__global__ void k_bnfinal(const float* __restrict__ stats,
                          const float* __restrict__ gam,
                          const float* __restrict__ bet,
                          float* __restrict__ bn) {
    int c = threadIdx.x;
    float mu  = stats[c] * (1.f / NN);
    float var = stats[256 + c] * (1.f / NN) - mu * mu;
    float rstd = rsqrtf(var + 1e-5f);
    float sc = rstd * gam[c];
    bn[c] = sc;
    bn[256 + c] = bet[c] - mu * sc;
}

// BN + ReLU, writes fp16 hi/lo only (serves as gather table + GEMM2 self op)
__global__ void k_bnrelu(const float* __restrict__ H, const float* __restrict__ bn,
                         __half* __restrict__ Hi, __half* __restrict__ Lo) {
    const int total = NN * DH / 4;
    for (int i = blockIdx.x * blockDim.x + threadIdx.x; i < total;
         i += gridDim.x * blockDim.x) {
        float4 v = ((const float4*)H)[i];
        int c = (i & 63) * 4;
        v.x = fmaxf(0.f, v.x * bn[c + 0] + bn[256 + c + 0]);
        v.y = fmaxf(0.f, v.y * bn[c + 1] + bn[256 + c + 1]);
        v.z = fmaxf(0.f, v.z * bn[c + 2] + bn[256 + c + 2]);
        v.w = fmaxf(0.f, v.w * bn[c + 3] + bn[256 + c + 3]);
        __half hx = __float2half_rn(v.x), hy = __float2half_rn(v.y);
        __half hz = __float2half_rn(v.z), hw = __float2half_rn(v.w);
        uint2 h = make_uint2(pkh(__half2float(hx), __half2float(hy)),
                             pkh(__half2float(hz), __half2float(hw)));
        uint2 l = make_uint2(pkh(v.x - __half2float(hx), v.y - __half2float(hy)),
                             pkh(v.z - __half2float(hz), v.w - __half2float(hw)));
        *(uint2*)((char*)Hi + (size_t)i * 8) = h;
        *(uint2*)((char*)Lo + (size_t)i * 8) = l;
    }
}

// ---------------- final FC with fused BN+ReLU ------------------------------
__global__ void __launch_bounds__(256) k_fc(const float* __restrict__ H,
                                            const float* __restrict__ bn,
                                            const float* __restrict__ W,
                                            const float* __restrict__ b,
                                            float* __restrict__ out) {
    __shared__ __align__(16) float Ws[DH * NCLS];
    __shared__ float sbn[512];
    for (int i = threadIdx.x; i < DH * NCLS / 4; i += 256)
        ((float4*)Ws)[i] = ((const float4*)W)[i];
    if (threadIdx.x < 256) {
        sbn[threadIdx.x] = bn[threadIdx.x];
        sbn[256 + threadIdx.x] = bn[256 + threadIdx.x];
    }
    __syncthreads();
    int row = blockIdx.x * 32 + (threadIdx.x >> 3);
    int c = (threadIdx.x & 7) * 4;
    if (row >= NN) return;
    const float4* hr = (const float4*)(H + (size_t)row * DH);
    float4 acc = *(const float4*)(b + c);
#pragma unroll 8
    for (int k4 = 0; k4 < DH / 4; k4++) {
        float4 h = hr[k4];
        int kb = k4 * 4;
        h.x = fmaxf(0.f, h.x * sbn[kb + 0] + sbn[256 + kb + 0]);
        h.y = fmaxf(0.f, h.y * sbn[kb + 1] + sbn[256 + kb + 1]);
        h.z = fmaxf(0.f, h.z * sbn[kb + 2] + sbn[256 + kb + 2]);
        h.w = fmaxf(0.f, h.w * sbn[kb + 3] + sbn[256 + kb + 3]);
        float4 w0 = *(float4*)&Ws[(kb + 0) * NCLS + c];
        float4 w1 = *(float4*)&Ws[(kb + 1) * NCLS + c];
        float4 w2 = *(float4*)&Ws[(kb + 2) * NCLS + c];
        float4 w3 = *(float4*)&Ws[(kb + 3) * NCLS + c];
        acc.x += h.x * w0.x + h.y * w1.x + h.z * w2.x + h.w * w3.x;
        acc.y += h.x * w0.y + h.y * w1.y + h.z * w2.y + h.w * w3.y;
        acc.z += h.x * w0.z + h.y * w1.z + h.z * w2.z + h.w * w3.z;
        acc.w += h.x * w0.w + h.y * w1.w + h.z * w2.w + h.w * w3.w;
    }
    *(float4*)(out + (size_t)row * NCLS + c) = acc;
}

// ---------------- launch ----------------------------------------------------
extern "C" void kernel_launch(void* const* d_in, const int* in_sizes, int n_in,
                              void* d_out, int out_size) {
    const float* x    = (const float*)d_in[0];
    const int*   esrc = (const int*)d_in[1];
    const int*   edst = (const int*)d_in[2];
    const float* W1l  = (const float*)d_in[3];
    const float* b1   = (const float*)d_in[4];
    const float* W1r  = (const float*)d_in[5];
    const float* g1   = (const float*)d_in[6];
    const float* be1  = (const float*)d_in[7];
    const float* W2l  = (const float*)d_in[8];
    const float* b2   = (const float*)d_in[9];
    const float* W2r  = (const float*)d_in[10];
    const float* g2   = (const float*)d_in[11];
    const float* be2  = (const float*)d_in[12];
    const float* Wfc  = (const float*)d_in[13];
    const float* bfc  = (const float*)d_in[14];
    float* out = (float*)d_out;

    __half *p_Ahi, *p_Alo, *p_Shi, *p_Slo, *p_Bh;
    float *p_h1, *p_h2, *p_stats, *p_bn;
    cudaGetSymbolAddress((void**)&p_Ahi,   g_Ahi);
    cudaGetSymbolAddress((void**)&p_Alo,   g_Alo);
    cudaGetSymbolAddress((void**)&p_Shi,   g_Shi);
    cudaGetSymbolAddress((void**)&p_Slo,   g_Slo);
    cudaGetSymbolAddress((void**)&p_Bh,    g_Bhi);
    cudaGetSymbolAddress((void**)&p_h1,    g_h1);
    cudaGetSymbolAddress((void**)&p_h2,    g_h2);
    cudaGetSymbolAddress((void**)&p_stats, g_stats);
    cudaGetSymbolAddress((void**)&p_bn,    g_bn);

    const int SMEM = 2048 + 4 * 24576;   // hdr + 4 stages = 100352
    cudaFuncSetAttribute(k_mmagemm<DIN>,
                         cudaFuncAttributeMaxDynamicSharedMemorySize, SMEM);
    cudaFuncSetAttribute(k_mmagemm<DH>,
                         cudaFuncAttributeMaxDynamicSharedMemorySize, SMEM);

    const int nb1 = (NN + 1023) / 1024;
    const int egrid = (NE + 255) / 256;
    dim3 gg((NN + 127) / 128, 2);        // 782 x 2 CTAs

    k_init<<<(NN + 255) / 256, 256>>>();
    k_hist<<<egrid, 256>>>(edst);
    k_scan1<<<nb1, 1024>>>();
    k_scan2<<<1, 128>>>(nb1);
    k_scan3<<<nb1, 1024>>>();
    k_fill<<<egrid, 256>>>(esrc, edst);

    // layer 1
    k_split<<<2048, 256>>>(x, p_Shi, p_Slo, NN * DIN / 4);
    k_prepB<DIN><<<DIN, 256>>>(W1l, W1r, p_Bh);
    k_spmm1<<<(NN + 7) / 8, 256>>>(p_Shi, p_Ahi, p_Alo);
    k_mmagemm<DIN><<<gg, 256, SMEM>>>(p_Ahi, p_Alo, p_Shi, p_Slo, p_Bh,
                                      b1, p_h1, p_stats);
    k_bnfinal<<<1, 256>>>(p_stats, g1, be1, p_bn);
    k_bnrelu<<<2048, 256>>>(p_h1, p_bn, p_Shi, p_Slo);

    // layer 2
    k_prepB<DH><<<DH, 256>>>(W2l, W2r, p_Bh);
    k_spmm2<<<(NN + 7) / 8, 256>>>(p_Shi, p_Ahi, p_Alo);
    k_mmagemm<DH><<<gg, 256, SMEM>>>(p_Ahi, p_Alo, p_Shi, p_Slo, p_Bh,
                                     b2, p_h2, p_stats + 512);
    k_bnfinal<<<1, 256>>>(p_stats + 512, g2, be2, p_bn + 512);

    // classifier (BN+ReLU fused)
    k_fc<<<(NN + 31) / 32, 256>>>(p_h2, p_bn + 512, Wfc, bfc, out);
}

// round 9
// speedup vs baseline: 1.7705x; 1.0014x over previous
#include <cuda_runtime.h>
#include <cuda_fp16.h>
#include <cstdint>

#define NN   100000
#define NE   1600000
#define DIN  128
#define DH   256
#define NCLS 32

typedef unsigned long long ull;

// ---------------- scratch (device globals) ---------------------------------
__device__ int   g_deg[NN];
__device__ int   g_rowptr[NN + 1];
__device__ int   g_cursor[NN];
__device__ int   g_csr[NE];
__device__ int   g_bsum[128];
__device__ __align__(128) __half g_Ahi[(size_t)NN * DH];
__device__ __align__(128) __half g_Alo[(size_t)NN * DH];
__device__ __align__(128) __half g_Shi[(size_t)NN * DH];
__device__ __align__(128) __half g_Slo[(size_t)NN * DH];
__device__ __align__(128) __half g_Bhi[DH * 2 * DH];     // 256 x 512 max
__device__ __align__(128) float  g_h1[(size_t)NN * DH];
__device__ __align__(128) float  g_h2[(size_t)NN * DH];
__device__ float g_stats[1024];

// ---------------- helpers ---------------------------------------------------
__device__ __forceinline__ uint32_t smem_u32(const void* p) {
    uint32_t a;
    asm("{ .reg .u64 t; cvta.to.shared.u64 t, %1; cvt.u32.u64 %0, t; }"
        : "=r"(a) : "l"(p));
    return a;
}
__device__ __forceinline__ void cpasync16(uint32_t dst, const void* src) {
    asm volatile("cp.async.cg.shared.global [%0], [%1], 16;"
                 :: "r"(dst), "l"(src));
}
#define CP_COMMIT() asm volatile("cp.async.commit_group;" ::: "memory")

__device__ __forceinline__ void ldsm_x4(uint32_t* r, uint32_t addr) {
    asm volatile("ldmatrix.sync.aligned.m8n8.x4.shared.b16 {%0,%1,%2,%3}, [%4];"
                 : "=r"(r[0]), "=r"(r[1]), "=r"(r[2]), "=r"(r[3]) : "r"(addr));
}
__device__ __forceinline__ void ldsm_x2(uint32_t* r, uint32_t addr) {
    asm volatile("ldmatrix.sync.aligned.m8n8.x2.shared.b16 {%0,%1}, [%2];"
                 : "=r"(r[0]), "=r"(r[1]) : "r"(addr));
}
__device__ __forceinline__ void mma16816(float* c, const uint32_t* a,
                                         const uint32_t* b) {
    asm volatile(
        "mma.sync.aligned.m16n8k16.row.col.f32.f16.f16.f32 "
        "{%0,%1,%2,%3}, {%4,%5,%6,%7}, {%8,%9}, {%0,%1,%2,%3};"
        : "+f"(c[0]), "+f"(c[1]), "+f"(c[2]), "+f"(c[3])
        : "r"(a[0]), "r"(a[1]), "r"(a[2]), "r"(a[3]), "r"(b[0]), "r"(b[1]));
}

__device__ __forceinline__ uint32_t pkh(float a, float b) {
    __half2 t = __floats2half2_rn(a, b);
    return *(uint32_t*)&t;
}

// ---------------- scan helper ----------------------------------------------
__device__ __forceinline__ int block_scan_incl(int v) {
    __shared__ int ws[32];
    int lane = threadIdx.x & 31, wid = threadIdx.x >> 5;
#pragma unroll
    for (int o = 1; o < 32; o <<= 1) {
        int n = __shfl_up_sync(0xffffffffu, v, o);
        if (lane >= o) v += n;
    }
    if (lane == 31) ws[wid] = v;
    __syncthreads();
    int nw = blockDim.x >> 5;
    if (wid == 0) {
        int s = (lane < nw) ? ws[lane] : 0;
#pragma unroll
        for (int o = 1; o < 32; o <<= 1) {
            int n = __shfl_up_sync(0xffffffffu, s, o);
            if (lane >= o) s += n;
        }
        ws[lane] = s;
    }
    __syncthreads();
    if (wid > 0) v += ws[wid - 1];
    return v;
}

// ---------------- graph prep ----------------------------------------------
__global__ void k_init() {
    int i = blockIdx.x * blockDim.x + threadIdx.x;
    if (i < NN) { g_deg[i] = 0; g_cursor[i] = 0; }
    if (i < 1024) g_stats[i] = 0.f;
}
__global__ void k_hist(const int* __restrict__ dst) {
    int e = blockIdx.x * blockDim.x + threadIdx.x;
    if (e < NE) atomicAdd(&g_deg[dst[e]], 1);
}
__global__ void k_scan1() {
    int i = blockIdx.x * 1024 + threadIdx.x;
    int v = (i < NN) ? g_deg[i] : 0;
    int incl = block_scan_incl(v);
    if (i < NN) g_rowptr[i + 1] = incl;
    if (threadIdx.x == 1023) g_bsum[blockIdx.x] = incl;
}
// scan2 folded in: every block redundantly scans the 98 block sums
__global__ void k_scan3(int nb) {
    __shared__ int s_off;
    int t = threadIdx.x;
    int v = (t < nb) ? g_bsum[t] : 0;
    int incl = block_scan_incl(v);
    if (blockIdx.x == 0) {
        if (t == 0) s_off = 0;
    } else if (t == (int)blockIdx.x - 1) {
        s_off = incl;
    }
    __syncthreads();
    int i = blockIdx.x * 1024 + t;
    if (i < NN) g_rowptr[i + 1] += s_off;
    if (i == 0) g_rowptr[0] = 0;
}
__global__ void k_fill(const int* __restrict__ src, const int* __restrict__ dst) {
    int e = blockIdx.x * blockDim.x + threadIdx.x;
    if (e < NE) {
        int d = dst[e];
        int p = atomicAdd(&g_cursor[d], 1);
        g_csr[g_rowptr[d] + p] = src[e];
    }
}

// ---------------- x -> hi/lo fp16 split ------------------------------------
__global__ void k_split(const float* __restrict__ X, __half* __restrict__ Hi,
                        __half* __restrict__ Lo, int total4) {
    for (int i = blockIdx.x * blockDim.x + threadIdx.x; i < total4;
         i += gridDim.x * blockDim.x) {
        float4 v = ((const float4*)X)[i];
        __half hx = __float2half_rn(v.x), hy = __float2half_rn(v.y);
        __half hz = __float2half_rn(v.z), hw = __float2half_rn(v.w);
        uint2 h = make_uint2(pkh(__half2float(hx), __half2float(hy)),
                             pkh(__half2float(hz), __half2float(hw)));
        uint2 l = make_uint2(pkh(v.x - __half2float(hx), v.y - __half2float(hy)),
                             pkh(v.z - __half2float(hz), v.w - __half2float(hw)));
        *(uint2*)((char*)Hi + (size_t)i * 8) = h;
        *(uint2*)((char*)Lo + (size_t)i * 8) = l;
    }
}

// ---------------- SpMM layer1: gather fp16 hi table (D=128) ----------------
__global__ void __launch_bounds__(256) k_spmm1(const __half* __restrict__ Xh,
                                               __half* __restrict__ Ahi,
                                               __half* __restrict__ Alo) {
    int warp = threadIdx.x >> 5, lane = threadIdx.x & 31;
    int node = blockIdx.x * 8 + warp;
    if (node >= NN) return;
    int beg = g_rowptr[node], end = g_rowptr[node + 1];
    int deg = end - beg;
    int myidx = (beg + lane < end) ? __ldg(&g_csr[beg + lane]) : 0;
    int dmax = deg < 32 ? deg : 32;

    float4 p = make_float4(0.f, 0.f, 0.f, 0.f);
    float4 q = make_float4(0.f, 0.f, 0.f, 0.f);

    auto addu2 = [&](float4& a, uint2 u) {
        __half2* ph = (__half2*)&u;
        float2 f0 = __half22float2(ph[0]);
        float2 f1 = __half22float2(ph[1]);
        a.x += f0.x; a.y += f0.y; a.z += f1.x; a.w += f1.y;
    };

    int j = 0;
    for (; j + 4 <= dmax; j += 4) {
        int s0 = __shfl_sync(0xffffffffu, myidx, j + 0);
        int s1 = __shfl_sync(0xffffffffu, myidx, j + 1);
        int s2 = __shfl_sync(0xffffffffu, myidx, j + 2);
        int s3 = __shfl_sync(0xffffffffu, myidx, j + 3);
        uint2 u0 = __ldg((const uint2*)(Xh + (size_t)s0 * DIN) + lane);
        uint2 u1 = __ldg((const uint2*)(Xh + (size_t)s1 * DIN) + lane);
        uint2 u2 = __ldg((const uint2*)(Xh + (size_t)s2 * DIN) + lane);
        uint2 u3 = __ldg((const uint2*)(Xh + (size_t)s3 * DIN) + lane);
        addu2(p, u0); addu2(q, u1); addu2(p, u2); addu2(q, u3);
    }
    for (; j < dmax; j++) {
        int s0 = __shfl_sync(0xffffffffu, myidx, j);
        addu2(p, __ldg((const uint2*)(Xh + (size_t)s0 * DIN) + lane));
    }
    for (int jj = beg + 32; jj < end; jj++) {
        int s0 = __ldg(&g_csr[jj]);
        addu2(p, __ldg((const uint2*)(Xh + (size_t)s0 * DIN) + lane));
    }

    float inv = 1.f / fmaxf((float)deg, 1.f);
    float4 a = make_float4((p.x + q.x) * inv, (p.y + q.y) * inv,
                           (p.z + q.z) * inv, (p.w + q.w) * inv);
    __half hx = __float2half_rn(a.x), hy = __float2half_rn(a.y);
    __half hz = __float2half_rn(a.z), hw = __float2half_rn(a.w);
    uint2 h = make_uint2(pkh(__half2float(hx), __half2float(hy)),
                         pkh(__half2float(hz), __half2float(hw)));
    uint2 l = make_uint2(pkh(a.x - __half2float(hx), a.y - __half2float(hy)),
                         pkh(a.z - __half2float(hz), a.w - __half2float(hw)));
    *(uint2*)(Ahi + (size_t)node * DIN + lane * 4) = h;
    *(uint2*)(Alo + (size_t)node * DIN + lane * 4) = l;
}

// ---------------- SpMM layer2: gather fp16 hi table (D=256) ----------------
__global__ void __launch_bounds__(256) k_spmm2(const __half* __restrict__ Xh,
                                               __half* __restrict__ Ahi,
                                               __half* __restrict__ Alo) {
    int warp = threadIdx.x >> 5, lane = threadIdx.x & 31;
    int node = blockIdx.x * 8 + warp;
    if (node >= NN) return;
    int beg = g_rowptr[node], end = g_rowptr[node + 1];
    int deg = end - beg;
    int myidx = (beg + lane < end) ? __ldg(&g_csr[beg + lane]) : 0;
    int dmax = deg < 32 ? deg : 32;

    float p[8] = {0, 0, 0, 0, 0, 0, 0, 0};
    float q[8] = {0, 0, 0, 0, 0, 0, 0, 0};

    auto addu4 = [&](float* a, uint4 u) {
        __half2* ph = (__half2*)&u;
#pragma unroll
        for (int z = 0; z < 4; z++) {
            float2 f = __half22float2(ph[z]);
            a[z * 2] += f.x; a[z * 2 + 1] += f.y;
        }
    };

    int j = 0;
    for (; j + 2 <= dmax; j += 2) {
        int s0 = __shfl_sync(0xffffffffu, myidx, j + 0);
        int s1 = __shfl_sync(0xffffffffu, myidx, j + 1);
        uint4 u0 = __ldg((const uint4*)(Xh + (size_t)s0 * DH) + lane);
        uint4 u1 = __ldg((const uint4*)(Xh + (size_t)s1 * DH) + lane);
        addu4(p, u0); addu4(q, u1);
    }
    for (; j < dmax; j++) {
        int s0 = __shfl_sync(0xffffffffu, myidx, j);
        addu4(p, __ldg((const uint4*)(Xh + (size_t)s0 * DH) + lane));
    }
    for (int jj = beg + 32; jj < end; jj++) {
        int s0 = __ldg(&g_csr[jj]);
        addu4(p, __ldg((const uint4*)(Xh + (size_t)s0 * DH) + lane));
    }

    float inv = 1.f / fmaxf((float)deg, 1.f);
    uint4 h, l;
    uint32_t* hp = (uint32_t*)&h;
    uint32_t* lp = (uint32_t*)&l;
#pragma unroll
    for (int z = 0; z < 4; z++) {
        float v0 = (p[z * 2] + q[z * 2]) * inv;
        float v1 = (p[z * 2 + 1] + q[z * 2 + 1]) * inv;
        __half h0 = __float2half_rn(v0), h1 = __float2half_rn(v1);
        hp[z] = pkh(__half2float(h0), __half2float(h1));
        lp[z] = pkh(v0 - __half2float(h0), v1 - __half2float(h1));
    }
    *(uint4*)(Ahi + (size_t)node * DH + lane * 8) = h;
    *(uint4*)(Alo + (size_t)node * DH + lane * 8) = l;
}

// ---------------- weight prep: Bh [n][2K] fp16 K-major ----------------------
template <int K>
__global__ void k_prepB(const float* __restrict__ Wl, const float* __restrict__ Wr,
                        __half* __restrict__ Bh) {
    int idx = blockIdx.x * 256 + threadIdx.x;
    if (idx >= K * 256) return;
    int k = idx >> 8, n = idx & 255;
    const int LDB = 2 * K;
    Bh[(size_t)n * LDB + k]     = __float2half_rn(Wl[idx]);
    Bh[(size_t)n * LDB + K + k] = __float2half_rn(Wr[idx]);
}

// ---------------- mma.sync GEMM fp16 2-product + fused BN stats -------------
// CTA 128x128, 3 stages, 2 CTAs/SM. acc += aH*bH + aL*bH.
template <int K>
__global__ void __launch_bounds__(256, 2)
k_mmagemm(const __half* __restrict__ Ahi, const __half* __restrict__ Alo,
          const __half* __restrict__ Shi, const __half* __restrict__ Slo,
          const __half* __restrict__ Bh,  const float* __restrict__ bias,
          float* __restrict__ Out, float* __restrict__ stats) {
    constexpr int CH  = 2 * K / 32;
    constexpr int LDB = 2 * K;
    constexpr int T_AH = 0, T_AL = 8192, T_BH = 16384;
    constexpr int STAGE = 24576;

    extern __shared__ __align__(128) char dsm[];
    float* sbias = (float*)dsm;                 // 512B
    float* s_red = (float*)(dsm + 512);         // 1KB: sum[128], sq[128]
    uint32_t stage0 = smem_u32(dsm) + 2048;

    const int t = threadIdx.x;
    const int wid = t >> 5, lane = t & 31;
    const int wm = wid >> 2, wn = wid & 3;       // warps 2 x 4
    const int m0 = blockIdx.x * 128;
    const int n0 = blockIdx.y * 128;

    if (t < 128) { sbias[t] = bias[n0 + t]; s_red[t] = 0.f; s_red[128 + t] = 0.f; }

    float acc[4][4][4];
#pragma unroll
    for (int i = 0; i < 4; i++)
#pragma unroll
        for (int j = 0; j < 4; j++)
#pragma unroll
            for (int q = 0; q < 4; q++) acc[i][j][q] = 0.f;

    auto load_chunk = [&](int c, int s) {
        uint32_t sb = stage0 + s * STAGE;
        const __half* Ah; const __half* Al; int k0;
        if (c < K / 32) { Ah = Ahi; Al = Alo; k0 = c * 32; }
        else            { Ah = Shi; Al = Slo; k0 = (c - K / 32) * 32; }
#pragma unroll
        for (int it = 0; it < 2; it++) {
            int i = t + 256 * it;                 // 0..511
            int row = i >> 2, ch = i & 3;
            uint32_t sw = row * 64 + ((ch ^ (row & 3)) << 4);
            int gr = m0 + row; if (gr > NN - 1) gr = NN - 1;
            cpasync16(sb + T_AH + sw, Ah + (size_t)gr * K + k0 + ch * 8);
            cpasync16(sb + T_AL + sw, Al + (size_t)gr * K + k0 + ch * 8);
            cpasync16(sb + T_BH + sw, Bh + (size_t)(n0 + row) * LDB + c * 32 + ch * 8);
        }
        CP_COMMIT();
    };

    load_chunk(0, 0);
    load_chunk(1, 1);
    load_chunk(2, 2);

#pragma unroll 1
    for (int c = 0; c < CH; c++) {
        int s = c % 3;
        int rem = CH - 1 - c;
        if (rem >= 2)      asm volatile("cp.async.wait_group 2;" ::: "memory");
        else if (rem == 1) asm volatile("cp.async.wait_group 1;" ::: "memory");
        else               asm volatile("cp.async.wait_group 0;" ::: "memory");
        __syncthreads();

        uint32_t sb = stage0 + s * STAGE;
#pragma unroll
        for (int ks = 0; ks < 2; ks++) {
            uint32_t aH[4][4], aL[4][4], bH[4][2];
#pragma unroll
            for (int mt = 0; mt < 4; mt++) {
                int r = wm * 64 + mt * 16 + (lane & 15);
                int kc = ks * 2 + (lane >> 4);
                uint32_t sw = r * 64 + ((kc ^ (r & 3)) << 4);
                ldsm_x4(aH[mt], sb + T_AH + sw);
                ldsm_x4(aL[mt], sb + T_AL + sw);
            }
#pragma unroll
            for (int nt = 0; nt < 4; nt++) {
                int l15 = lane & 15;
                int n = wn * 32 + nt * 8 + (l15 & 7);
                int kc = ks * 2 + (l15 >> 3);
                ldsm_x2(bH[nt], sb + T_BH + n * 64 + ((kc ^ (n & 3)) << 4));
            }
#pragma unroll
            for (int mt = 0; mt < 4; mt++)
#pragma unroll
                for (int nt = 0; nt < 4; nt++) {
                    mma16816(acc[mt][nt], aH[mt], bH[nt]);
                    mma16816(acc[mt][nt], aL[mt], bH[nt]);
                }
        }
        __syncthreads();
        if (c + 3 < CH) load_chunk(c + 3, s);
    }

    // epilogue: bias + store + per-column BN partial stats
    float csum[4][2], csq[4][2];
#pragma unroll
    for (int nt = 0; nt < 4; nt++) {
        csum[nt][0] = 0.f; csum[nt][1] = 0.f;
        csq[nt][0] = 0.f;  csq[nt][1] = 0.f;
    }
#pragma unroll
    for (int mt = 0; mt < 4; mt++) {
        int r0 = m0 + wm * 64 + mt * 16 + (lane >> 2);
        bool v0ok = r0 < NN, v1ok = (r0 + 8) < NN;
#pragma unroll
        for (int nt = 0; nt < 4; nt++) {
            int lc = wn * 32 + nt * 8 + (lane & 3) * 2;
            float bx = sbias[lc], by = sbias[lc + 1];
            if (v0ok) {
                float vx = acc[mt][nt][0] + bx, vy = acc[mt][nt][1] + by;
                *(float2*)(Out + (size_t)r0 * DH + n0 + lc) = make_float2(vx, vy);
                csum[nt][0] += vx; csq[nt][0] += vx * vx;
                csum[nt][1] += vy; csq[nt][1] += vy * vy;
            }
            if (v1ok) {
                float vx = acc[mt][nt][2] + bx, vy = acc[mt][nt][3] + by;
                *(float2*)(Out + (size_t)(r0 + 8) * DH + n0 + lc) = make_float2(vx, vy);
                csum[nt][0] += vx; csq[nt][0] += vx * vx;
                csum[nt][1] += vy; csq[nt][1] += vy * vy;
            }
        }
    }
    __syncthreads();
#pragma unroll
    for (int nt = 0; nt < 4; nt++) {
        int lc = wn * 32 + nt * 8 + (lane & 3) * 2;
        atomicAdd(&s_red[lc], csum[nt][0]);
        atomicAdd(&s_red[lc + 1], csum[nt][1]);
        atomicAdd(&s_red[128 + lc], csq[nt][0]);
        atomicAdd(&s_red[128 + lc + 1], csq[nt][1]);
    }
    __syncthreads();
    if (t < 128) {
        atomicAdd(&stats[n0 + t], s_red[t]);
        atomicAdd(&stats[256 + n0 + t], s_red[128 + t]);
    }
}

// ---------------- BN(from stats) + ReLU -> fp16 hi/lo table -----------------
__global__ void k_bnrelu(const float* __restrict__ H, const float* __restrict__ stats,
                         const float* __restrict__ gam, const float* __restrict__ bet,
                         __half* __restrict__ Hi, __half* __restrict__ Lo) {
    __shared__ float sbn[512];
    {
        int c = threadIdx.x;
        float mu  = stats[c] * (1.f / NN);
        float var = stats[256 + c] * (1.f / NN) - mu * mu;
        float rstd = rsqrtf(var + 1e-5f);
        float sc = rstd * gam[c];
        sbn[c] = sc;
        sbn[256 + c] = bet[c] - mu * sc;
    }
    __syncthreads();
    const int total = NN * DH / 4;
    for (int i = blockIdx.x * blockDim.x + threadIdx.x; i < total;
         i += gridDim.x * blockDim.x) {
        float4 v = ((const float4*)H)[i];
        int c = (i & 63) * 4;
        v.x = fmaxf(0.f, v.x * sbn[c + 0] + sbn[256 + c + 0]);
        v.y = fmaxf(0.f, v.y * sbn[c + 1] + sbn[256 + c + 1]);
        v.z = fmaxf(0.f, v.z * sbn[c + 2] + sbn[256 + c + 2]);
        v.w = fmaxf(0.f, v.w * sbn[c + 3] + sbn[256 + c + 3]);
        __half hx = __float2half_rn(v.x), hy = __float2half_rn(v.y);
        __half hz = __float2half_rn(v.z), hw = __float2half_rn(v.w);
        uint2 h = make_uint2(pkh(__half2float(hx), __half2float(hy)),
                             pkh(__half2float(hz), __half2float(hw)));
        uint2 l = make_uint2(pkh(v.x - __half2float(hx), v.y - __half2float(hy)),
                             pkh(v.z - __half2float(hz), v.w - __half2float(hw)));
        *(uint2*)((char*)Hi + (size_t)i * 8) = h;
        *(uint2*)((char*)Lo + (size_t)i * 8) = l;
    }
}

// ---------------- final FC with fused BN(from stats)+ReLU -------------------
__global__ void __launch_bounds__(256) k_fc(const float* __restrict__ H,
                                            const float* __restrict__ stats,
                                            const float* __restrict__ gam,
                                            const float* __restrict__ bet,
                                            const float* __restrict__ W,
                                            const float* __restrict__ b,
                                            float* __restrict__ out) {
    __shared__ __align__(16) float Ws[DH * NCLS];
    __shared__ float sbn[512];
    for (int i = threadIdx.x; i < DH * NCLS / 4; i += 256)
        ((float4*)Ws)[i] = ((const float4*)W)[i];
    {
        int c = threadIdx.x;
        float mu  = stats[c] * (1.f / NN);
        float var = stats[256 + c] * (1.f / NN) - mu * mu;
        float rstd = rsqrtf(var + 1e-5f);
        float sc = rstd * gam[c];
        sbn[c] = sc;
        sbn[256 + c] = bet[c] - mu * sc;
    }
    __syncthreads();
    int row = blockIdx.x * 32 + (threadIdx.x >> 3);
    int c = (threadIdx.x & 7) * 4;
    if (row >= NN) return;
    const float4* hr = (const float4*)(H + (size_t)row * DH);
    float4 acc = *(const float4*)(b + c);
#pragma unroll 8
    for (int k4 = 0; k4 < DH / 4; k4++) {
        float4 h = hr[k4];
        int kb = k4 * 4;
        h.x = fmaxf(0.f, h.x * sbn[kb + 0] + sbn[256 + kb + 0]);
        h.y = fmaxf(0.f, h.y * sbn[kb + 1] + sbn[256 + kb + 1]);
        h.z = fmaxf(0.f, h.z * sbn[kb + 2] + sbn[256 + kb + 2]);
        h.w = fmaxf(0.f, h.w * sbn[kb + 3] + sbn[256 + kb + 3]);
        float4 w0 = *(float4*)&Ws[(kb + 0) * NCLS + c];
        float4 w1 = *(float4*)&Ws[(kb + 1) * NCLS + c];
        float4 w2 = *(float4*)&Ws[(kb + 2) * NCLS + c];
        float4 w3 = *(float4*)&Ws[(kb + 3) * NCLS + c];
        acc.x += h.x * w0.x + h.y * w1.x + h.z * w2.x + h.w * w3.x;
        acc.y += h.x * w0.y + h.y * w1.y + h.z * w2.y + h.w * w3.y;
        acc.z += h.x * w0.z + h.y * w1.z + h.z * w2.z + h.w * w3.z;
        acc.w += h.x * w0.w + h.y * w1.w + h.z * w2.w + h.w * w3.w;
    }
    *(float4*)(out + (size_t)row * NCLS + c) = acc;
}

// ---------------- launch ----------------------------------------------------
extern "C" void kernel_launch(void* const* d_in, const int* in_sizes, int n_in,
                              void* d_out, int out_size) {
    const float* x    = (const float*)d_in[0];
    const int*   esrc = (const int*)d_in[1];
    const int*   edst = (const int*)d_in[2];
    const float* W1l  = (const float*)d_in[3];
    const float* b1   = (const float*)d_in[4];
    const float* W1r  = (const float*)d_in[5];
    const float* g1   = (const float*)d_in[6];
    const float* be1  = (const float*)d_in[7];
    const float* W2l  = (const float*)d_in[8];
    const float* b2   = (const float*)d_in[9];
    const float* W2r  = (const float*)d_in[10];
    const float* g2   = (const float*)d_in[11];
    const float* be2  = (const float*)d_in[12];
    const float* Wfc  = (const float*)d_in[13];
    const float* bfc  = (const float*)d_in[14];
    float* out = (float*)d_out;

    __half *p_Ahi, *p_Alo, *p_Shi, *p_Slo, *p_Bh;
    float *p_h1, *p_h2, *p_stats;
    cudaGetSymbolAddress((void**)&p_Ahi,   g_Ahi);
    cudaGetSymbolAddress((void**)&p_Alo,   g_Alo);
    cudaGetSymbolAddress((void**)&p_Shi,   g_Shi);
    cudaGetSymbolAddress((void**)&p_Slo,   g_Slo);
    cudaGetSymbolAddress((void**)&p_Bh,    g_Bhi);
    cudaGetSymbolAddress((void**)&p_h1,    g_h1);
    cudaGetSymbolAddress((void**)&p_h2,    g_h2);
    cudaGetSymbolAddress((void**)&p_stats, g_stats);

    const int SMEM = 2048 + 3 * 24576;   // 75776 -> 2 CTAs/SM
    cudaFuncSetAttribute(k_mmagemm<DIN>,
                         cudaFuncAttributeMaxDynamicSharedMemorySize, SMEM);
    cudaFuncSetAttribute(k_mmagemm<DH>,
                         cudaFuncAttributeMaxDynamicSharedMemorySize, SMEM);

    const int nb1 = (NN + 1023) / 1024;
    const int egrid = (NE + 255) / 256;
    dim3 gg((NN + 127) / 128, 2);        // 782 x 2 CTAs

    k_init<<<(NN + 255) / 256, 256>>>();
    k_hist<<<egrid, 256>>>(edst);
    k_scan1<<<nb1, 1024>>>();
    k_scan3<<<nb1, 1024>>>(nb1);
    k_fill<<<egrid, 256>>>(esrc, edst);

    // layer 1
    k_split<<<2048, 256>>>(x, p_Shi, p_Slo, NN * DIN / 4);
    k_prepB<DIN><<<DIN, 256>>>(W1l, W1r, p_Bh);
    k_spmm1<<<(NN + 7) / 8, 256>>>(p_Shi, p_Ahi, p_Alo);
    k_mmagemm<DIN><<<gg, 256, SMEM>>>(p_Ahi, p_Alo, p_Shi, p_Slo, p_Bh,
                                      b1, p_h1, p_stats);
    k_bnrelu<<<2048, 256>>>(p_h1, p_stats, g1, be1, p_Shi, p_Slo);

    // layer 2
    k_prepB<DH><<<DH, 256>>>(W2l, W2r, p_Bh);
    k_spmm2<<<(NN + 7) / 8, 256>>>(p_Shi, p_Ahi, p_Alo);
    k_mmagemm<DH><<<gg, 256, SMEM>>>(p_Ahi, p_Alo, p_Shi, p_Slo, p_Bh,
                                     b2, p_h2, p_stats + 512);

    // classifier (BN+ReLU fused, stats->bn computed in-kernel)
    k_fc<<<(NN + 31) / 32, 256>>>(p_h2, p_stats + 512, g2, be2, Wfc, bfc, out);
}

// round 10
// speedup vs baseline: 2.0487x; 1.1571x over previous
#include <cuda_runtime.h>
#include <cuda_fp16.h>
#include <cstdint>

#define NN   100000
#define NE   1600000
#define DIN  128
#define DH   256
#define NCLS 32

typedef unsigned long long ull;

// ---------------- scratch (device globals) ---------------------------------
__device__ int   g_deg[NN];
__device__ int   g_rowptr[NN + 1];
__device__ int   g_cursor[NN];
__device__ int   g_csr[NE];
__device__ int   g_bsum[128];
__device__ __align__(128) __half g_Ahi[(size_t)NN * DH];
__device__ __align__(128) __half g_Shi[(size_t)NN * DH];
__device__ __align__(128) __half g_Bhi[DH * 2 * DH];     // 256 x 512 max
__device__ __align__(128) float  g_h1[(size_t)NN * DH];
__device__ __align__(128) float  g_h2[(size_t)NN * DH];
__device__ float g_stats[1024];

// ---------------- helpers ---------------------------------------------------
__device__ __forceinline__ uint32_t smem_u32(const void* p) {
    uint32_t a;
    asm("{ .reg .u64 t; cvta.to.shared.u64 t, %1; cvt.u32.u64 %0, t; }"
        : "=r"(a) : "l"(p));
    return a;
}
__device__ __forceinline__ void cpasync16(uint32_t dst, const void* src) {
    asm volatile("cp.async.cg.shared.global [%0], [%1], 16;"
                 :: "r"(dst), "l"(src));
}
#define CP_COMMIT() asm volatile("cp.async.commit_group;" ::: "memory")

__device__ __forceinline__ void ldsm_x4(uint32_t* r, uint32_t addr) {
    asm volatile("ldmatrix.sync.aligned.m8n8.x4.shared.b16 {%0,%1,%2,%3}, [%4];"
                 : "=r"(r[0]), "=r"(r[1]), "=r"(r[2]), "=r"(r[3]) : "r"(addr));
}
__device__ __forceinline__ void ldsm_x2(uint32_t* r, uint32_t addr) {
    asm volatile("ldmatrix.sync.aligned.m8n8.x2.shared.b16 {%0,%1}, [%2];"
                 : "=r"(r[0]), "=r"(r[1]) : "r"(addr));
}
__device__ __forceinline__ void mma16816(float* c, const uint32_t* a,
                                         const uint32_t* b) {
    asm volatile(
        "mma.sync.aligned.m16n8k16.row.col.f32.f16.f16.f32 "
        "{%0,%1,%2,%3}, {%4,%5,%6,%7}, {%8,%9}, {%0,%1,%2,%3};"
        : "+f"(c[0]), "+f"(c[1]), "+f"(c[2]), "+f"(c[3])
        : "r"(a[0]), "r"(a[1]), "r"(a[2]), "r"(a[3]), "r"(b[0]), "r"(b[1]));
}

__device__ __forceinline__ uint32_t pkh(float a, float b) {
    __half2 t = __floats2half2_rn(a, b);
    return *(uint32_t*)&t;
}

// ---------------- scan helper ----------------------------------------------
__device__ __forceinline__ int block_scan_incl(int v) {
    __shared__ int ws[32];
    int lane = threadIdx.x & 31, wid = threadIdx.x >> 5;
#pragma unroll
    for (int o = 1; o < 32; o <<= 1) {
        int n = __shfl_up_sync(0xffffffffu, v, o);
        if (lane >= o) v += n;
    }
    if (lane == 31) ws[wid] = v;
    __syncthreads();
    int nw = blockDim.x >> 5;
    if (wid == 0) {
        int s = (lane < nw) ? ws[lane] : 0;
#pragma unroll
        for (int o = 1; o < 32; o <<= 1) {
            int n = __shfl_up_sync(0xffffffffu, s, o);
            if (lane >= o) s += n;
        }
        ws[lane] = s;
    }
    __syncthreads();
    if (wid > 0) v += ws[wid - 1];
    return v;
}

// ---------------- graph prep ----------------------------------------------
__global__ void k_init() {
    int i = blockIdx.x * blockDim.x + threadIdx.x;
    if (i < NN) { g_deg[i] = 0; g_cursor[i] = 0; }
    if (i < 1024) g_stats[i] = 0.f;
}
__global__ void k_hist(const int* __restrict__ dst) {
    int e = blockIdx.x * blockDim.x + threadIdx.x;
    if (e < NE) atomicAdd(&g_deg[dst[e]], 1);
}
__global__ void k_scan1() {
    int i = blockIdx.x * 1024 + threadIdx.x;
    int v = (i < NN) ? g_deg[i] : 0;
    int incl = block_scan_incl(v);
    if (i < NN) g_rowptr[i + 1] = incl;
    if (threadIdx.x == 1023) g_bsum[blockIdx.x] = incl;
}
// scan2 folded in: every block redundantly scans the 98 block sums
__global__ void k_scan3(int nb) {
    __shared__ int s_off;
    int t = threadIdx.x;
    int v = (t < nb) ? g_bsum[t] : 0;
    int incl = block_scan_incl(v);
    if (blockIdx.x == 0) {
        if (t == 0) s_off = 0;
    } else if (t == (int)blockIdx.x - 1) {
        s_off = incl;
    }
    __syncthreads();
    int i = blockIdx.x * 1024 + t;
    if (i < NN) g_rowptr[i + 1] += s_off;
    if (i == 0) g_rowptr[0] = 0;
}
__global__ void k_fill(const int* __restrict__ src, const int* __restrict__ dst) {
    int e = blockIdx.x * blockDim.x + threadIdx.x;
    if (e < NE) {
        int d = dst[e];
        int p = atomicAdd(&g_cursor[d], 1);
        g_csr[g_rowptr[d] + p] = src[e];
    }
}

// ---------------- x -> fp16 convert ----------------------------------------
__global__ void k_split(const float* __restrict__ X, __half* __restrict__ Hi,
                        int total4) {
    for (int i = blockIdx.x * blockDim.x + threadIdx.x; i < total4;
         i += gridDim.x * blockDim.x) {
        float4 v = ((const float4*)X)[i];
        uint2 h = make_uint2(pkh(v.x, v.y), pkh(v.z, v.w));
        *(uint2*)((char*)Hi + (size_t)i * 8) = h;
    }
}

// ---------------- SpMM layer1: gather fp16 table (D=128) -------------------
__global__ void __launch_bounds__(256) k_spmm1(const __half* __restrict__ Xh,
                                               __half* __restrict__ Ahi) {
    int warp = threadIdx.x >> 5, lane = threadIdx.x & 31;
    int node = blockIdx.x * 8 + warp;
    if (node >= NN) return;
    int beg = g_rowptr[node], end = g_rowptr[node + 1];
    int deg = end - beg;
    int myidx = (beg + lane < end) ? __ldg(&g_csr[beg + lane]) : 0;
    int dmax = deg < 32 ? deg : 32;

    float4 p = make_float4(0.f, 0.f, 0.f, 0.f);
    float4 q = make_float4(0.f, 0.f, 0.f, 0.f);

    auto addu2 = [&](float4& a, uint2 u) {
        __half2* ph = (__half2*)&u;
        float2 f0 = __half22float2(ph[0]);
        float2 f1 = __half22float2(ph[1]);
        a.x += f0.x; a.y += f0.y; a.z += f1.x; a.w += f1.y;
    };

    int j = 0;
    for (; j + 4 <= dmax; j += 4) {
        int s0 = __shfl_sync(0xffffffffu, myidx, j + 0);
        int s1 = __shfl_sync(0xffffffffu, myidx, j + 1);
        int s2 = __shfl_sync(0xffffffffu, myidx, j + 2);
        int s3 = __shfl_sync(0xffffffffu, myidx, j + 3);
        uint2 u0 = __ldg((const uint2*)(Xh + (size_t)s0 * DIN) + lane);
        uint2 u1 = __ldg((const uint2*)(Xh + (size_t)s1 * DIN) + lane);
        uint2 u2 = __ldg((const uint2*)(Xh + (size_t)s2 * DIN) + lane);
        uint2 u3 = __ldg((const uint2*)(Xh + (size_t)s3 * DIN) + lane);
        addu2(p, u0); addu2(q, u1); addu2(p, u2); addu2(q, u3);
    }
    for (; j < dmax; j++) {
        int s0 = __shfl_sync(0xffffffffu, myidx, j);
        addu2(p, __ldg((const uint2*)(Xh + (size_t)s0 * DIN) + lane));
    }
    for (int jj = beg + 32; jj < end; jj++) {
        int s0 = __ldg(&g_csr[jj]);
        addu2(p, __ldg((const uint2*)(Xh + (size_t)s0 * DIN) + lane));
    }

    float inv = 1.f / fmaxf((float)deg, 1.f);
    float4 a = make_float4((p.x + q.x) * inv, (p.y + q.y) * inv,
                           (p.z + q.z) * inv, (p.w + q.w) * inv);
    uint2 h = make_uint2(pkh(a.x, a.y), pkh(a.z, a.w));
    *(uint2*)(Ahi + (size_t)node * DIN + lane * 4) = h;
}

// ---------------- SpMM layer2: gather fp16 table (D=256) -------------------
__global__ void __launch_bounds__(256) k_spmm2(const __half* __restrict__ Xh,
                                               __half* __restrict__ Ahi) {
    int warp = threadIdx.x >> 5, lane = threadIdx.x & 31;
    int node = blockIdx.x * 8 + warp;
    if (node >= NN) return;
    int beg = g_rowptr[node], end = g_rowptr[node + 1];
    int deg = end - beg;
    int myidx = (beg + lane < end) ? __ldg(&g_csr[beg + lane]) : 0;
    int dmax = deg < 32 ? deg : 32;

    float p[8] = {0, 0, 0, 0, 0, 0, 0, 0};
    float q[8] = {0, 0, 0, 0, 0, 0, 0, 0};

    auto addu4 = [&](float* a, uint4 u) {
        __half2* ph = (__half2*)&u;
#pragma unroll
        for (int z = 0; z < 4; z++) {
            float2 f = __half22float2(ph[z]);
            a[z * 2] += f.x; a[z * 2 + 1] += f.y;
        }
    };

    int j = 0;
    for (; j + 2 <= dmax; j += 2) {
        int s0 = __shfl_sync(0xffffffffu, myidx, j + 0);
        int s1 = __shfl_sync(0xffffffffu, myidx, j + 1);
        uint4 u0 = __ldg((const uint4*)(Xh + (size_t)s0 * DH) + lane);
        uint4 u1 = __ldg((const uint4*)(Xh + (size_t)s1 * DH) + lane);
        addu4(p, u0); addu4(q, u1);
    }
    for (; j < dmax; j++) {
        int s0 = __shfl_sync(0xffffffffu, myidx, j);
        addu4(p, __ldg((const uint4*)(Xh + (size_t)s0 * DH) + lane));
    }
    for (int jj = beg + 32; jj < end; jj++) {
        int s0 = __ldg(&g_csr[jj]);
        addu4(p, __ldg((const uint4*)(Xh + (size_t)s0 * DH) + lane));
    }

    float inv = 1.f / fmaxf((float)deg, 1.f);
    uint4 h;
    uint32_t* hp = (uint32_t*)&h;
#pragma unroll
    for (int z = 0; z < 4; z++) {
        float v0 = (p[z * 2] + q[z * 2]) * inv;
        float v1 = (p[z * 2 + 1] + q[z * 2 + 1]) * inv;
        hp[z] = pkh(v0, v1);
    }
    *(uint4*)(Ahi + (size_t)node * DH + lane * 8) = h;
}

// ---------------- weight prep: Bh [n][2K] fp16 K-major ----------------------
template <int K>
__global__ void k_prepB(const float* __restrict__ Wl, const float* __restrict__ Wr,
                        __half* __restrict__ Bh) {
    int idx = blockIdx.x * 256 + threadIdx.x;
    if (idx >= K * 256) return;
    int k = idx >> 8, n = idx & 255;
    const int LDB = 2 * K;
    Bh[(size_t)n * LDB + k]     = __float2half_rn(Wl[idx]);
    Bh[(size_t)n * LDB + K + k] = __float2half_rn(Wr[idx]);
}

// ---------------- mma.sync GEMM fp16 single-product + fused BN stats --------
// CTA 128x128, 4 stages (16KB each), 2 CTAs/SM. acc += aH*bH.
template <int K>
__global__ void __launch_bounds__(256, 2)
k_mmagemm(const __half* __restrict__ Ahi, const __half* __restrict__ Shi,
          const __half* __restrict__ Bh,  const float* __restrict__ bias,
          float* __restrict__ Out, float* __restrict__ stats) {
    constexpr int CH  = 2 * K / 32;
    constexpr int LDB = 2 * K;
    constexpr int T_BH = 8192;
    constexpr int STAGE = 16384;

    extern __shared__ __align__(128) char dsm[];
    float* sbias = (float*)dsm;                 // 512B
    float* s_red = (float*)(dsm + 512);         // 1KB: sum[128], sq[128]
    uint32_t stage0 = smem_u32(dsm) + 2048;

    const int t = threadIdx.x;
    const int wid = t >> 5, lane = t & 31;
    const int wm = wid >> 2, wn = wid & 3;       // warps 2 x 4
    const int m0 = blockIdx.x * 128;
    const int n0 = blockIdx.y * 128;

    if (t < 128) { sbias[t] = bias[n0 + t]; s_red[t] = 0.f; s_red[128 + t] = 0.f; }

    float acc[4][4][4];
#pragma unroll
    for (int i = 0; i < 4; i++)
#pragma unroll
        for (int j = 0; j < 4; j++)
#pragma unroll
            for (int q = 0; q < 4; q++) acc[i][j][q] = 0.f;

    auto load_chunk = [&](int c, int s) {
        uint32_t sb = stage0 + s * STAGE;
        const __half* Ah; int k0;
        if (c < K / 32) { Ah = Ahi; k0 = c * 32; }
        else            { Ah = Shi; k0 = (c - K / 32) * 32; }
#pragma unroll
        for (int it = 0; it < 2; it++) {
            int i = t + 256 * it;                 // 0..511
            int row = i >> 2, ch = i & 3;
            uint32_t sw = row * 64 + ((ch ^ (row & 3)) << 4);
            int gr = m0 + row; if (gr > NN - 1) gr = NN - 1;
            cpasync16(sb + sw, Ah + (size_t)gr * K + k0 + ch * 8);
            cpasync16(sb + T_BH + sw, Bh + (size_t)(n0 + row) * LDB + c * 32 + ch * 8);
        }
        CP_COMMIT();
    };

    load_chunk(0, 0);
    load_chunk(1, 1);
    load_chunk(2, 2);
    load_chunk(3, 3);

#pragma unroll 1
    for (int c = 0; c < CH; c++) {
        int s = c & 3;
        int rem = CH - 1 - c;
        if (rem >= 3)      asm volatile("cp.async.wait_group 3;" ::: "memory");
        else if (rem == 2) asm volatile("cp.async.wait_group 2;" ::: "memory");
        else if (rem == 1) asm volatile("cp.async.wait_group 1;" ::: "memory");
        else               asm volatile("cp.async.wait_group 0;" ::: "memory");
        __syncthreads();

        uint32_t sb = stage0 + s * STAGE;
#pragma unroll
        for (int ks = 0; ks < 2; ks++) {
            uint32_t aH[4][4], bH[4][2];
#pragma unroll
            for (int mt = 0; mt < 4; mt++) {
                int r = wm * 64 + mt * 16 + (lane & 15);
                int kc = ks * 2 + (lane >> 4);
                ldsm_x4(aH[mt], sb + r * 64 + ((kc ^ (r & 3)) << 4));
            }
#pragma unroll
            for (int nt = 0; nt < 4; nt++) {
                int l15 = lane & 15;
                int n = wn * 32 + nt * 8 + (l15 & 7);
                int kc = ks * 2 + (l15 >> 3);
                ldsm_x2(bH[nt], sb + T_BH + n * 64 + ((kc ^ (n & 3)) << 4));
            }
#pragma unroll
            for (int mt = 0; mt < 4; mt++)
#pragma unroll
                for (int nt = 0; nt < 4; nt++)
                    mma16816(acc[mt][nt], aH[mt], bH[nt]);
        }
        __syncthreads();
        if (c + 4 < CH) load_chunk(c + 4, s);
    }

    // epilogue: bias + store + per-column BN partial stats
    float csum[4][2], csq[4][2];
#pragma unroll
    for (int nt = 0; nt < 4; nt++) {
        csum[nt][0] = 0.f; csum[nt][1] = 0.f;
        csq[nt][0] = 0.f;  csq[nt][1] = 0.f;
    }
#pragma unroll
    for (int mt = 0; mt < 4; mt++) {
        int r0 = m0 + wm * 64 + mt * 16 + (lane >> 2);
        bool v0ok = r0 < NN, v1ok = (r0 + 8) < NN;
#pragma unroll
        for (int nt = 0; nt < 4; nt++) {
            int lc = wn * 32 + nt * 8 + (lane & 3) * 2;
            float bx = sbias[lc], by = sbias[lc + 1];
            if (v0ok) {
                float vx = acc[mt][nt][0] + bx, vy = acc[mt][nt][1] + by;
                *(float2*)(Out + (size_t)r0 * DH + n0 + lc) = make_float2(vx, vy);
                csum[nt][0] += vx; csq[nt][0] += vx * vx;
                csum[nt][1] += vy; csq[nt][1] += vy * vy;
            }
            if (v1ok) {
                float vx = acc[mt][nt][2] + bx, vy = acc[mt][nt][3] + by;
                *(float2*)(Out + (size_t)(r0 + 8) * DH + n0 + lc) = make_float2(vx, vy);
                csum[nt][0] += vx; csq[nt][0] += vx * vx;
                csum[nt][1] += vy; csq[nt][1] += vy * vy;
            }
        }
    }
    __syncthreads();
#pragma unroll
    for (int nt = 0; nt < 4; nt++) {
        int lc = wn * 32 + nt * 8 + (lane & 3) * 2;
        atomicAdd(&s_red[lc], csum[nt][0]);
        atomicAdd(&s_red[lc + 1], csum[nt][1]);
        atomicAdd(&s_red[128 + lc], csq[nt][0]);
        atomicAdd(&s_red[128 + lc + 1], csq[nt][1]);
    }
    __syncthreads();
    if (t < 128) {
        atomicAdd(&stats[n0 + t], s_red[t]);
        atomicAdd(&stats[256 + n0 + t], s_red[128 + t]);
    }
}

// ---------------- BN(from stats) + ReLU -> fp16 table -----------------------
__global__ void k_bnrelu(const float* __restrict__ H, const float* __restrict__ stats,
                         const float* __restrict__ gam, const float* __restrict__ bet,
                         __half* __restrict__ Hi) {
    __shared__ float sbn[512];
    {
        int c = threadIdx.x;
        float mu  = stats[c] * (1.f / NN);
        float var = stats[256 + c] * (1.f / NN) - mu * mu;
        float rstd = rsqrtf(var + 1e-5f);
        float sc = rstd * gam[c];
        sbn[c] = sc;
        sbn[256 + c] = bet[c] - mu * sc;
    }
    __syncthreads();
    const int total = NN * DH / 4;
    for (int i = blockIdx.x * blockDim.x + threadIdx.x; i < total;
         i += gridDim.x * blockDim.x) {
        float4 v = ((const float4*)H)[i];
        int c = (i & 63) * 4;
        v.x = fmaxf(0.f, v.x * sbn[c + 0] + sbn[256 + c + 0]);
        v.y = fmaxf(0.f, v.y * sbn[c + 1] + sbn[256 + c + 1]);
        v.z = fmaxf(0.f, v.z * sbn[c + 2] + sbn[256 + c + 2]);
        v.w = fmaxf(0.f, v.w * sbn[c + 3] + sbn[256 + c + 3]);
        uint2 h = make_uint2(pkh(v.x, v.y), pkh(v.z, v.w));
        *(uint2*)((char*)Hi + (size_t)i * 8) = h;
    }
}

// ---------------- final FC with fused BN(from stats)+ReLU -------------------
__global__ void __launch_bounds__(256) k_fc(const float* __restrict__ H,
                                            const float* __restrict__ stats,
                                            const float* __restrict__ gam,
                                            const float* __restrict__ bet,
                                            const float* __restrict__ W,
                                            const float* __restrict__ b,
                                            float* __restrict__ out) {
    __shared__ __align__(16) float Ws[DH * NCLS];
    __shared__ float sbn[512];
    for (int i = threadIdx.x; i < DH * NCLS / 4; i += 256)
        ((float4*)Ws)[i] = ((const float4*)W)[i];
    {
        int c = threadIdx.x;
        float mu  = stats[c] * (1.f / NN);
        float var = stats[256 + c] * (1.f / NN) - mu * mu;
        float rstd = rsqrtf(var + 1e-5f);
        float sc = rstd * gam[c];
        sbn[c] = sc;
        sbn[256 + c] = bet[c] - mu * sc;
    }
    __syncthreads();
    int row = blockIdx.x * 32 + (threadIdx.x >> 3);
    int c = (threadIdx.x & 7) * 4;
    if (row >= NN) return;
    const float4* hr = (const float4*)(H + (size_t)row * DH);
    float4 acc = *(const float4*)(b + c);
#pragma unroll 8
    for (int k4 = 0; k4 < DH / 4; k4++) {
        float4 h = hr[k4];
        int kb = k4 * 4;
        h.x = fmaxf(0.f, h.x * sbn[kb + 0] + sbn[256 + kb + 0]);
        h.y = fmaxf(0.f, h.y * sbn[kb + 1] + sbn[256 + kb + 1]);
        h.z = fmaxf(0.f, h.z * sbn[kb + 2] + sbn[256 + kb + 2]);
        h.w = fmaxf(0.f, h.w * sbn[kb + 3] + sbn[256 + kb + 3]);
        float4 w0 = *(float4*)&Ws[(kb + 0) * NCLS + c];
        float4 w1 = *(float4*)&Ws[(kb + 1) * NCLS + c];
        float4 w2 = *(float4*)&Ws[(kb + 2) * NCLS + c];
        float4 w3 = *(float4*)&Ws[(kb + 3) * NCLS + c];
        acc.x += h.x * w0.x + h.y * w1.x + h.z * w2.x + h.w * w3.x;
        acc.y += h.x * w0.y + h.y * w1.y + h.z * w2.y + h.w * w3.y;
        acc.z += h.x * w0.z + h.y * w1.z + h.z * w2.z + h.w * w3.z;
        acc.w += h.x * w0.w + h.y * w1.w + h.z * w2.w + h.w * w3.w;
    }
    *(float4*)(out + (size_t)row * NCLS + c) = acc;
}

// ---------------- launch ----------------------------------------------------
extern "C" void kernel_launch(void* const* d_in, const int* in_sizes, int n_in,
                              void* d_out, int out_size) {
    const float* x    = (const float*)d_in[0];
    const int*   esrc = (const int*)d_in[1];
    const int*   edst = (const int*)d_in[2];
    const float* W1l  = (const float*)d_in[3];
    const float* b1   = (const float*)d_in[4];
    const float* W1r  = (const float*)d_in[5];
    const float* g1   = (const float*)d_in[6];
    const float* be1  = (const float*)d_in[7];
    const float* W2l  = (const float*)d_in[8];
    const float* b2   = (const float*)d_in[9];
    const float* W2r  = (const float*)d_in[10];
    const float* g2   = (const float*)d_in[11];
    const float* be2  = (const float*)d_in[12];
    const float* Wfc  = (const float*)d_in[13];
    const float* bfc  = (const float*)d_in[14];
    float* out = (float*)d_out;

    __half *p_Ahi, *p_Shi, *p_Bh;
    float *p_h1, *p_h2, *p_stats;
    cudaGetSymbolAddress((void**)&p_Ahi,   g_Ahi);
    cudaGetSymbolAddress((void**)&p_Shi,   g_Shi);
    cudaGetSymbolAddress((void**)&p_Bh,    g_Bhi);
    cudaGetSymbolAddress((void**)&p_h1,    g_h1);
    cudaGetSymbolAddress((void**)&p_h2,    g_h2);
    cudaGetSymbolAddress((void**)&p_stats, g_stats);

    const int SMEM = 2048 + 4 * 16384;   // 67584 -> 2 CTAs/SM
    cudaFuncSetAttribute(k_mmagemm<DIN>,
                         cudaFuncAttributeMaxDynamicSharedMemorySize, SMEM);
    cudaFuncSetAttribute(k_mmagemm<DH>,
                         cudaFuncAttributeMaxDynamicSharedMemorySize, SMEM);

    const int nb1 = (NN + 1023) / 1024;
    const int egrid = (NE + 255) / 256;
    dim3 gg((NN + 127) / 128, 2);        // 782 x 2 CTAs

    k_init<<<(NN + 255) / 256, 256>>>();
    k_hist<<<egrid, 256>>>(edst);
    k_scan1<<<nb1, 1024>>>();
    k_scan3<<<nb1, 1024>>>(nb1);
    k_fill<<<egrid, 256>>>(esrc, edst);

    // layer 1
    k_split<<<2048, 256>>>(x, p_Shi, NN * DIN / 4);
    k_prepB<DIN><<<DIN, 256>>>(W1l, W1r, p_Bh);
    k_spmm1<<<(NN + 7) / 8, 256>>>(p_Shi, p_Ahi);
    k_mmagemm<DIN><<<gg, 256, SMEM>>>(p_Ahi, p_Shi, p_Bh, b1, p_h1, p_stats);
    k_bnrelu<<<2048, 256>>>(p_h1, p_stats, g1, be1, p_Shi);

    // layer 2
    k_prepB<DH><<<DH, 256>>>(W2l, W2r, p_Bh);
    k_spmm2<<<(NN + 7) / 8, 256>>>(p_Shi, p_Ahi);
    k_mmagemm<DH><<<gg, 256, SMEM>>>(p_Ahi, p_Shi, p_Bh, b2, p_h2, p_stats + 512);

    // classifier (BN+ReLU fused, stats->bn computed in-kernel)
    k_fc<<<(NN + 31) / 32, 256>>>(p_h2, p_stats + 512, g2, be2, Wfc, bfc, out);
}

// round 11
// speedup vs baseline: 2.7717x; 1.3529x over previous
#include <cuda_runtime.h>
#include <cuda_fp16.h>
#include <cstdint>

#define NN   100000
#define NE   1600000
#define DIN  128
#define DH   256
#define NCLS 32

typedef unsigned long long ull;

// ---------------- scratch (device globals) ---------------------------------
__device__ int   g_deg[NN];
__device__ int   g_rowptr[NN + 1];
__device__ int   g_cursor[NN];
__device__ int   g_csr[NE];
__device__ int   g_bsum[128];
__device__ __align__(128) __half g_Ahi[(size_t)NN * DH];
__device__ __align__(128) __half g_Shi[(size_t)NN * DH];
__device__ __align__(128) __half g_Bhi[DH * 2 * DH];     // 256 x 512 max
__device__ __align__(128) float  g_h1[(size_t)NN * DH];
__device__ __align__(128) float  g_h2[(size_t)NN * DH];
__device__ float g_stats[1024];

// ---------------- helpers ---------------------------------------------------
__device__ __forceinline__ uint32_t smem_u32(const void* p) {
    uint32_t a;
    asm("{ .reg .u64 t; cvta.to.shared.u64 t, %1; cvt.u32.u64 %0, t; }"
        : "=r"(a) : "l"(p));
    return a;
}
__device__ __forceinline__ void cpasync16(uint32_t dst, const void* src) {
    asm volatile("cp.async.cg.shared.global [%0], [%1], 16;"
                 :: "r"(dst), "l"(src));
}
#define CP_COMMIT() asm volatile("cp.async.commit_group;" ::: "memory")

__device__ __forceinline__ void ldsm_x4(uint32_t* r, uint32_t addr) {
    asm volatile("ldmatrix.sync.aligned.m8n8.x4.shared.b16 {%0,%1,%2,%3}, [%4];"
                 : "=r"(r[0]), "=r"(r[1]), "=r"(r[2]), "=r"(r[3]) : "r"(addr));
}
__device__ __forceinline__ void mma16816(float* c, const uint32_t* a,
                                         const uint32_t* b) {
    asm volatile(
        "mma.sync.aligned.m16n8k16.row.col.f32.f16.f16.f32 "
        "{%0,%1,%2,%3}, {%4,%5,%6,%7}, {%8,%9}, {%0,%1,%2,%3};"
        : "+f"(c[0]), "+f"(c[1]), "+f"(c[2]), "+f"(c[3])
        : "r"(a[0]), "r"(a[1]), "r"(a[2]), "r"(a[3]), "r"(b[0]), "r"(b[1]));
}

__device__ __forceinline__ uint32_t pkh(float a, float b) {
    __half2 t = __floats2half2_rn(a, b);
    return *(uint32_t*)&t;
}

// ---------------- scan helper ----------------------------------------------
__device__ __forceinline__ int block_scan_incl(int v) {
    __shared__ int ws[32];
    int lane = threadIdx.x & 31, wid = threadIdx.x >> 5;
#pragma unroll
    for (int o = 1; o < 32; o <<= 1) {
        int n = __shfl_up_sync(0xffffffffu, v, o);
        if (lane >= o) v += n;
    }
    if (lane == 31) ws[wid] = v;
    __syncthreads();
    int nw = blockDim.x >> 5;
    if (wid == 0) {
        int s = (lane < nw) ? ws[lane] : 0;
#pragma unroll
        for (int o = 1; o < 32; o <<= 1) {
            int n = __shfl_up_sync(0xffffffffu, s, o);
            if (lane >= o) s += n;
        }
        ws[lane] = s;
    }
    __syncthreads();
    if (wid > 0) v += ws[wid - 1];
    return v;
}

// ---------------- fused prep1: init | x->fp16 split | prepB<DIN> ------------
// blocks [0,391): init; [391,1415): split; [1415,1543): prepB layer1
__global__ void __launch_bounds__(256) k_prep1(const float* __restrict__ X,
                                               __half* __restrict__ Shi,
                                               const float* __restrict__ Wl,
                                               const float* __restrict__ Wr,
                                               __half* __restrict__ Bh) {
    int b = blockIdx.x, t = threadIdx.x;
    if (b < 391) {
        int i = b * 256 + t;
        if (i < NN) { g_deg[i] = 0; g_cursor[i] = 0; }
        if (i < 1024) g_stats[i] = 0.f;
    } else if (b < 1415) {
        const int total4 = NN * DIN / 4;
        for (int i = (b - 391) * 256 + t; i < total4; i += 1024 * 256) {
            float4 v = ((const float4*)X)[i];
            uint2 h = make_uint2(pkh(v.x, v.y), pkh(v.z, v.w));
            *(uint2*)((char*)Shi + (size_t)i * 8) = h;
        }
    } else {
        int idx = (b - 1415) * 256 + t;          // 128 blocks -> DIN*256
        int k = idx >> 8, n = idx & 255;
        const int LDB = 2 * DIN;
        Bh[(size_t)n * LDB + k]       = __float2half_rn(Wl[idx]);
        Bh[(size_t)n * LDB + DIN + k] = __float2half_rn(Wr[idx]);
    }
}

// ---------------- graph prep ----------------------------------------------
__global__ void k_hist(const int* __restrict__ dst) {
    int e4 = blockIdx.x * blockDim.x + threadIdx.x;
    if (e4 * 4 < NE) {
        int4 d = __ldg((const int4*)dst + e4);
        atomicAdd(&g_deg[d.x], 1);
        atomicAdd(&g_deg[d.y], 1);
        atomicAdd(&g_deg[d.z], 1);
        atomicAdd(&g_deg[d.w], 1);
    }
}
__global__ void k_scan1() {
    int i = blockIdx.x * 1024 + threadIdx.x;
    int v = (i < NN) ? g_deg[i] : 0;
    int incl = block_scan_incl(v);
    if (i < NN) g_rowptr[i + 1] = incl;
    if (threadIdx.x == 1023) g_bsum[blockIdx.x] = incl;
}
__global__ void k_scan3(int nb) {
    __shared__ int s_off;
    int t = threadIdx.x;
    int v = (t < nb) ? g_bsum[t] : 0;
    int incl = block_scan_incl(v);
    if (blockIdx.x == 0) {
        if (t == 0) s_off = 0;
    } else if (t == (int)blockIdx.x - 1) {
        s_off = incl;
    }
    __syncthreads();
    int i = blockIdx.x * 1024 + t;
    if (i < NN) g_rowptr[i + 1] += s_off;
    if (i == 0) g_rowptr[0] = 0;
}
__global__ void k_fill(const int* __restrict__ src, const int* __restrict__ dst) {
    int e4 = blockIdx.x * blockDim.x + threadIdx.x;
    if (e4 * 4 < NE) {
        int4 d = __ldg((const int4*)dst + e4);
        int4 s = __ldg((const int4*)src + e4);
        int p;
        p = atomicAdd(&g_cursor[d.x], 1); g_csr[g_rowptr[d.x] + p] = s.x;
        p = atomicAdd(&g_cursor[d.y], 1); g_csr[g_rowptr[d.y] + p] = s.y;
        p = atomicAdd(&g_cursor[d.z], 1); g_csr[g_rowptr[d.z] + p] = s.z;
        p = atomicAdd(&g_cursor[d.w], 1); g_csr[g_rowptr[d.w] + p] = s.w;
    }
}

// ---------------- SpMM layer1: gather fp16 table (D=128) -------------------
__global__ void __launch_bounds__(256) k_spmm1(const __half* __restrict__ Xh,
                                               __half* __restrict__ Ahi) {
    int warp = threadIdx.x >> 5, lane = threadIdx.x & 31;
    int node = blockIdx.x * 8 + warp;
    if (node >= NN) return;
    int beg = g_rowptr[node], end = g_rowptr[node + 1];
    int deg = end - beg;
    int myidx = (beg + lane < end) ? __ldg(&g_csr[beg + lane]) : 0;
    int dmax = deg < 32 ? deg : 32;

    float4 p = make_float4(0.f, 0.f, 0.f, 0.f);
    float4 q = make_float4(0.f, 0.f, 0.f, 0.f);

    auto addu2 = [&](float4& a, uint2 u) {
        __half2* ph = (__half2*)&u;
        float2 f0 = __half22float2(ph[0]);
        float2 f1 = __half22float2(ph[1]);
        a.x += f0.x; a.y += f0.y; a.z += f1.x; a.w += f1.y;
    };

    int j = 0;
    for (; j + 4 <= dmax; j += 4) {
        int s0 = __shfl_sync(0xffffffffu, myidx, j + 0);
        int s1 = __shfl_sync(0xffffffffu, myidx, j + 1);
        int s2 = __shfl_sync(0xffffffffu, myidx, j + 2);
        int s3 = __shfl_sync(0xffffffffu, myidx, j + 3);
        uint2 u0 = __ldg((const uint2*)(Xh + (size_t)s0 * DIN) + lane);
        uint2 u1 = __ldg((const uint2*)(Xh + (size_t)s1 * DIN) + lane);
        uint2 u2 = __ldg((const uint2*)(Xh + (size_t)s2 * DIN) + lane);
        uint2 u3 = __ldg((const uint2*)(Xh + (size_t)s3 * DIN) + lane);
        addu2(p, u0); addu2(q, u1); addu2(p, u2); addu2(q, u3);
    }
    for (; j < dmax; j++) {
        int s0 = __shfl_sync(0xffffffffu, myidx, j);
        addu2(p, __ldg((const uint2*)(Xh + (size_t)s0 * DIN) + lane));
    }
    for (int jj = beg + 32; jj < end; jj++) {
        int s0 = __ldg(&g_csr[jj]);
        addu2(p, __ldg((const uint2*)(Xh + (size_t)s0 * DIN) + lane));
    }

    float inv = 1.f / fmaxf((float)deg, 1.f);
    float4 a = make_float4((p.x + q.x) * inv, (p.y + q.y) * inv,
                           (p.z + q.z) * inv, (p.w + q.w) * inv);
    uint2 h = make_uint2(pkh(a.x, a.y), pkh(a.z, a.w));
    *(uint2*)(Ahi + (size_t)node * DIN + lane * 4) = h;
}

// ---------------- SpMM layer2: gather fp16 table (D=256) -------------------
__global__ void __launch_bounds__(256) k_spmm2(const __half* __restrict__ Xh,
                                               __half* __restrict__ Ahi) {
    int warp = threadIdx.x >> 5, lane = threadIdx.x & 31;
    int node = blockIdx.x * 8 + warp;
    if (node >= NN) return;
    int beg = g_rowptr[node], end = g_rowptr[node + 1];
    int deg = end - beg;
    int myidx = (beg + lane < end) ? __ldg(&g_csr[beg + lane]) : 0;
    int dmax = deg < 32 ? deg : 32;

    float p[8] = {0, 0, 0, 0, 0, 0, 0, 0};
    float q[8] = {0, 0, 0, 0, 0, 0, 0, 0};

    auto addu4 = [&](float* a, uint4 u) {
        __half2* ph = (__half2*)&u;
#pragma unroll
        for (int z = 0; z < 4; z++) {
            float2 f = __half22float2(ph[z]);
            a[z * 2] += f.x; a[z * 2 + 1] += f.y;
        }
    };

    int j = 0;
    for (; j + 2 <= dmax; j += 2) {
        int s0 = __shfl_sync(0xffffffffu, myidx, j + 0);
        int s1 = __shfl_sync(0xffffffffu, myidx, j + 1);
        uint4 u0 = __ldg((const uint4*)(Xh + (size_t)s0 * DH) + lane);
        uint4 u1 = __ldg((const uint4*)(Xh + (size_t)s1 * DH) + lane);
        addu4(p, u0); addu4(q, u1);
    }
    for (; j < dmax; j++) {
        int s0 = __shfl_sync(0xffffffffu, myidx, j);
        addu4(p, __ldg((const uint4*)(Xh + (size_t)s0 * DH) + lane));
    }
    for (int jj = beg + 32; jj < end; jj++) {
        int s0 = __ldg(&g_csr[jj]);
        addu4(p, __ldg((const uint4*)(Xh + (size_t)s0 * DH) + lane));
    }

    float inv = 1.f / fmaxf((float)deg, 1.f);
    uint4 h;
    uint32_t* hp = (uint32_t*)&h;
#pragma unroll
    for (int z = 0; z < 4; z++) {
        float v0 = (p[z * 2] + q[z * 2]) * inv;
        float v1 = (p[z * 2 + 1] + q[z * 2 + 1]) * inv;
        hp[z] = pkh(v0, v1);
    }
    *(uint4*)(Ahi + (size_t)node * DH + lane * 8) = h;
}

// ---------------- mma.sync GEMM fp16, K-chunk 64, x4 B loads ----------------
// CTA 128x128, 3 stages x 32KB. acc += aH*bH. BN stats fused in epilogue.
template <int K>
__global__ void __launch_bounds__(256, 2)
k_mmagemm(const __half* __restrict__ Ahi, const __half* __restrict__ Shi,
          const __half* __restrict__ Bh,  const float* __restrict__ bias,
          float* __restrict__ Out, float* __restrict__ stats) {
    constexpr int CH  = 2 * K / 64;
    constexpr int LDB = 2 * K;
    constexpr int T_BH = 16384;
    constexpr int STAGE = 32768;

    extern __shared__ __align__(128) char dsm[];
    float* sbias = (float*)dsm;                 // 512B
    float* s_red = (float*)(dsm + 512);         // 1KB: sum[128], sq[128]
    uint32_t stage0 = smem_u32(dsm) + 2048;

    const int t = threadIdx.x;
    const int wid = t >> 5, lane = t & 31;
    const int wm = wid >> 2, wn = wid & 3;       // warps 2 x 4
    const int m0 = blockIdx.x * 128;
    const int n0 = blockIdx.y * 128;

    if (t < 128) { sbias[t] = bias[n0 + t]; s_red[t] = 0.f; s_red[128 + t] = 0.f; }

    float acc[4][4][4];
#pragma unroll
    for (int i = 0; i < 4; i++)
#pragma unroll
        for (int j = 0; j < 4; j++)
#pragma unroll
            for (int q = 0; q < 4; q++) acc[i][j][q] = 0.f;

    auto load_chunk = [&](int c, int s) {
        uint32_t sb = stage0 + s * STAGE;
        const __half* Ah; int k0;
        if (c < K / 64) { Ah = Ahi; k0 = c * 64; }
        else            { Ah = Shi; k0 = (c - K / 64) * 64; }
#pragma unroll
        for (int it = 0; it < 4; it++) {
            int i = t + 256 * it;                 // 0..1023
            int row = i >> 3, ch = i & 7;
            uint32_t sw = row * 128 + ((ch ^ (row & 7)) << 4);
            int gr = m0 + row; if (gr > NN - 1) gr = NN - 1;
            cpasync16(sb + sw, Ah + (size_t)gr * K + k0 + ch * 8);
            cpasync16(sb + T_BH + sw, Bh + (size_t)(n0 + row) * LDB + c * 64 + ch * 8);
        }
        CP_COMMIT();
    };

    load_chunk(0, 0);
    load_chunk(1, 1);
    if (CH > 2) load_chunk(2, 2);

#pragma unroll 1
    for (int c = 0; c < CH; c++) {
        int s = c % 3;
        int rem = CH - 1 - c;
        if (rem >= 2)      asm volatile("cp.async.wait_group 2;" ::: "memory");
        else if (rem == 1) asm volatile("cp.async.wait_group 1;" ::: "memory");
        else               asm volatile("cp.async.wait_group 0;" ::: "memory");
        __syncthreads();

        uint32_t sb = stage0 + s * STAGE;
#pragma unroll
        for (int ks = 0; ks < 4; ks++) {
            uint32_t aH[4][4], bH[4][2];
#pragma unroll
            for (int mt = 0; mt < 4; mt++) {
                int r = wm * 64 + mt * 16 + (lane & 15);
                int kc = ks * 2 + (lane >> 4);
                ldsm_x4(aH[mt], sb + r * 128 + ((kc ^ (r & 7)) << 4));
            }
#pragma unroll
            for (int np = 0; np < 2; np++) {
                int nrow = wn * 32 + np * 16 + (lane & 7) + ((lane >> 4) << 3);
                int kc = ks * 2 + ((lane >> 3) & 1);
                uint32_t bp[4];
                ldsm_x4(bp, sb + T_BH + nrow * 128 + ((kc ^ (nrow & 7)) << 4));
                bH[np * 2][0] = bp[0];     bH[np * 2][1] = bp[1];
                bH[np * 2 + 1][0] = bp[2]; bH[np * 2 + 1][1] = bp[3];
            }
#pragma unroll
            for (int mt = 0; mt < 4; mt++)
#pragma unroll
                for (int nt = 0; nt < 4; nt++)
                    mma16816(acc[mt][nt], aH[mt], bH[nt]);
        }
        __syncthreads();
        if (c + 3 < CH) load_chunk(c + 3, s);
    }

    // epilogue: bias + store + per-column BN partial stats (shfl-reduced)
    float csum[4][2], csq[4][2];
#pragma unroll
    for (int nt = 0; nt < 4; nt++) {
        csum[nt][0] = 0.f; csum[nt][1] = 0.f;
        csq[nt][0] = 0.f;  csq[nt][1] = 0.f;
    }
#pragma unroll
    for (int mt = 0; mt < 4; mt++) {
        int r0 = m0 + wm * 64 + mt * 16 + (lane >> 2);
        bool v0ok = r0 < NN, v1ok = (r0 + 8) < NN;
#pragma unroll
        for (int nt = 0; nt < 4; nt++) {
            int lc = wn * 32 + nt * 8 + (lane & 3) * 2;
            float bx = sbias[lc], by = sbias[lc + 1];
            if (v0ok) {
                float vx = acc[mt][nt][0] + bx, vy = acc[mt][nt][1] + by;
                *(float2*)(Out + (size_t)r0 * DH + n0 + lc) = make_float2(vx, vy);
                csum[nt][0] += vx; csq[nt][0] += vx * vx;
                csum[nt][1] += vy; csq[nt][1] += vy * vy;
            }
            if (v1ok) {
                float vx = acc[mt][nt][2] + bx, vy = acc[mt][nt][3] + by;
                *(float2*)(Out + (size_t)(r0 + 8) * DH + n0 + lc) = make_float2(vx, vy);
                csum[nt][0] += vx; csq[nt][0] += vx * vx;
                csum[nt][1] += vy; csq[nt][1] += vy * vy;
            }
        }
    }
    // reduce across the 8 lanes sharing each column pair (lane & 3 fixed)
#pragma unroll
    for (int nt = 0; nt < 4; nt++) {
#pragma unroll
        for (int off = 4; off < 32; off <<= 1) {
            csum[nt][0] += __shfl_xor_sync(0xffffffffu, csum[nt][0], off);
            csum[nt][1] += __shfl_xor_sync(0xffffffffu, csum[nt][1], off);
            csq[nt][0]  += __shfl_xor_sync(0xffffffffu, csq[nt][0], off);
            csq[nt][1]  += __shfl_xor_sync(0xffffffffu, csq[nt][1], off);
        }
    }
    __syncthreads();
    if (lane < 4) {
#pragma unroll
        for (int nt = 0; nt < 4; nt++) {
            int lc = wn * 32 + nt * 8 + lane * 2;
            atomicAdd(&s_red[lc], csum[nt][0]);
            atomicAdd(&s_red[lc + 1], csum[nt][1]);
            atomicAdd(&s_red[128 + lc], csq[nt][0]);
            atomicAdd(&s_red[128 + lc + 1], csq[nt][1]);
        }
    }
    __syncthreads();
    if (t < 128) {
        atomicAdd(&stats[n0 + t], s_red[t]);
        atomicAdd(&stats[256 + n0 + t], s_red[128 + t]);
    }
}

// ---------------- fused prep2: BN+ReLU->fp16 | prepB<DH> --------------------
// blocks [0,1024): bnrelu; [1024,1280): prepB layer2
__global__ void __launch_bounds__(256) k_prep2(const float* __restrict__ H,
                                               const float* __restrict__ stats,
                                               const float* __restrict__ gam,
                                               const float* __restrict__ bet,
                                               __half* __restrict__ Hi,
                                               const float* __restrict__ Wl,
                                               const float* __restrict__ Wr,
                                               __half* __restrict__ Bh) {
    int b = blockIdx.x, t = threadIdx.x;
    if (b >= 1024) {
        int idx = (b - 1024) * 256 + t;          // 256 blocks -> DH*256
        int k = idx >> 8, n = idx & 255;
        const int LDB = 2 * DH;
        Bh[(size_t)n * LDB + k]      = __float2half_rn(Wl[idx]);
        Bh[(size_t)n * LDB + DH + k] = __float2half_rn(Wr[idx]);
        return;
    }
    __shared__ float sbn[512];
    {
        int c = t;
        float mu  = stats[c] * (1.f / NN);
        float var = stats[256 + c] * (1.f / NN) - mu * mu;
        float rstd = rsqrtf(var + 1e-5f);
        float sc = rstd * gam[c];
        sbn[c] = sc;
        sbn[256 + c] = bet[c] - mu * sc;
    }
    __syncthreads();
    const int total = NN * DH / 4;
    for (int i = b * 256 + t; i < total; i += 1024 * 256) {
        float4 v = ((const float4*)H)[i];
        int c = (i & 63) * 4;
        v.x = fmaxf(0.f, v.x * sbn[c + 0] + sbn[256 + c + 0]);
        v.y = fmaxf(0.f, v.y * sbn[c + 1] + sbn[256 + c + 1]);
        v.z = fmaxf(0.f, v.z * sbn[c + 2] + sbn[256 + c + 2]);
        v.w = fmaxf(0.f, v.w * sbn[c + 3] + sbn[256 + c + 3]);
        uint2 h = make_uint2(pkh(v.x, v.y), pkh(v.z, v.w));
        *(uint2*)((char*)Hi + (size_t)i * 8) = h;
    }
}

// ---------------- final FC with fused BN(from stats)+ReLU -------------------
__global__ void __launch_bounds__(256) k_fc(const float* __restrict__ H,
                                            const float* __restrict__ stats,
                                            const float* __restrict__ gam,
                                            const float* __restrict__ bet,
                                            const float* __restrict__ W,
                                            const float* __restrict__ b,
                                            float* __restrict__ out) {
    __shared__ __align__(16) float Ws[DH * NCLS];
    __shared__ float sbn[512];
    for (int i = threadIdx.x; i < DH * NCLS / 4; i += 256)
        ((float4*)Ws)[i] = ((const float4*)W)[i];
    {
        int c = threadIdx.x;
        float mu  = stats[c] * (1.f / NN);
        float var = stats[256 + c] * (1.f / NN) - mu * mu;
        float rstd = rsqrtf(var + 1e-5f);
        float sc = rstd * gam[c];
        sbn[c] = sc;
        sbn[256 + c] = bet[c] - mu * sc;
    }
    __syncthreads();
    int row = blockIdx.x * 32 + (threadIdx.x >> 3);
    int c = (threadIdx.x & 7) * 4;
    if (row >= NN) return;
    const float4* hr = (const float4*)(H + (size_t)row * DH);
    float4 acc = *(const float4*)(b + c);
#pragma unroll 8
    for (int k4 = 0; k4 < DH / 4; k4++) {
        float4 h = hr[k4];
        int kb = k4 * 4;
        h.x = fmaxf(0.f, h.x * sbn[kb + 0] + sbn[256 + kb + 0]);
        h.y = fmaxf(0.f, h.y * sbn[kb + 1] + sbn[256 + kb + 1]);
        h.z = fmaxf(0.f, h.z * sbn[kb + 2] + sbn[256 + kb + 2]);
        h.w = fmaxf(0.f, h.w * sbn[kb + 3] + sbn[256 + kb + 3]);
        float4 w0 = *(float4*)&Ws[(kb + 0) * NCLS + c];
        float4 w1 = *(float4*)&Ws[(kb + 1) * NCLS + c];
        float4 w2 = *(float4*)&Ws[(kb + 2) * NCLS + c];
        float4 w3 = *(float4*)&Ws[(kb + 3) * NCLS + c];
        acc.x += h.x * w0.x + h.y * w1.x + h.z * w2.x + h.w * w3.x;
        acc.y += h.x * w0.y + h.y * w1.y + h.z * w2.y + h.w * w3.y;
        acc.z += h.x * w0.z + h.y * w1.z + h.z * w2.z + h.w * w3.z;
        acc.w += h.x * w0.w + h.y * w1.w + h.z * w2.w + h.w * w3.w;
    }
    *(float4*)(out + (size_t)row * NCLS + c) = acc;
}

// ---------------- launch ----------------------------------------------------
extern "C" void kernel_launch(void* const* d_in, const int* in_sizes, int n_in,
                              void* d_out, int out_size) {
    const float* x    = (const float*)d_in[0];
    const int*   esrc = (const int*)d_in[1];
    const int*   edst = (const int*)d_in[2];
    const float* W1l  = (const float*)d_in[3];
    const float* b1   = (const float*)d_in[4];
    const float* W1r  = (const float*)d_in[5];
    const float* g1   = (const float*)d_in[6];
    const float* be1  = (const float*)d_in[7];
    const float* W2l  = (const float*)d_in[8];
    const float* b2   = (const float*)d_in[9];
    const float* W2r  = (const float*)d_in[10];
    const float* g2   = (const float*)d_in[11];
    const float* be2  = (const float*)d_in[12];
    const float* Wfc  = (const float*)d_in[13];
    const float* bfc  = (const float*)d_in[14];
    float* out = (float*)d_out;

    __half *p_Ahi, *p_Shi, *p_Bh;
    float *p_h1, *p_h2, *p_stats;
    cudaGetSymbolAddress((void**)&p_Ahi,   g_Ahi);
    cudaGetSymbolAddress((void**)&p_Shi,   g_Shi);
    cudaGetSymbolAddress((void**)&p_Bh,    g_Bhi);
    cudaGetSymbolAddress((void**)&p_h1,    g_h1);
    cudaGetSymbolAddress((void**)&p_h2,    g_h2);
    cudaGetSymbolAddress((void**)&p_stats, g_stats);

    const int SMEM = 2048 + 3 * 32768;   // 100352
    cudaFuncSetAttribute(k_mmagemm<DIN>,
                         cudaFuncAttributeMaxDynamicSharedMemorySize, SMEM);
    cudaFuncSetAttribute(k_mmagemm<DH>,
                         cudaFuncAttributeMaxDynamicSharedMemorySize, SMEM);

    const int nb1 = (NN + 1023) / 1024;
    const int e4grid = (NE / 4 + 255) / 256;
    dim3 gg((NN + 127) / 128, 2);        // 782 x 2 CTAs

    // prep (init | split | prepB1 concurrent) + CSR build
    k_prep1<<<1543, 256>>>(x, p_Shi, W1l, W1r, p_Bh);
    k_hist<<<e4grid, 256>>>(edst);
    k_scan1<<<nb1, 1024>>>();
    k_scan3<<<nb1, 1024>>>(nb1);
    k_fill<<<e4grid, 256>>>(esrc, edst);

    // layer 1
    k_spmm1<<<(NN + 7) / 8, 256>>>(p_Shi, p_Ahi);
    k_mmagemm<DIN><<<gg, 256, SMEM>>>(p_Ahi, p_Shi, p_Bh, b1, p_h1, p_stats);

    // bnrelu | prepB2 concurrent
    k_prep2<<<1280, 256>>>(p_h1, p_stats, g1, be1, p_Shi, W2l, W2r, p_Bh);

    // layer 2
    k_spmm2<<<(NN + 7) / 8, 256>>>(p_Shi, p_Ahi);
    k_mmagemm<DH><<<gg, 256, SMEM>>>(p_Ahi, p_Shi, p_Bh, b2, p_h2, p_stats + 512);

    // classifier (BN+ReLU fused)
    k_fc<<<(NN + 31) / 32, 256>>>(p_h2, p_stats + 512, g2, be2, Wfc, bfc, out);
}

// round 12
// speedup vs baseline: 2.7836x; 1.0043x over previous
#include <cuda_runtime.h>
#include <cuda_fp16.h>
#include <cstdint>

#define NN   100000
#define NE   1600000
#define DIN  128
#define DH   256
#define NCLS 32

typedef unsigned long long ull;

// ---------------- scratch (device globals; zero-init at load) ---------------
// NOTE: g_deg/g_cursor/g_stats are re-zeroed by tail kernels of each run so
// the next graph replay sees clean state (zero-init covers the first run).
__device__ int   g_deg[NN];
__device__ int   g_rowptr[NN + 1];
__device__ int   g_cursor[NN];
__device__ int   g_csr[NE];
__device__ int   g_bsum[128];
__device__ __align__(128) __half g_Ahi[(size_t)NN * DH];
__device__ __align__(128) __half g_Shi[(size_t)NN * DH];
__device__ __align__(128) __half g_Bhi[DIN * 2 * DH];    // layer1 B: 256 x 256
__device__ __align__(128) __half g_Bhi2[DH * 2 * DH];    // layer2 B: 256 x 512
__device__ __align__(128) float  g_h1[(size_t)NN * DH];
__device__ __align__(128) float  g_h2[(size_t)NN * DH];
__device__ float g_stats[1024];

// ---------------- helpers ---------------------------------------------------
__device__ __forceinline__ uint32_t smem_u32(const void* p) {
    uint32_t a;
    asm("{ .reg .u64 t; cvta.to.shared.u64 t, %1; cvt.u32.u64 %0, t; }"
        : "=r"(a) : "l"(p));
    return a;
}
__device__ __forceinline__ void cpasync16(uint32_t dst, const void* src) {
    asm volatile("cp.async.cg.shared.global [%0], [%1], 16;"
                 :: "r"(dst), "l"(src));
}
#define CP_COMMIT() asm volatile("cp.async.commit_group;" ::: "memory")

__device__ __forceinline__ void ldsm_x4(uint32_t* r, uint32_t addr) {
    asm volatile("ldmatrix.sync.aligned.m8n8.x4.shared.b16 {%0,%1,%2,%3}, [%4];"
                 : "=r"(r[0]), "=r"(r[1]), "=r"(r[2]), "=r"(r[3]) : "r"(addr));
}
__device__ __forceinline__ void mma16816(float* c, const uint32_t* a,
                                         const uint32_t* b) {
    asm volatile(
        "mma.sync.aligned.m16n8k16.row.col.f32.f16.f16.f32 "
        "{%0,%1,%2,%3}, {%4,%5,%6,%7}, {%8,%9}, {%0,%1,%2,%3};"
        : "+f"(c[0]), "+f"(c[1]), "+f"(c[2]), "+f"(c[3])
        : "r"(a[0]), "r"(a[1]), "r"(a[2]), "r"(a[3]), "r"(b[0]), "r"(b[1]));
}

__device__ __forceinline__ uint32_t pkh(float a, float b) {
    __half2 t = __floats2half2_rn(a, b);
    return *(uint32_t*)&t;
}

// ---------------- scan helper ----------------------------------------------
__device__ __forceinline__ int block_scan_incl(int v) {
    __shared__ int ws[32];
    int lane = threadIdx.x & 31, wid = threadIdx.x >> 5;
#pragma unroll
    for (int o = 1; o < 32; o <<= 1) {
        int n = __shfl_up_sync(0xffffffffu, v, o);
        if (lane >= o) v += n;
    }
    if (lane == 31) ws[wid] = v;
    __syncthreads();
    int nw = blockDim.x >> 5;
    if (wid == 0) {
        int s = (lane < nw) ? ws[lane] : 0;
#pragma unroll
        for (int o = 1; o < 32; o <<= 1) {
            int n = __shfl_up_sync(0xffffffffu, s, o);
            if (lane >= o) s += n;
        }
        ws[lane] = s;
    }
    __syncthreads();
    if (wid > 0) v += ws[wid - 1];
    return v;
}

// ---------------- fused prep1: hist | x-split | prepB1 | prepB2 -------------
// blocks [0,1563): hist; [1563,2587): split; [2587,2715): prepB1;
// [2715,2971): prepB2.  g_deg was zeroed by the previous run's k_fc.
__global__ void __launch_bounds__(256) k_prep1(
    const int* __restrict__ dst, const float* __restrict__ X,
    __half* __restrict__ Shi,
    const float* __restrict__ W1l, const float* __restrict__ W1r,
    __half* __restrict__ Bh1,
    const float* __restrict__ W2l, const float* __restrict__ W2r,
    __half* __restrict__ Bh2) {
    int b = blockIdx.x, t = threadIdx.x;
    if (b < 1563) {
        int e4 = b * 256 + t;
        if (e4 * 4 < NE) {
            int4 d = __ldg((const int4*)dst + e4);
            atomicAdd(&g_deg[d.x], 1);
            atomicAdd(&g_deg[d.y], 1);
            atomicAdd(&g_deg[d.z], 1);
            atomicAdd(&g_deg[d.w], 1);
        }
    } else if (b < 2587) {
        const int total4 = NN * DIN / 4;
        for (int i = (b - 1563) * 256 + t; i < total4; i += 1024 * 256) {
            float4 v = ((const float4*)X)[i];
            uint2 h = make_uint2(pkh(v.x, v.y), pkh(v.z, v.w));
            *(uint2*)((char*)Shi + (size_t)i * 8) = h;
        }
    } else if (b < 2715) {
        int idx = (b - 2587) * 256 + t;          // 128 blocks -> DIN*256
        int k = idx >> 8, n = idx & 255;
        const int LDB = 2 * DIN;
        Bh1[(size_t)n * LDB + k]       = __float2half_rn(W1l[idx]);
        Bh1[(size_t)n * LDB + DIN + k] = __float2half_rn(W1r[idx]);
    } else {
        int idx = (b - 2715) * 256 + t;          // 256 blocks -> DH*256
        int k = idx >> 8, n = idx & 255;
        const int LDB = 2 * DH;
        Bh2[(size_t)n * LDB + k]      = __float2half_rn(W2l[idx]);
        Bh2[(size_t)n * LDB + DH + k] = __float2half_rn(W2r[idx]);
    }
}

// ---------------- CSR scan + fill ------------------------------------------
__global__ void k_scan1() {
    int i = blockIdx.x * 1024 + threadIdx.x;
    int v = (i < NN) ? g_deg[i] : 0;
    int incl = block_scan_incl(v);
    if (i < NN) g_rowptr[i + 1] = incl;
    if (threadIdx.x == 1023) g_bsum[blockIdx.x] = incl;
}
__global__ void k_scan3(int nb) {
    __shared__ int s_off;
    int t = threadIdx.x;
    int v = (t < nb) ? g_bsum[t] : 0;
    int incl = block_scan_incl(v);
    if (blockIdx.x == 0) {
        if (t == 0) s_off = 0;
    } else if (t == (int)blockIdx.x - 1) {
        s_off = incl;
    }
    __syncthreads();
    int i = blockIdx.x * 1024 + t;
    if (i < NN) g_rowptr[i + 1] += s_off;
    if (i == 0) g_rowptr[0] = 0;
}
__global__ void k_fill(const int* __restrict__ src, const int* __restrict__ dst) {
    int e4 = blockIdx.x * blockDim.x + threadIdx.x;
    if (e4 * 4 < NE) {
        int4 d = __ldg((const int4*)dst + e4);
        int4 s = __ldg((const int4*)src + e4);
        int p;
        p = atomicAdd(&g_cursor[d.x], 1); g_csr[g_rowptr[d.x] + p] = s.x;
        p = atomicAdd(&g_cursor[d.y], 1); g_csr[g_rowptr[d.y] + p] = s.y;
        p = atomicAdd(&g_cursor[d.z], 1); g_csr[g_rowptr[d.z] + p] = s.z;
        p = atomicAdd(&g_cursor[d.w], 1); g_csr[g_rowptr[d.w] + p] = s.w;
    }
}

// ---------------- SpMM layer1: gather fp16 table (D=128) -------------------
__global__ void __launch_bounds__(256) k_spmm1(const __half* __restrict__ Xh,
                                               __half* __restrict__ Ahi) {
    int warp = threadIdx.x >> 5, lane = threadIdx.x & 31;
    int node = blockIdx.x * 8 + warp;
    if (node >= NN) return;
    int beg = g_rowptr[node], end = g_rowptr[node + 1];
    int deg = end - beg;
    int myidx = (beg + lane < end) ? __ldg(&g_csr[beg + lane]) : 0;
    int dmax = deg < 32 ? deg : 32;

    float4 p = make_float4(0.f, 0.f, 0.f, 0.f);
    float4 q = make_float4(0.f, 0.f, 0.f, 0.f);

    auto addu2 = [&](float4& a, uint2 u) {
        __half2* ph = (__half2*)&u;
        float2 f0 = __half22float2(ph[0]);
        float2 f1 = __half22float2(ph[1]);
        a.x += f0.x; a.y += f0.y; a.z += f1.x; a.w += f1.y;
    };

    int j = 0;
    for (; j + 4 <= dmax; j += 4) {
        int s0 = __shfl_sync(0xffffffffu, myidx, j + 0);
        int s1 = __shfl_sync(0xffffffffu, myidx, j + 1);
        int s2 = __shfl_sync(0xffffffffu, myidx, j + 2);
        int s3 = __shfl_sync(0xffffffffu, myidx, j + 3);
        uint2 u0 = __ldg((const uint2*)(Xh + (size_t)s0 * DIN) + lane);
        uint2 u1 = __ldg((const uint2*)(Xh + (size_t)s1 * DIN) + lane);
        uint2 u2 = __ldg((const uint2*)(Xh + (size_t)s2 * DIN) + lane);
        uint2 u3 = __ldg((const uint2*)(Xh + (size_t)s3 * DIN) + lane);
        addu2(p, u0); addu2(q, u1); addu2(p, u2); addu2(q, u3);
    }
    for (; j < dmax; j++) {
        int s0 = __shfl_sync(0xffffffffu, myidx, j);
        addu2(p, __ldg((const uint2*)(Xh + (size_t)s0 * DIN) + lane));
    }
    for (int jj = beg + 32; jj < end; jj++) {
        int s0 = __ldg(&g_csr[jj]);
        addu2(p, __ldg((const uint2*)(Xh + (size_t)s0 * DIN) + lane));
    }

    float inv = 1.f / fmaxf((float)deg, 1.f);
    float4 a = make_float4((p.x + q.x) * inv, (p.y + q.y) * inv,
                           (p.z + q.z) * inv, (p.w + q.w) * inv);
    uint2 h = make_uint2(pkh(a.x, a.y), pkh(a.z, a.w));
    *(uint2*)(Ahi + (size_t)node * DIN + lane * 4) = h;
}

// ---------------- SpMM layer2: gather fp16 table (D=256) -------------------
__global__ void __launch_bounds__(256) k_spmm2(const __half* __restrict__ Xh,
                                               __half* __restrict__ Ahi) {
    int warp = threadIdx.x >> 5, lane = threadIdx.x & 31;
    int node = blockIdx.x * 8 + warp;
    if (node >= NN) return;
    int beg = g_rowptr[node], end = g_rowptr[node + 1];
    int deg = end - beg;
    int myidx = (beg + lane < end) ? __ldg(&g_csr[beg + lane]) : 0;
    int dmax = deg < 32 ? deg : 32;

    float p[8] = {0, 0, 0, 0, 0, 0, 0, 0};
    float q[8] = {0, 0, 0, 0, 0, 0, 0, 0};

    auto addu4 = [&](float* a, uint4 u) {
        __half2* ph = (__half2*)&u;
#pragma unroll
        for (int z = 0; z < 4; z++) {
            float2 f = __half22float2(ph[z]);
            a[z * 2] += f.x; a[z * 2 + 1] += f.y;
        }
    };

    int j = 0;
    for (; j + 2 <= dmax; j += 2) {
        int s0 = __shfl_sync(0xffffffffu, myidx, j + 0);
        int s1 = __shfl_sync(0xffffffffu, myidx, j + 1);
        uint4 u0 = __ldg((const uint4*)(Xh + (size_t)s0 * DH) + lane);
        uint4 u1 = __ldg((const uint4*)(Xh + (size_t)s1 * DH) + lane);
        addu4(p, u0); addu4(q, u1);
    }
    for (; j < dmax; j++) {
        int s0 = __shfl_sync(0xffffffffu, myidx, j);
        addu4(p, __ldg((const uint4*)(Xh + (size_t)s0 * DH) + lane));
    }
    for (int jj = beg + 32; jj < end; jj++) {
        int s0 = __ldg(&g_csr[jj]);
        addu4(p, __ldg((const uint4*)(Xh + (size_t)s0 * DH) + lane));
    }

    float inv = 1.f / fmaxf((float)deg, 1.f);
    uint4 h;
    uint32_t* hp = (uint32_t*)&h;
#pragma unroll
    for (int z = 0; z < 4; z++) {
        float v0 = (p[z * 2] + q[z * 2]) * inv;
        float v1 = (p[z * 2 + 1] + q[z * 2 + 1]) * inv;
        hp[z] = pkh(v0, v1);
    }
    *(uint4*)(Ahi + (size_t)node * DH + lane * 8) = h;
}

// ---------------- mma.sync GEMM fp16, K-chunk 64, x4 B loads ----------------
// CTA 128x128, 3 stages x 32KB. acc += aH*bH. BN stats fused in epilogue.
template <int K>
__global__ void __launch_bounds__(256, 2)
k_mmagemm(const __half* __restrict__ Ahi, const __half* __restrict__ Shi,
          const __half* __restrict__ Bh,  const float* __restrict__ bias,
          float* __restrict__ Out, float* __restrict__ stats) {
    constexpr int CH  = 2 * K / 64;
    constexpr int LDB = 2 * K;
    constexpr int T_BH = 16384;
    constexpr int STAGE = 32768;

    extern __shared__ __align__(128) char dsm[];
    float* sbias = (float*)dsm;                 // 512B
    float* s_red = (float*)(dsm + 512);         // 1KB: sum[128], sq[128]
    uint32_t stage0 = smem_u32(dsm) + 2048;

    const int t = threadIdx.x;
    const int wid = t >> 5, lane = t & 31;
    const int wm = wid >> 2, wn = wid & 3;       // warps 2 x 4
    const int m0 = blockIdx.x * 128;
    const int n0 = blockIdx.y * 128;

    if (t < 128) { sbias[t] = bias[n0 + t]; s_red[t] = 0.f; s_red[128 + t] = 0.f; }

    float acc[4][4][4];
#pragma unroll
    for (int i = 0; i < 4; i++)
#pragma unroll
        for (int j = 0; j < 4; j++)
#pragma unroll
            for (int q = 0; q < 4; q++) acc[i][j][q] = 0.f;

    auto load_chunk = [&](int c, int s) {
        uint32_t sb = stage0 + s * STAGE;
        const __half* Ah; int k0;
        if (c < K / 64) { Ah = Ahi; k0 = c * 64; }
        else            { Ah = Shi; k0 = (c - K / 64) * 64; }
#pragma unroll
        for (int it = 0; it < 4; it++) {
            int i = t + 256 * it;                 // 0..1023
            int row = i >> 3, ch = i & 7;
            uint32_t sw = row * 128 + ((ch ^ (row & 7)) << 4);
            int gr = m0 + row; if (gr > NN - 1) gr = NN - 1;
            cpasync16(sb + sw, Ah + (size_t)gr * K + k0 + ch * 8);
            cpasync16(sb + T_BH + sw, Bh + (size_t)(n0 + row) * LDB + c * 64 + ch * 8);
        }
        CP_COMMIT();
    };

    load_chunk(0, 0);
    load_chunk(1, 1);
    if (CH > 2) load_chunk(2, 2);

#pragma unroll 1
    for (int c = 0; c < CH; c++) {
        int s = c % 3;
        int rem = CH - 1 - c;
        if (rem >= 2)      asm volatile("cp.async.wait_group 2;" ::: "memory");
        else if (rem == 1) asm volatile("cp.async.wait_group 1;" ::: "memory");
        else               asm volatile("cp.async.wait_group 0;" ::: "memory");
        __syncthreads();

        uint32_t sb = stage0 + s * STAGE;
#pragma unroll
        for (int ks = 0; ks < 4; ks++) {
            uint32_t aH[4][4], bH[4][2];
#pragma unroll
            for (int mt = 0; mt < 4; mt++) {
                int r = wm * 64 + mt * 16 + (lane & 15);
                int kc = ks * 2 + (lane >> 4);
                ldsm_x4(aH[mt], sb + r * 128 + ((kc ^ (r & 7)) << 4));
            }
#pragma unroll
            for (int np = 0; np < 2; np++) {
                int nrow = wn * 32 + np * 16 + (lane & 7) + ((lane >> 4) << 3);
                int kc = ks * 2 + ((lane >> 3) & 1);
                uint32_t bp[4];
                ldsm_x4(bp, sb + T_BH + nrow * 128 + ((kc ^ (nrow & 7)) << 4));
                bH[np * 2][0] = bp[0];     bH[np * 2][1] = bp[1];
                bH[np * 2 + 1][0] = bp[2]; bH[np * 2 + 1][1] = bp[3];
            }
#pragma unroll
            for (int mt = 0; mt < 4; mt++)
#pragma unroll
                for (int nt = 0; nt < 4; nt++)
                    mma16816(acc[mt][nt], aH[mt], bH[nt]);
        }
        __syncthreads();
        if (c + 3 < CH) load_chunk(c + 3, s);
    }

    // epilogue: bias + store + per-column BN partial stats (shfl-reduced)
    float csum[4][2], csq[4][2];
#pragma unroll
    for (int nt = 0; nt < 4; nt++) {
        csum[nt][0] = 0.f; csum[nt][1] = 0.f;
        csq[nt][0] = 0.f;  csq[nt][1] = 0.f;
    }
#pragma unroll
    for (int mt = 0; mt < 4; mt++) {
        int r0 = m0 + wm * 64 + mt * 16 + (lane >> 2);
        bool v0ok = r0 < NN, v1ok = (r0 + 8) < NN;
#pragma unroll
        for (int nt = 0; nt < 4; nt++) {
            int lc = wn * 32 + nt * 8 + (lane & 3) * 2;
            float bx = sbias[lc], by = sbias[lc + 1];
            if (v0ok) {
                float vx = acc[mt][nt][0] + bx, vy = acc[mt][nt][1] + by;
                *(float2*)(Out + (size_t)r0 * DH + n0 + lc) = make_float2(vx, vy);
                csum[nt][0] += vx; csq[nt][0] += vx * vx;
                csum[nt][1] += vy; csq[nt][1] += vy * vy;
            }
            if (v1ok) {
                float vx = acc[mt][nt][2] + bx, vy = acc[mt][nt][3] + by;
                *(float2*)(Out + (size_t)(r0 + 8) * DH + n0 + lc) = make_float2(vx, vy);
                csum[nt][0] += vx; csq[nt][0] += vx * vx;
                csum[nt][1] += vy; csq[nt][1] += vy * vy;
            }
        }
    }
#pragma unroll
    for (int nt = 0; nt < 4; nt++) {
#pragma unroll
        for (int off = 4; off < 32; off <<= 1) {
            csum[nt][0] += __shfl_xor_sync(0xffffffffu, csum[nt][0], off);
            csum[nt][1] += __shfl_xor_sync(0xffffffffu, csum[nt][1], off);
            csq[nt][0]  += __shfl_xor_sync(0xffffffffu, csq[nt][0], off);
            csq[nt][1]  += __shfl_xor_sync(0xffffffffu, csq[nt][1], off);
        }
    }
    __syncthreads();
    if (lane < 4) {
#pragma unroll
        for (int nt = 0; nt < 4; nt++) {
            int lc = wn * 32 + nt * 8 + lane * 2;
            atomicAdd(&s_red[lc], csum[nt][0]);
            atomicAdd(&s_red[lc + 1], csum[nt][1]);
            atomicAdd(&s_red[128 + lc], csq[nt][0]);
            atomicAdd(&s_red[128 + lc + 1], csq[nt][1]);
        }
    }
    __syncthreads();
    if (t < 128) {
        atomicAdd(&stats[n0 + t], s_red[t]);
        atomicAdd(&stats[256 + n0 + t], s_red[128 + t]);
    }
}

// ---------------- prep2: BN+ReLU->fp16 + zero layer2 stats ------------------
// blocks [0,1024): bnrelu; block 1024: zero stats[512:1024) for gemm2.
__global__ void __launch_bounds__(256) k_prep2(const float* __restrict__ H,
                                               const float* __restrict__ stats,
                                               const float* __restrict__ gam,
                                               const float* __restrict__ bet,
                                               __half* __restrict__ Hi,
                                               float* __restrict__ stats_mut) {
    int b = blockIdx.x, t = threadIdx.x;
    if (b >= 1024) {
        stats_mut[512 + t] = 0.f;
        stats_mut[768 + t] = 0.f;
        return;
    }
    __shared__ float sbn[512];
    {
        int c = t;
        float mu  = stats[c] * (1.f / NN);
        float var = stats[256 + c] * (1.f / NN) - mu * mu;
        float rstd = rsqrtf(var + 1e-5f);
        float sc = rstd * gam[c];
        sbn[c] = sc;
        sbn[256 + c] = bet[c] - mu * sc;
    }
    __syncthreads();
    const int total = NN * DH / 4;
    for (int i = b * 256 + t; i < total; i += 1024 * 256) {
        float4 v = ((const float4*)H)[i];
        int c = (i & 63) * 4;
        v.x = fmaxf(0.f, v.x * sbn[c + 0] + sbn[256 + c + 0]);
        v.y = fmaxf(0.f, v.y * sbn[c + 1] + sbn[256 + c + 1]);
        v.z = fmaxf(0.f, v.z * sbn[c + 2] + sbn[256 + c + 2]);
        v.w = fmaxf(0.f, v.w * sbn[c + 3] + sbn[256 + c + 3]);
        uint2 h = make_uint2(pkh(v.x, v.y), pkh(v.z, v.w));
        *(uint2*)((char*)Hi + (size_t)i * 8) = h;
    }
}

// ---------------- final FC (BN fused) + re-zero state for next replay -------
// blocks [0,3125): fc; [3125,3516): zero g_deg/g_cursor + stats[0:512)
__global__ void __launch_bounds__(256) k_fc(const float* __restrict__ H,
                                            float* __restrict__ stats,  // base
                                            const float* __restrict__ gam,
                                            const float* __restrict__ bet,
                                            const float* __restrict__ W,
                                            const float* __restrict__ b,
                                            float* __restrict__ out) {
    int blk = blockIdx.x, t = threadIdx.x;
    if (blk >= 3125) {
        int i = (blk - 3125) * 256 + t;
        if (i < NN) { g_deg[i] = 0; g_cursor[i] = 0; }
        if (i < 512) stats[i] = 0.f;   // layer1 stats for next run
        return;
    }
    __shared__ __align__(16) float Ws[DH * NCLS];
    __shared__ float sbn[512];
    for (int i = t; i < DH * NCLS / 4; i += 256)
        ((float4*)Ws)[i] = ((const float4*)W)[i];
    {
        int c = t;
        float mu  = stats[512 + c] * (1.f / NN);
        float var = stats[768 + c] * (1.f / NN) - mu * mu;
        float rstd = rsqrtf(var + 1e-5f);
        float sc = rstd * gam[c];
        sbn[c] = sc;
        sbn[256 + c] = bet[c] - mu * sc;
    }
    __syncthreads();
    int row = blk * 32 + (t >> 3);
    int c = (t & 7) * 4;
    if (row >= NN) return;
    const float4* hr = (const float4*)(H + (size_t)row * DH);
    float4 acc = *(const float4*)(b + c);
#pragma unroll 8
    for (int k4 = 0; k4 < DH / 4; k4++) {
        float4 h = hr[k4];
        int kb = k4 * 4;
        h.x = fmaxf(0.f, h.x * sbn[kb + 0] + sbn[256 + kb + 0]);
        h.y = fmaxf(0.f, h.y * sbn[kb + 1] + sbn[256 + kb + 1]);
        h.z = fmaxf(0.f, h.z * sbn[kb + 2] + sbn[256 + kb + 2]);
        h.w = fmaxf(0.f, h.w * sbn[kb + 3] + sbn[256 + kb + 3]);
        float4 w0 = *(float4*)&Ws[(kb + 0) * NCLS + c];
        float4 w1 = *(float4*)&Ws[(kb + 1) * NCLS + c];
        float4 w2 = *(float4*)&Ws[(kb + 2) * NCLS + c];
        float4 w3 = *(float4*)&Ws[(kb + 3) * NCLS + c];
        acc.x += h.x * w0.x + h.y * w1.x + h.z * w2.x + h.w * w3.x;
        acc.y += h.x * w0.y + h.y * w1.y + h.z * w2.y + h.w * w3.y;
        acc.z += h.x * w0.z + h.y * w1.z + h.z * w2.z + h.w * w3.z;
        acc.w += h.x * w0.w + h.y * w1.w + h.z * w2.w + h.w * w3.w;
    }
    *(float4*)(out + (size_t)row * NCLS + c) = acc;
}

// ---------------- launch ----------------------------------------------------
extern "C" void kernel_launch(void* const* d_in, const int* in_sizes, int n_in,
                              void* d_out, int out_size) {
    const float* x    = (const float*)d_in[0];
    const int*   esrc = (const int*)d_in[1];
    const int*   edst = (const int*)d_in[2];
    const float* W1l  = (const float*)d_in[3];
    const float* b1   = (const float*)d_in[4];
    const float* W1r  = (const float*)d_in[5];
    const float* g1   = (const float*)d_in[6];
    const float* be1  = (const float*)d_in[7];
    const float* W2l  = (const float*)d_in[8];
    const float* b2   = (const float*)d_in[9];
    const float* W2r  = (const float*)d_in[10];
    const float* g2   = (const float*)d_in[11];
    const float* be2  = (const float*)d_in[12];
    const float* Wfc  = (const float*)d_in[13];
    const float* bfc  = (const float*)d_in[14];
    float* out = (float*)d_out;

    __half *p_Ahi, *p_Shi, *p_Bh, *p_Bh2;
    float *p_h1, *p_h2, *p_stats;
    cudaGetSymbolAddress((void**)&p_Ahi,   g_Ahi);
    cudaGetSymbolAddress((void**)&p_Shi,   g_Shi);
    cudaGetSymbolAddress((void**)&p_Bh,    g_Bhi);
    cudaGetSymbolAddress((void**)&p_Bh2,   g_Bhi2);
    cudaGetSymbolAddress((void**)&p_h1,    g_h1);
    cudaGetSymbolAddress((void**)&p_h2,    g_h2);
    cudaGetSymbolAddress((void**)&p_stats, g_stats);

    const int SMEM = 2048 + 3 * 32768;   // 100352
    cudaFuncSetAttribute(k_mmagemm<DIN>,
                         cudaFuncAttributeMaxDynamicSharedMemorySize, SMEM);
    cudaFuncSetAttribute(k_mmagemm<DH>,
                         cudaFuncAttributeMaxDynamicSharedMemorySize, SMEM);

    const int nb1 = (NN + 1023) / 1024;
    const int e4grid = (NE / 4 + 255) / 256;
    dim3 gg((NN + 127) / 128, 2);        // 782 x 2 CTAs

    // hist | split | prepB1 | prepB2 concurrent, then CSR scan + fill
    k_prep1<<<2971, 256>>>(edst, x, p_Shi, W1l, W1r, p_Bh, W2l, W2r, p_Bh2);
    k_scan1<<<nb1, 1024>>>();
    k_scan3<<<nb1, 1024>>>(nb1);
    k_fill<<<e4grid, 256>>>(esrc, edst);

    // layer 1
    k_spmm1<<<(NN + 7) / 8, 256>>>(p_Shi, p_Ahi);
    k_mmagemm<DIN><<<gg, 256, SMEM>>>(p_Ahi, p_Shi, p_Bh, b1, p_h1, p_stats);

    // bnrelu (+ zero layer2 stats)
    k_prep2<<<1025, 256>>>(p_h1, p_stats, g1, be1, p_Shi, p_stats);

    // layer 2
    k_spmm2<<<(NN + 7) / 8, 256>>>(p_Shi, p_Ahi);
    k_mmagemm<DH><<<gg, 256, SMEM>>>(p_Ahi, p_Shi, p_Bh2, b2, p_h2, p_stats + 512);

    // classifier (BN fused) + re-zero deg/cursor/layer1-stats for next replay
    k_fc<<<3516, 256>>>(p_h2, p_stats, g2, be2, Wfc, bfc, out);
}